// round 8
// baseline (speedup 1.0000x reference)
#include <cuda_runtime.h>
#include <cuda_bf16.h>
#include <cstdint>

#define BATCH     32
#define SEQ       1024
#define CTXD      1024
#define DMODEL    768
#define NHEAD     8
#define HDIM      96
#define NQ        256
#define MROWS     (BATCH * SEQ)   // 32768
#define NZ        (BATCH * NHEAD) // 256

typedef __nv_bfloat16 bf16;
typedef __nv_bfloat162 bf162;

// ============================ device scratch ============================
__device__ bf16 g_xhi[MROWS * CTXD];
__device__ bf16 g_xlo[MROWS * CTXD];
__device__ bf16 g_wkhi[DMODEL * CTXD];
__device__ bf16 g_wklo[DMODEL * CTXD];
__device__ bf16 g_wvhi[DMODEL * CTXD];
__device__ bf16 g_wvlo[DMODEL * CTXD];
__device__ bf16 g_wohi[DMODEL * DMODEL];
__device__ bf16 g_wolo[DMODEL * DMODEL];
__device__ bf16 g_khhi[MROWS * DMODEL];
__device__ bf16 g_khlo[MROWS * DMODEL];
__device__ bf16 g_vhhi[MROWS * DMODEL];
__device__ bf16 g_vhlo[MROWS * DMODEL];
__device__ bf16 g_qhhi[NQ * DMODEL];
__device__ bf16 g_qhlo[NQ * DMODEL];
__device__ bf16 g_aohi[BATCH * NQ * DMODEL];
__device__ bf16 g_aolo[BATCH * NQ * DMODEL];
__device__ float g_qln[NQ * DMODEL];
__device__ float g_qh[NQ * DMODEL];
__device__ float g_bias[MROWS];

// ============================ asm helpers ============================
__device__ __forceinline__ uint32_t smem_u32(const void* p) {
    uint32_t a;
    asm("{ .reg .u64 t; cvta.to.shared.u64 t, %1; cvt.u32.u64 %0, t; }" : "=r"(a) : "l"(p));
    return a;
}
__device__ __forceinline__ void ldm_x4(uint32_t* r, uint32_t addr) {
    asm volatile("ldmatrix.sync.aligned.m8n8.x4.shared.b16 {%0,%1,%2,%3}, [%4];"
                 : "=r"(r[0]), "=r"(r[1]), "=r"(r[2]), "=r"(r[3]) : "r"(addr));
}
__device__ __forceinline__ void ldm_x4_t(uint32_t* r, uint32_t addr) {
    asm volatile("ldmatrix.sync.aligned.m8n8.x4.trans.shared.b16 {%0,%1,%2,%3}, [%4];"
                 : "=r"(r[0]), "=r"(r[1]), "=r"(r[2]), "=r"(r[3]) : "r"(addr));
}
__device__ __forceinline__ void mma16816(float* c, const uint32_t* a, const uint32_t* b) {
    asm volatile("mma.sync.aligned.m16n8k16.row.col.f32.bf16.bf16.f32 "
                 "{%0,%1,%2,%3}, {%4,%5,%6,%7}, {%8,%9}, {%0,%1,%2,%3};"
                 : "+f"(c[0]), "+f"(c[1]), "+f"(c[2]), "+f"(c[3])
                 : "r"(a[0]), "r"(a[1]), "r"(a[2]), "r"(a[3]), "r"(b[0]), "r"(b[1]));
}
__device__ __forceinline__ void cp16(uint32_t dst, const void* src) {
    asm volatile("cp.async.cg.shared.global [%0], [%1], 16;" :: "r"(dst), "l"(src));
}
#define CP_COMMIT() asm volatile("cp.async.commit_group;")
#define CP_WAIT0()  asm volatile("cp.async.wait_group 0;")

__device__ __forceinline__ void split2(float v0, float v1, bf162& h2, bf162& l2) {
    bf16 h0 = __float2bfloat16(v0);
    bf16 h1 = __float2bfloat16(v1);
    h2 = bf162(h0, h1);
    l2 = bf162(__float2bfloat16(v0 - __bfloat162float(h0)),
               __float2bfloat16(v1 - __bfloat162float(h1)));
}
__device__ __forceinline__ void splitpack(float v0, float v1, uint32_t& hi, uint32_t& lo) {
    bf162 h2, l2;
    split2(v0, v1, h2, l2);
    hi = *reinterpret_cast<uint32_t*>(&h2);
    lo = *reinterpret_cast<uint32_t*>(&l2);
}

// ============================ split-bf16 NT GEMM ============================
// k-chunk 32, double-buffered, 2 CTAs/SM. MMAs grouped by term for ILP.
#define G3_SMEM 81920
#define LDS_BF 40

template<int EPI>  // 0: fp32 out, 1: split bf16 out
__device__ __forceinline__ void gemm3_dev(
    char* smem,
    const bf16* __restrict__ Ahi, const bf16* __restrict__ Alo, int lda,
    const bf16* __restrict__ Bhi, const bf16* __restrict__ Blo, int ldb,
    int K, int m0, int n0, float alpha, const float* __restrict__ bias_n,
    float* __restrict__ Cf, bf16* __restrict__ Chi, bf16* __restrict__ Clo, int ldc)
{
    const int tid  = threadIdx.x;
    const int wid  = tid >> 5;
    const int lane = tid & 31;
    const int wm = (wid & 3) * 32;
    const int wn = (wid >> 2) * 64;

    const uint32_t smBase = smem_u32(smem);
    const uint32_t aRow = (uint32_t)(wm + (lane & 15)) * LDS_BF + (uint32_t)(lane >> 4) * 8u;
    const uint32_t bRow = (uint32_t)(wn + (lane & 7) + ((lane >> 4) * 8)) * LDS_BF
                        + (uint32_t)((lane >> 3) & 1) * 8u;

    float acc[2][8][4];
    #pragma unroll
    for (int i = 0; i < 2; i++)
        #pragma unroll
        for (int j = 0; j < 8; j++)
            #pragma unroll
            for (int k = 0; k < 4; k++) acc[i][j][k] = 0.f;

    const int r  = tid >> 2;
    const int cc = tid & 3;
    const int nchunks = K >> 5;

    auto load_chunk = [&](int k0, int buf) {
        uint32_t aB = smBase + (uint32_t)buf * 20480u;
        uint32_t bB = smBase + 40960u + (uint32_t)buf * 20480u;
        #pragma unroll
        for (int h = 0; h < 2; h++) {
            int rr = r + h * 64;
            uint32_t so = ((uint32_t)rr * LDS_BF + (uint32_t)cc * 8u) * 2u;
            size_t ga = (size_t)(m0 + rr) * lda + k0 + cc * 8;
            size_t gb = (size_t)(n0 + rr) * ldb + k0 + cc * 8;
            cp16(aB + so,           Ahi + ga);
            cp16(aB + 10240u + so,  Alo + ga);
            cp16(bB + so,           Bhi + gb);
            cp16(bB + 10240u + so,  Blo + gb);
        }
    };

    load_chunk(0, 0);
    CP_COMMIT();

    for (int c = 0; c < nchunks; c++) {
        CP_WAIT0();
        __syncthreads();
        if (c + 1 < nchunks) { load_chunk((c + 1) << 5, (c + 1) & 1); CP_COMMIT(); }

        uint32_t aB = smBase + (uint32_t)(c & 1) * 20480u;
        uint32_t bB = smBase + 40960u + (uint32_t)(c & 1) * 20480u;
        #pragma unroll
        for (int ks = 0; ks < 2; ks++) {
            const uint32_t kcol = (uint32_t)ks * 16u;
            uint32_t ahi[2][4], alo[2][4], bhi[4][4], blo[4][4];
            // ---- load ALL fragments up front ----
            #pragma unroll
            for (int g = 0; g < 4; g++) {
                uint32_t off = (bRow + (uint32_t)g * 16u * LDS_BF + kcol) * 2u;
                ldm_x4(bhi[g], bB + off);
                ldm_x4(blo[g], bB + 10240u + off);
            }
            #pragma unroll
            for (int mi = 0; mi < 2; mi++) {
                uint32_t off = (aRow + (uint32_t)mi * 16u * LDS_BF + kcol) * 2u;
                ldm_x4(ahi[mi], aB + off);
                ldm_x4(alo[mi], aB + 10240u + off);
            }
            // ---- term 1: ahi x bhi (16 independent MMAs) ----
            #pragma unroll
            for (int mi = 0; mi < 2; mi++)
                #pragma unroll
                for (int nj = 0; nj < 8; nj++)
                    mma16816(acc[mi][nj], ahi[mi], &bhi[nj >> 1][(nj & 1) * 2]);
            // ---- term 2: alo x bhi ----
            #pragma unroll
            for (int mi = 0; mi < 2; mi++)
                #pragma unroll
                for (int nj = 0; nj < 8; nj++)
                    mma16816(acc[mi][nj], alo[mi], &bhi[nj >> 1][(nj & 1) * 2]);
            // ---- term 3: ahi x blo ----
            #pragma unroll
            for (int mi = 0; mi < 2; mi++)
                #pragma unroll
                for (int nj = 0; nj < 8; nj++)
                    mma16816(acc[mi][nj], ahi[mi], &blo[nj >> 1][(nj & 1) * 2]);
        }
        __syncthreads();
    }

    #pragma unroll
    for (int mi = 0; mi < 2; mi++) {
        int gm = m0 + wm + mi * 16 + (lane >> 2);
        #pragma unroll
        for (int nj = 0; nj < 8; nj++) {
            int gn = n0 + wn + nj * 8 + (lane & 3) * 2;
            float b0 = bias_n ? bias_n[gn]     : 0.f;
            float b1 = bias_n ? bias_n[gn + 1] : 0.f;
            float v00 = alpha * acc[mi][nj][0] + b0;
            float v01 = alpha * acc[mi][nj][1] + b1;
            float v10 = alpha * acc[mi][nj][2] + b0;
            float v11 = alpha * acc[mi][nj][3] + b1;
            if (EPI == 0) {
                *reinterpret_cast<float2*>(Cf + (size_t)gm * ldc + gn)       = make_float2(v00, v01);
                *reinterpret_cast<float2*>(Cf + (size_t)(gm + 8) * ldc + gn) = make_float2(v10, v11);
            } else {
                bf162 h2, l2;
                split2(v00, v01, h2, l2);
                *reinterpret_cast<bf162*>(Chi + (size_t)gm * ldc + gn) = h2;
                *reinterpret_cast<bf162*>(Clo + (size_t)gm * ldc + gn) = l2;
                split2(v10, v11, h2, l2);
                *reinterpret_cast<bf162*>(Chi + (size_t)(gm + 8) * ldc + gn) = h2;
                *reinterpret_cast<bf162*>(Clo + (size_t)(gm + 8) * ldc + gn) = l2;
            }
        }
    }
}

__global__ void __launch_bounds__(256, 2)
kv_gemm(const bf16* __restrict__ Ahi, const bf16* __restrict__ Alo,
        const bf16* __restrict__ Bhi, const bf16* __restrict__ Blo,
        const float* __restrict__ bias_n, bf16* __restrict__ Chi, bf16* __restrict__ Clo) {
    extern __shared__ char smem[];
    gemm3_dev<1>(smem, Ahi, Alo, CTXD, Bhi, Blo, CTXD, CTXD,
                 blockIdx.y * 128, blockIdx.x * 128, 1.0f, bias_n,
                 nullptr, Chi, Clo, DMODEL);
}

__global__ void __launch_bounds__(256, 2)
oproj_gemm(const bf16* __restrict__ Ahi, const bf16* __restrict__ Alo,
           const bf16* __restrict__ Bhi, const bf16* __restrict__ Blo,
           const float* __restrict__ bias_n, float* __restrict__ C) {
    extern __shared__ char smem[];
    gemm3_dev<0>(smem, Ahi, Alo, DMODEL, Bhi, Blo, DMODEL, DMODEL,
                 blockIdx.y * 128, blockIdx.x * 128, 1.0f, bias_n,
                 C, nullptr, nullptr, DMODEL);
}

// ============================ fused flash attention ============================
#define FA_SMEM 160256
#define FA_LDS 104

__global__ void __launch_bounds__(256, 1)
fa_kernel(const bf16* __restrict__ Qhi, const bf16* __restrict__ Qlo,
          const bf16* __restrict__ Khi, const bf16* __restrict__ Klo,
          const bf16* __restrict__ Vhi, const bf16* __restrict__ Vlo,
          const float* __restrict__ biasBL, float scale,
          bf16* __restrict__ Ohi, bf16* __restrict__ Olo) {
    extern __shared__ char smem[];
    const int tid = threadIdx.x;
    const int wid = tid >> 5, lane = tid & 31;
    const int z = blockIdx.y;
    const int b = z >> 3, h = z & 7;
    const int q0 = blockIdx.x * 128;
    const size_t bSeq = (size_t)b * SEQ;
    const int hOff = h * HDIM;

    const uint32_t smBase = smem_u32(smem);
    const uint32_t KBASE = 53248u, VBASE = 106496u, TSTR = 13312u, BBASE = 159744u;

    for (int i = tid; i < 1536; i += 256) {
        int row = i / 12, col = i % 12;
        uint32_t so = ((uint32_t)row * FA_LDS + (uint32_t)col * 8u) * 2u;
        size_t go = (size_t)(q0 + row) * DMODEL + hOff + col * 8;
        cp16(smBase + so,           Qhi + go);
        cp16(smBase + 26624u + so,  Qlo + go);
    }
    CP_COMMIT();

    auto load_kv = [&](int c, int buf) {
        int l0 = c * 64;
        uint32_t kB = smBase + KBASE + (uint32_t)buf * 26624u;
        uint32_t vB = smBase + VBASE + (uint32_t)buf * 26624u;
        for (int i = tid; i < 768; i += 256) {
            int row = i / 12, col = i % 12;
            uint32_t so = ((uint32_t)row * FA_LDS + (uint32_t)col * 8u) * 2u;
            size_t go = (bSeq + l0 + row) * DMODEL + hOff + col * 8;
            cp16(kB + so,        Khi + go);
            cp16(kB + TSTR + so, Klo + go);
            cp16(vB + so,        Vhi + go);
            cp16(vB + TSTR + so, Vlo + go);
        }
        if (tid < 16)
            cp16(smBase + BBASE + (uint32_t)buf * 256u + (uint32_t)tid * 16u,
                 biasBL + bSeq + l0 + tid * 4);
    };
    load_kv(0, 0);
    CP_COMMIT();

    const uint32_t aRow = (uint32_t)(wid * 16 + (lane & 15)) * FA_LDS + (uint32_t)(lane >> 4) * 8u;
    const uint32_t bRow = (uint32_t)((lane & 7) + ((lane >> 4) * 8)) * FA_LDS
                        + (uint32_t)((lane >> 3) & 1) * 8u;
    const uint32_t vLaneRow = (uint32_t)((lane & 7) + ((lane >> 3) & 1) * 8);
    const uint32_t vLaneCol = (uint32_t)(lane >> 4) * 8u;

    float oacc[12][4];
    #pragma unroll
    for (int j = 0; j < 12; j++)
        #pragma unroll
        for (int k = 0; k < 4; k++) oacc[j][k] = 0.f;
    float m0 = -1e30f, m1 = -1e30f, l0s = 0.f, l1s = 0.f;

    for (int c = 0; c < 16; c++) {
        CP_WAIT0();
        __syncthreads();
        if (c + 1 < 16) { load_kv(c + 1, (c + 1) & 1); CP_COMMIT(); }

        const uint32_t kB = smBase + KBASE + (uint32_t)(c & 1) * 26624u;
        const uint32_t vB = smBase + VBASE + (uint32_t)(c & 1) * 26624u;
        const float* sbias = reinterpret_cast<const float*>(smem + BBASE + (c & 1) * 256);

        float s[8][4];
        #pragma unroll
        for (int j = 0; j < 8; j++)
            #pragma unroll
            for (int k = 0; k < 4; k++) s[j][k] = 0.f;

        #pragma unroll
        for (int ks = 0; ks < 6; ks++) {
            const uint32_t kcol = (uint32_t)ks * 16u;
            uint32_t qhiF[4], qloF[4], kk[4];
            uint32_t qoff = (aRow + kcol) * 2u;
            ldm_x4(qhiF, smBase + qoff);
            ldm_x4(qloF, smBase + 26624u + qoff);
            #pragma unroll
            for (int g = 0; g < 4; g++) {
                uint32_t off = (bRow + (uint32_t)g * 16u * FA_LDS + kcol) * 2u;
                ldm_x4(kk, kB + off);
                mma16816(s[2 * g],     qhiF, &kk[0]);
                mma16816(s[2 * g + 1], qhiF, &kk[2]);
                mma16816(s[2 * g],     qloF, &kk[0]);
                mma16816(s[2 * g + 1], qloF, &kk[2]);
                ldm_x4(kk, kB + TSTR + off);
                mma16816(s[2 * g],     qhiF, &kk[0]);
                mma16816(s[2 * g + 1], qhiF, &kk[2]);
            }
        }

        float mx0 = -1e30f, mx1 = -1e30f;
        #pragma unroll
        for (int nj = 0; nj < 8; nj++) {
            int cidx = nj * 8 + (lane & 3) * 2;
            float bj0 = sbias[cidx], bj1 = sbias[cidx + 1];
            s[nj][0] = s[nj][0] * scale + bj0;
            s[nj][1] = s[nj][1] * scale + bj1;
            s[nj][2] = s[nj][2] * scale + bj0;
            s[nj][3] = s[nj][3] * scale + bj1;
            mx0 = fmaxf(mx0, fmaxf(s[nj][0], s[nj][1]));
            mx1 = fmaxf(mx1, fmaxf(s[nj][2], s[nj][3]));
        }
        #pragma unroll
        for (int o = 1; o <= 2; o <<= 1) {
            mx0 = fmaxf(mx0, __shfl_xor_sync(0xffffffffu, mx0, o));
            mx1 = fmaxf(mx1, __shfl_xor_sync(0xffffffffu, mx1, o));
        }
        float mn0 = fmaxf(m0, mx0), mn1 = fmaxf(m1, mx1);
        float cor0 = __expf(m0 - mn0), cor1 = __expf(m1 - mn1);
        l0s *= cor0; l1s *= cor1;
        #pragma unroll
        for (int j = 0; j < 12; j++) {
            oacc[j][0] *= cor0; oacc[j][1] *= cor0;
            oacc[j][2] *= cor1; oacc[j][3] *= cor1;
        }
        m0 = mn0; m1 = mn1;

        float rs0 = 0.f, rs1 = 0.f;
        uint32_t phiF[4][4], ploF[4][4];
        #pragma unroll
        for (int t = 0; t < 4; t++) {
            float p00 = __expf(s[2 * t][0] - mn0);
            float p01 = __expf(s[2 * t][1] - mn0);
            float p10 = __expf(s[2 * t][2] - mn1);
            float p11 = __expf(s[2 * t][3] - mn1);
            float p20 = __expf(s[2 * t + 1][0] - mn0);
            float p21 = __expf(s[2 * t + 1][1] - mn0);
            float p30 = __expf(s[2 * t + 1][2] - mn1);
            float p31 = __expf(s[2 * t + 1][3] - mn1);
            rs0 += p00 + p01 + p20 + p21;
            rs1 += p10 + p11 + p30 + p31;
            splitpack(p00, p01, phiF[t][0], ploF[t][0]);
            splitpack(p10, p11, phiF[t][1], ploF[t][1]);
            splitpack(p20, p21, phiF[t][2], ploF[t][2]);
            splitpack(p30, p31, phiF[t][3], ploF[t][3]);
        }
        #pragma unroll
        for (int o = 1; o <= 2; o <<= 1) {
            rs0 += __shfl_xor_sync(0xffffffffu, rs0, o);
            rs1 += __shfl_xor_sync(0xffffffffu, rs1, o);
        }
        l0s += rs0; l1s += rs1;

        #pragma unroll
        for (int t = 0; t < 4; t++) {
            uint32_t vv[4];
            #pragma unroll
            for (int g = 0; g < 6; g++) {
                uint32_t off = (((uint32_t)t * 16u + vLaneRow) * FA_LDS
                                + (uint32_t)g * 16u + vLaneCol) * 2u;
                ldm_x4_t(vv, vB + off);
                mma16816(oacc[2 * g],     phiF[t], &vv[0]);
                mma16816(oacc[2 * g + 1], phiF[t], &vv[2]);
                mma16816(oacc[2 * g],     ploF[t], &vv[0]);
                mma16816(oacc[2 * g + 1], ploF[t], &vv[2]);
                ldm_x4_t(vv, vB + TSTR + off);
                mma16816(oacc[2 * g],     phiF[t], &vv[0]);
                mma16816(oacc[2 * g + 1], phiF[t], &vv[2]);
            }
        }
    }

    float inv0 = 1.0f / l0s, inv1 = 1.0f / l1s;
    const int q = q0 + wid * 16 + (lane >> 2);
    #pragma unroll
    for (int j = 0; j < 12; j++) {
        int n = j * 8 + (lane & 3) * 2;
        size_t o0 = ((size_t)(b * NQ + q)) * DMODEL + hOff + n;
        size_t o1 = o0 + (size_t)8 * DMODEL;
        bf162 h2, l2;
        split2(oacc[j][0] * inv0, oacc[j][1] * inv0, h2, l2);
        *reinterpret_cast<bf162*>(Ohi + o0) = h2;
        *reinterpret_cast<bf162*>(Olo + o0) = l2;
        split2(oacc[j][2] * inv1, oacc[j][3] * inv1, h2, l2);
        *reinterpret_cast<bf162*>(Ohi + o1) = h2;
        *reinterpret_cast<bf162*>(Olo + o1) = l2;
    }
}

// ============================ LayerNorm / misc ============================
__device__ __forceinline__ void ln_stats(const float* __restrict__ xr, int ncols,
                                         float& mu, float& rs, float* s1, float* s2) {
    float sum = 0.f, sumsq = 0.f;
    for (int i = threadIdx.x; i < ncols; i += blockDim.x) {
        float v = xr[i];
        sum += v; sumsq += v * v;
    }
    #pragma unroll
    for (int o = 16; o; o >>= 1) {
        sum   += __shfl_xor_sync(0xffffffffu, sum, o);
        sumsq += __shfl_xor_sync(0xffffffffu, sumsq, o);
    }
    int wid = threadIdx.x >> 5, lid = threadIdx.x & 31;
    if (lid == 0) { s1[wid] = sum; s2[wid] = sumsq; }
    __syncthreads();
    if (threadIdx.x < 32) {
        int nw = blockDim.x >> 5;
        float a = (lid < nw) ? s1[lid] : 0.f;
        float c = (lid < nw) ? s2[lid] : 0.f;
        #pragma unroll
        for (int o = 16; o; o >>= 1) {
            a += __shfl_xor_sync(0xffffffffu, a, o);
            c += __shfl_xor_sync(0xffffffffu, c, o);
        }
        if (lid == 0) { s1[0] = a; s2[0] = c; }
    }
    __syncthreads();
    float inv_n = 1.0f / (float)ncols;
    mu = s1[0] * inv_n;
    float var = s2[0] * inv_n - mu * mu;
    rs = rsqrtf(var + 1e-5f);
}

__global__ void ln_kernel(const float* __restrict__ x, const float* __restrict__ w,
                          const float* __restrict__ b, float* __restrict__ out, int ncols) {
    __shared__ float s1[32], s2[32];
    const size_t row = blockIdx.x;
    const float* xr = x + row * (size_t)ncols;
    float mu, rs;
    ln_stats(xr, ncols, mu, rs, s1, s2);
    float* orow = out + row * (size_t)ncols;
    for (int i = threadIdx.x; i < ncols; i += blockDim.x)
        orow[i] = (xr[i] - mu) * rs * w[i] + b[i];
}

__global__ void ln_split_kernel(const float* __restrict__ x, const float* __restrict__ w,
                                const float* __restrict__ b,
                                bf16* __restrict__ hi, bf16* __restrict__ lo, int ncols) {
    __shared__ float s1[32], s2[32];
    const size_t row = blockIdx.x;
    const float* xr = x + row * (size_t)ncols;
    float mu, rs;
    ln_stats(xr, ncols, mu, rs, s1, s2);
    bf16* hrow = hi + row * (size_t)ncols;
    bf16* lrow = lo + row * (size_t)ncols;
    for (int i = threadIdx.x; i < ncols; i += blockDim.x) {
        float y = (xr[i] - mu) * rs * w[i] + b[i];
        bf16 hh = __float2bfloat16(y);
        hrow[i] = hh;
        lrow[i] = __float2bfloat16(y - __bfloat162float(hh));
    }
}

__global__ void split_kernel(const float* __restrict__ x,
                             bf16* __restrict__ hi, bf16* __restrict__ lo, int n) {
    int i = blockIdx.x * blockDim.x + threadIdx.x;
    if (i < n) {
        float v = x[i];
        bf16 h = __float2bfloat16(v);
        hi[i] = h;
        lo[i] = __float2bfloat16(v - __bfloat162float(h));
    }
}

__global__ void bias_kernel(const float* __restrict__ size_in, const float* __restrict__ mask,
                            float* __restrict__ bias, int n) {
    int i = blockIdx.x * blockDim.x + threadIdx.x;
    if (i < n) {
        float s = size_in[i];
        s = (s < 0.5f) ? 1.0f : s;
        bias[i] = logf(s) + mask[i];
    }
}

// ============================ SIMT GEMM (Q-proj only) ============================
#define TBM 64
#define TBN 64
#define TBK 16
#define SPAD 4

__global__ void __launch_bounds__(256)
gemm_nt_kernel(const float* __restrict__ A, int lda,
               const float* __restrict__ B, int ldb,
               float* __restrict__ C, int ldc,
               int M, int N, int K, float alpha, const float* __restrict__ bias_n) {
    __shared__ __align__(16) float As[TBK][TBM + SPAD];
    __shared__ __align__(16) float Bs[TBK][TBN + SPAD];
    const int m0 = blockIdx.y * TBM;
    const int n0 = blockIdx.x * TBN;
    const int t  = threadIdx.x;
    const int tx = t & 15, ty = t >> 4;
    float acc[4][4] = {};
    for (int k0 = 0; k0 < K; k0 += TBK) {
        {
            int col = t & 15, rowb = t >> 4;
            #pragma unroll
            for (int i = 0; i < 4; i++) {
                int rr = rowb + i * 16;
                As[col][rr] = A[(size_t)(m0 + rr) * lda + k0 + col];
            }
        }
        {
            int col = t & 15, rowb = t >> 4;
            #pragma unroll
            for (int i = 0; i < 4; i++) {
                int nn = rowb + i * 16;
                Bs[col][nn] = B[(size_t)(n0 + nn) * ldb + k0 + col];
            }
        }
        __syncthreads();
        #pragma unroll
        for (int kk = 0; kk < TBK; kk++) {
            float4 av = *reinterpret_cast<const float4*>(&As[kk][ty * 4]);
            float4 bv = *reinterpret_cast<const float4*>(&Bs[kk][tx * 4]);
            float a[4] = {av.x, av.y, av.z, av.w};
            float b[4] = {bv.x, bv.y, bv.z, bv.w};
            #pragma unroll
            for (int i = 0; i < 4; i++)
                #pragma unroll
                for (int j = 0; j < 4; j++)
                    acc[i][j] += a[i] * b[j];
        }
        __syncthreads();
    }
    #pragma unroll
    for (int i = 0; i < 4; i++) {
        int gm = m0 + ty * 4 + i;
        #pragma unroll
        for (int j = 0; j < 4; j++) {
            int gn = n0 + tx * 4 + j;
            float v = alpha * acc[i][j];
            if (bias_n) v += bias_n[gn];
            C[(size_t)gm * ldc + gn] = v;
        }
    }
}

// ============================ launch ============================
extern "C" void kernel_launch(void* const* d_in, const int* in_sizes, int n_in,
                              void* d_out, int out_size) {
    const float* x     = (const float*)d_in[0];
    const float* sizei = (const float*)d_in[1];
    const float* amask = (const float*)d_in[2];
    const float* query = (const float*)d_in[3];
    const float* ln_q_w = (const float*)d_in[4];
    const float* ln_q_b = (const float*)d_in[5];
    const float* ln_k_w = (const float*)d_in[6];
    const float* ln_k_b = (const float*)d_in[7];
    const float* Wq = (const float*)d_in[8];
    const float* Wk = (const float*)d_in[9];
    const float* Wv = (const float*)d_in[10];
    const float* bq = (const float*)d_in[11];
    const float* bk = (const float*)d_in[12];
    const float* bv = (const float*)d_in[13];
    const float* Wo = (const float*)d_in[14];
    const float* bo = (const float*)d_in[15];
    float* out = (float*)d_out;

    bf16 *xhi, *xlo, *wkhi, *wklo, *wvhi, *wvlo, *wohi, *wolo;
    bf16 *khhi, *khlo, *vhhi, *vhlo, *qhhi, *qhlo, *aohi, *aolo;
    float *qln, *qh, *bias;
    cudaGetSymbolAddress((void**)&xhi, g_xhi);
    cudaGetSymbolAddress((void**)&xlo, g_xlo);
    cudaGetSymbolAddress((void**)&wkhi, g_wkhi);
    cudaGetSymbolAddress((void**)&wklo, g_wklo);
    cudaGetSymbolAddress((void**)&wvhi, g_wvhi);
    cudaGetSymbolAddress((void**)&wvlo, g_wvlo);
    cudaGetSymbolAddress((void**)&wohi, g_wohi);
    cudaGetSymbolAddress((void**)&wolo, g_wolo);
    cudaGetSymbolAddress((void**)&khhi, g_khhi);
    cudaGetSymbolAddress((void**)&khlo, g_khlo);
    cudaGetSymbolAddress((void**)&vhhi, g_vhhi);
    cudaGetSymbolAddress((void**)&vhlo, g_vhlo);
    cudaGetSymbolAddress((void**)&qhhi, g_qhhi);
    cudaGetSymbolAddress((void**)&qhlo, g_qhlo);
    cudaGetSymbolAddress((void**)&aohi, g_aohi);
    cudaGetSymbolAddress((void**)&aolo, g_aolo);
    cudaGetSymbolAddress((void**)&qln, g_qln);
    cudaGetSymbolAddress((void**)&qh, g_qh);
    cudaGetSymbolAddress((void**)&bias, g_bias);

    cudaFuncSetAttribute(kv_gemm,    cudaFuncAttributeMaxDynamicSharedMemorySize, G3_SMEM);
    cudaFuncSetAttribute(oproj_gemm, cudaFuncAttributeMaxDynamicSharedMemorySize, G3_SMEM);
    cudaFuncSetAttribute(fa_kernel,  cudaFuncAttributeMaxDynamicSharedMemorySize, FA_SMEM);

    const float scale = 0.10206207261596575f;  // 1/sqrt(96)

    // launch order: index 3 (ncu-profiled) = kv_gemm(K)
    ln_split_kernel<<<MROWS, 256>>>(x, ln_k_w, ln_k_b, xhi, xlo, CTXD);               // 0
    split_kernel<<<(DMODEL * CTXD + 255) / 256, 256>>>(Wk, wkhi, wklo, DMODEL * CTXD); // 1
    split_kernel<<<(DMODEL * CTXD + 255) / 256, 256>>>(Wv, wvhi, wvlo, DMODEL * CTXD); // 2
    {
        dim3 grid(DMODEL / 128, MROWS / 128);
        kv_gemm<<<grid, 256, G3_SMEM>>>(xhi, xlo, wkhi, wklo, bk, khhi, khlo);         // 3 (profiled)
        kv_gemm<<<grid, 256, G3_SMEM>>>(xhi, xlo, wvhi, wvlo, bv, vhhi, vhlo);         // 4
    }
    ln_kernel<<<NQ, 256>>>(query, ln_q_w, ln_q_b, qln, DMODEL);                        // 5
    split_kernel<<<(DMODEL * DMODEL + 255) / 256, 256>>>(Wo, wohi, wolo, DMODEL * DMODEL); // 6
    bias_kernel<<<(MROWS + 255) / 256, 256>>>(sizei, amask, bias, MROWS);              // 7
    gemm_nt_kernel<<<dim3(DMODEL / TBN, NQ / TBM), 256>>>(                             // 8
        qln, DMODEL, Wq, DMODEL, qh, DMODEL, NQ, DMODEL, DMODEL, 1.0f, bq);
    split_kernel<<<(NQ * DMODEL + 255) / 256, 256>>>(qh, qhhi, qhlo, NQ * DMODEL);     // 9

    fa_kernel<<<dim3(NQ / 128, NZ), 256, FA_SMEM>>>(                                   // 10
        qhhi, qhlo, khhi, khlo, vhhi, vhlo, bias, scale, aohi, aolo);

    oproj_gemm<<<dim3(DMODEL / 128, BATCH * NQ / 128), 256, G3_SMEM>>>(                // 11
        aohi, aolo, wohi, wolo, bo, out);
}

// round 9
// speedup vs baseline: 1.2354x; 1.2354x over previous
#include <cuda_runtime.h>
#include <cuda_bf16.h>
#include <cuda_fp16.h>
#include <cstdint>

#define BATCH     32
#define SEQ       1024
#define CTXD      1024
#define DMODEL    768
#define NHEAD     8
#define HDIM      96
#define NQ        256
#define MROWS     (BATCH * SEQ)   // 32768
#define NZ        (BATCH * NHEAD) // 256

typedef __nv_bfloat16 bf16;
typedef __nv_bfloat162 bf162;

// ============================ device scratch ============================
__device__ __half g_x16hi[MROWS * CTXD];          // LN(x) fp16 hi
__device__ __half g_x16lo[MROWS * CTXD];          // LN(x) fp16 lo
__device__ __half g_wk16[DMODEL * CTXD];          // Wk fp16
__device__ __half g_wv16[DMODEL * CTXD];          // Wv fp16
__device__ bf16 g_wohi[DMODEL * DMODEL];
__device__ bf16 g_wolo[DMODEL * DMODEL];
__device__ bf16 g_khhi[MROWS * DMODEL];
__device__ bf16 g_khlo[MROWS * DMODEL];
__device__ bf16 g_vhhi[MROWS * DMODEL];
__device__ bf16 g_vhlo[MROWS * DMODEL];
__device__ bf16 g_qhhi[NQ * DMODEL];
__device__ bf16 g_qhlo[NQ * DMODEL];
__device__ bf16 g_aohi[BATCH * NQ * DMODEL];
__device__ bf16 g_aolo[BATCH * NQ * DMODEL];
__device__ float g_qln[NQ * DMODEL];
__device__ float g_qh[NQ * DMODEL];
__device__ float g_bias[MROWS];

// ============================ asm helpers ============================
__device__ __forceinline__ uint32_t smem_u32(const void* p) {
    uint32_t a;
    asm("{ .reg .u64 t; cvta.to.shared.u64 t, %1; cvt.u32.u64 %0, t; }" : "=r"(a) : "l"(p));
    return a;
}
__device__ __forceinline__ void ldm_x4(uint32_t* r, uint32_t addr) {
    asm volatile("ldmatrix.sync.aligned.m8n8.x4.shared.b16 {%0,%1,%2,%3}, [%4];"
                 : "=r"(r[0]), "=r"(r[1]), "=r"(r[2]), "=r"(r[3]) : "r"(addr));
}
__device__ __forceinline__ void ldm_x4_t(uint32_t* r, uint32_t addr) {
    asm volatile("ldmatrix.sync.aligned.m8n8.x4.trans.shared.b16 {%0,%1,%2,%3}, [%4];"
                 : "=r"(r[0]), "=r"(r[1]), "=r"(r[2]), "=r"(r[3]) : "r"(addr));
}
__device__ __forceinline__ void mma16816(float* c, const uint32_t* a, const uint32_t* b) {
    asm volatile("mma.sync.aligned.m16n8k16.row.col.f32.bf16.bf16.f32 "
                 "{%0,%1,%2,%3}, {%4,%5,%6,%7}, {%8,%9}, {%0,%1,%2,%3};"
                 : "+f"(c[0]), "+f"(c[1]), "+f"(c[2]), "+f"(c[3])
                 : "r"(a[0]), "r"(a[1]), "r"(a[2]), "r"(a[3]), "r"(b[0]), "r"(b[1]));
}
__device__ __forceinline__ void mma16816h(float* c, const uint32_t* a, const uint32_t* b) {
    asm volatile("mma.sync.aligned.m16n8k16.row.col.f32.f16.f16.f32 "
                 "{%0,%1,%2,%3}, {%4,%5,%6,%7}, {%8,%9}, {%0,%1,%2,%3};"
                 : "+f"(c[0]), "+f"(c[1]), "+f"(c[2]), "+f"(c[3])
                 : "r"(a[0]), "r"(a[1]), "r"(a[2]), "r"(a[3]), "r"(b[0]), "r"(b[1]));
}
__device__ __forceinline__ void cp16(uint32_t dst, const void* src) {
    asm volatile("cp.async.cg.shared.global [%0], [%1], 16;" :: "r"(dst), "l"(src));
}
#define CP_COMMIT() asm volatile("cp.async.commit_group;")
#define CP_WAIT0()  asm volatile("cp.async.wait_group 0;")

__device__ __forceinline__ void split2(float v0, float v1, bf162& h2, bf162& l2) {
    bf16 h0 = __float2bfloat16(v0);
    bf16 h1 = __float2bfloat16(v1);
    h2 = bf162(h0, h1);
    l2 = bf162(__float2bfloat16(v0 - __bfloat162float(h0)),
               __float2bfloat16(v1 - __bfloat162float(h1)));
}
__device__ __forceinline__ void splitpack(float v0, float v1, uint32_t& hi, uint32_t& lo) {
    bf162 h2, l2;
    split2(v0, v1, h2, l2);
    hi = *reinterpret_cast<uint32_t*>(&h2);
    lo = *reinterpret_cast<uint32_t*>(&l2);
}

#define LDS_BF 40

// ============================ fp16 2-term NT GEMM (KV projections) ============================
// C[M,N] = (Ahi+Alo)[m,k] * B16[n,k]^T + bias_n. A split fp16 (22-bit), B single fp16.
// k-chunk 32, double buffered, 2 CTAs/SM.
// smem: A: buf*20480 + term*10240 ; B: 40960 + buf*10240 ; total 61440
#define G2_SMEM 61440

__global__ void __launch_bounds__(256, 2)
kv_gemm_h(const __half* __restrict__ Ahi, const __half* __restrict__ Alo,
          const __half* __restrict__ B16,
          const float* __restrict__ bias_n,
          bf16* __restrict__ Chi, bf16* __restrict__ Clo) {
    extern __shared__ char smem[];
    const int tid  = threadIdx.x;
    const int wid  = tid >> 5;
    const int lane = tid & 31;
    const int m0 = blockIdx.y * 128;
    const int n0 = blockIdx.x * 128;
    const int wm = (wid & 3) * 32;
    const int wn = (wid >> 2) * 64;

    const uint32_t smBase = smem_u32(smem);
    const uint32_t aRow = (uint32_t)(wm + (lane & 15)) * LDS_BF + (uint32_t)(lane >> 4) * 8u;
    const uint32_t bRow = (uint32_t)(wn + (lane & 7) + ((lane >> 4) * 8)) * LDS_BF
                        + (uint32_t)((lane >> 3) & 1) * 8u;

    float acc[2][8][4];
    #pragma unroll
    for (int i = 0; i < 2; i++)
        #pragma unroll
        for (int j = 0; j < 8; j++)
            #pragma unroll
            for (int k = 0; k < 4; k++) acc[i][j][k] = 0.f;

    const int r  = tid >> 2;
    const int cc = tid & 3;

    auto load_chunk = [&](int k0, int buf) {
        uint32_t aB = smBase + (uint32_t)buf * 20480u;
        uint32_t bB = smBase + 40960u + (uint32_t)buf * 10240u;
        #pragma unroll
        for (int h = 0; h < 2; h++) {
            int rr = r + h * 64;
            uint32_t so = ((uint32_t)rr * LDS_BF + (uint32_t)cc * 8u) * 2u;
            size_t ga = (size_t)(m0 + rr) * CTXD + k0 + cc * 8;
            size_t gb = (size_t)(n0 + rr) * CTXD + k0 + cc * 8;
            cp16(aB + so,          Ahi + ga);
            cp16(aB + 10240u + so, Alo + ga);
            cp16(bB + so,          B16 + gb);
        }
    };

    load_chunk(0, 0);
    CP_COMMIT();

    for (int c = 0; c < CTXD / 32; c++) {
        CP_WAIT0();
        __syncthreads();
        if (c + 1 < CTXD / 32) { load_chunk((c + 1) << 5, (c + 1) & 1); CP_COMMIT(); }

        uint32_t aB = smBase + (uint32_t)(c & 1) * 20480u;
        uint32_t bB = smBase + 40960u + (uint32_t)(c & 1) * 10240u;
        #pragma unroll
        for (int ks = 0; ks < 2; ks++) {
            const uint32_t kcol = (uint32_t)ks * 16u;
            uint32_t ahi[2][4], alo[2][4], b[4][4];
            #pragma unroll
            for (int g = 0; g < 4; g++) {
                uint32_t off = (bRow + (uint32_t)g * 16u * LDS_BF + kcol) * 2u;
                ldm_x4(b[g], bB + off);
            }
            #pragma unroll
            for (int mi = 0; mi < 2; mi++) {
                uint32_t off = (aRow + (uint32_t)mi * 16u * LDS_BF + kcol) * 2u;
                ldm_x4(ahi[mi], aB + off);
                ldm_x4(alo[mi], aB + 10240u + off);
            }
            #pragma unroll
            for (int mi = 0; mi < 2; mi++)
                #pragma unroll
                for (int nj = 0; nj < 8; nj++)
                    mma16816h(acc[mi][nj], ahi[mi], &b[nj >> 1][(nj & 1) * 2]);
            #pragma unroll
            for (int mi = 0; mi < 2; mi++)
                #pragma unroll
                for (int nj = 0; nj < 8; nj++)
                    mma16816h(acc[mi][nj], alo[mi], &b[nj >> 1][(nj & 1) * 2]);
        }
        __syncthreads();
    }

    #pragma unroll
    for (int mi = 0; mi < 2; mi++) {
        int gm = m0 + wm + mi * 16 + (lane >> 2);
        #pragma unroll
        for (int nj = 0; nj < 8; nj++) {
            int gn = n0 + wn + nj * 8 + (lane & 3) * 2;
            float b0 = bias_n[gn], b1 = bias_n[gn + 1];
            float v00 = acc[mi][nj][0] + b0;
            float v01 = acc[mi][nj][1] + b1;
            float v10 = acc[mi][nj][2] + b0;
            float v11 = acc[mi][nj][3] + b1;
            bf162 h2, l2;
            split2(v00, v01, h2, l2);
            *reinterpret_cast<bf162*>(Chi + (size_t)gm * DMODEL + gn) = h2;
            *reinterpret_cast<bf162*>(Clo + (size_t)gm * DMODEL + gn) = l2;
            split2(v10, v11, h2, l2);
            *reinterpret_cast<bf162*>(Chi + (size_t)(gm + 8) * DMODEL + gn) = h2;
            *reinterpret_cast<bf162*>(Clo + (size_t)(gm + 8) * DMODEL + gn) = l2;
        }
    }
}

// ============================ split-bf16 3-term NT GEMM (O-proj) ============================
#define G3_SMEM 81920

__global__ void __launch_bounds__(256, 2)
oproj_gemm(const bf16* __restrict__ Ahi, const bf16* __restrict__ Alo,
           const bf16* __restrict__ Bhi, const bf16* __restrict__ Blo,
           const float* __restrict__ bias_n, float* __restrict__ C) {
    extern __shared__ char smem[];
    const int tid  = threadIdx.x;
    const int wid  = tid >> 5;
    const int lane = tid & 31;
    const int m0 = blockIdx.y * 128;
    const int n0 = blockIdx.x * 128;
    const int wm = (wid & 3) * 32;
    const int wn = (wid >> 2) * 64;

    const uint32_t smBase = smem_u32(smem);
    const uint32_t aRow = (uint32_t)(wm + (lane & 15)) * LDS_BF + (uint32_t)(lane >> 4) * 8u;
    const uint32_t bRow = (uint32_t)(wn + (lane & 7) + ((lane >> 4) * 8)) * LDS_BF
                        + (uint32_t)((lane >> 3) & 1) * 8u;

    float acc[2][8][4];
    #pragma unroll
    for (int i = 0; i < 2; i++)
        #pragma unroll
        for (int j = 0; j < 8; j++)
            #pragma unroll
            for (int k = 0; k < 4; k++) acc[i][j][k] = 0.f;

    const int r  = tid >> 2;
    const int cc = tid & 3;

    auto load_chunk = [&](int k0, int buf) {
        uint32_t aB = smBase + (uint32_t)buf * 20480u;
        uint32_t bB = smBase + 40960u + (uint32_t)buf * 20480u;
        #pragma unroll
        for (int h = 0; h < 2; h++) {
            int rr = r + h * 64;
            uint32_t so = ((uint32_t)rr * LDS_BF + (uint32_t)cc * 8u) * 2u;
            size_t ga = (size_t)(m0 + rr) * DMODEL + k0 + cc * 8;
            size_t gb = (size_t)(n0 + rr) * DMODEL + k0 + cc * 8;
            cp16(aB + so,           Ahi + ga);
            cp16(aB + 10240u + so,  Alo + ga);
            cp16(bB + so,           Bhi + gb);
            cp16(bB + 10240u + so,  Blo + gb);
        }
    };

    load_chunk(0, 0);
    CP_COMMIT();

    for (int c = 0; c < DMODEL / 32; c++) {
        CP_WAIT0();
        __syncthreads();
        if (c + 1 < DMODEL / 32) { load_chunk((c + 1) << 5, (c + 1) & 1); CP_COMMIT(); }

        uint32_t aB = smBase + (uint32_t)(c & 1) * 20480u;
        uint32_t bB = smBase + 40960u + (uint32_t)(c & 1) * 20480u;
        #pragma unroll
        for (int ks = 0; ks < 2; ks++) {
            const uint32_t kcol = (uint32_t)ks * 16u;
            uint32_t ahi[2][4], alo[2][4], bhi[4][4], blo[4][4];
            #pragma unroll
            for (int g = 0; g < 4; g++) {
                uint32_t off = (bRow + (uint32_t)g * 16u * LDS_BF + kcol) * 2u;
                ldm_x4(bhi[g], bB + off);
                ldm_x4(blo[g], bB + 10240u + off);
            }
            #pragma unroll
            for (int mi = 0; mi < 2; mi++) {
                uint32_t off = (aRow + (uint32_t)mi * 16u * LDS_BF + kcol) * 2u;
                ldm_x4(ahi[mi], aB + off);
                ldm_x4(alo[mi], aB + 10240u + off);
            }
            #pragma unroll
            for (int mi = 0; mi < 2; mi++)
                #pragma unroll
                for (int nj = 0; nj < 8; nj++)
                    mma16816(acc[mi][nj], ahi[mi], &bhi[nj >> 1][(nj & 1) * 2]);
            #pragma unroll
            for (int mi = 0; mi < 2; mi++)
                #pragma unroll
                for (int nj = 0; nj < 8; nj++)
                    mma16816(acc[mi][nj], alo[mi], &bhi[nj >> 1][(nj & 1) * 2]);
            #pragma unroll
            for (int mi = 0; mi < 2; mi++)
                #pragma unroll
                for (int nj = 0; nj < 8; nj++)
                    mma16816(acc[mi][nj], ahi[mi], &blo[nj >> 1][(nj & 1) * 2]);
        }
        __syncthreads();
    }

    #pragma unroll
    for (int mi = 0; mi < 2; mi++) {
        int gm = m0 + wm + mi * 16 + (lane >> 2);
        #pragma unroll
        for (int nj = 0; nj < 8; nj++) {
            int gn = n0 + wn + nj * 8 + (lane & 3) * 2;
            float b0 = bias_n[gn], b1 = bias_n[gn + 1];
            *reinterpret_cast<float2*>(C + (size_t)gm * DMODEL + gn) =
                make_float2(acc[mi][nj][0] + b0, acc[mi][nj][1] + b1);
            *reinterpret_cast<float2*>(C + (size_t)(gm + 8) * DMODEL + gn) =
                make_float2(acc[mi][nj][2] + b0, acc[mi][nj][3] + b1);
        }
    }
}

// ============================ fused flash attention ============================
#define FA_SMEM 160256
#define FA_LDS 104

__global__ void __launch_bounds__(256, 1)
fa_kernel(const bf16* __restrict__ Qhi, const bf16* __restrict__ Qlo,
          const bf16* __restrict__ Khi, const bf16* __restrict__ Klo,
          const bf16* __restrict__ Vhi, const bf16* __restrict__ Vlo,
          const float* __restrict__ biasBL, float scale,
          bf16* __restrict__ Ohi, bf16* __restrict__ Olo) {
    extern __shared__ char smem[];
    const int tid = threadIdx.x;
    const int wid = tid >> 5, lane = tid & 31;
    const int z = blockIdx.y;
    const int b = z >> 3, h = z & 7;
    const int q0 = blockIdx.x * 128;
    const size_t bSeq = (size_t)b * SEQ;
    const int hOff = h * HDIM;

    const uint32_t smBase = smem_u32(smem);
    const uint32_t KBASE = 53248u, VBASE = 106496u, TSTR = 13312u, BBASE = 159744u;

    for (int i = tid; i < 1536; i += 256) {
        int row = i / 12, col = i % 12;
        uint32_t so = ((uint32_t)row * FA_LDS + (uint32_t)col * 8u) * 2u;
        size_t go = (size_t)(q0 + row) * DMODEL + hOff + col * 8;
        cp16(smBase + so,           Qhi + go);
        cp16(smBase + 26624u + so,  Qlo + go);
    }
    CP_COMMIT();

    auto load_kv = [&](int c, int buf) {
        int l0 = c * 64;
        uint32_t kB = smBase + KBASE + (uint32_t)buf * 26624u;
        uint32_t vB = smBase + VBASE + (uint32_t)buf * 26624u;
        for (int i = tid; i < 768; i += 256) {
            int row = i / 12, col = i % 12;
            uint32_t so = ((uint32_t)row * FA_LDS + (uint32_t)col * 8u) * 2u;
            size_t go = (bSeq + l0 + row) * DMODEL + hOff + col * 8;
            cp16(kB + so,        Khi + go);
            cp16(kB + TSTR + so, Klo + go);
            cp16(vB + so,        Vhi + go);
            cp16(vB + TSTR + so, Vlo + go);
        }
        if (tid < 16)
            cp16(smBase + BBASE + (uint32_t)buf * 256u + (uint32_t)tid * 16u,
                 biasBL + bSeq + l0 + tid * 4);
    };
    load_kv(0, 0);
    CP_COMMIT();

    const uint32_t aRow = (uint32_t)(wid * 16 + (lane & 15)) * FA_LDS + (uint32_t)(lane >> 4) * 8u;
    const uint32_t bRow = (uint32_t)((lane & 7) + ((lane >> 4) * 8)) * FA_LDS
                        + (uint32_t)((lane >> 3) & 1) * 8u;
    const uint32_t vLaneRow = (uint32_t)((lane & 7) + ((lane >> 3) & 1) * 8);
    const uint32_t vLaneCol = (uint32_t)(lane >> 4) * 8u;

    float oacc[12][4];
    #pragma unroll
    for (int j = 0; j < 12; j++)
        #pragma unroll
        for (int k = 0; k < 4; k++) oacc[j][k] = 0.f;
    float m0 = -1e30f, m1 = -1e30f, l0s = 0.f, l1s = 0.f;

    for (int c = 0; c < 16; c++) {
        CP_WAIT0();
        __syncthreads();
        if (c + 1 < 16) { load_kv(c + 1, (c + 1) & 1); CP_COMMIT(); }

        const uint32_t kB = smBase + KBASE + (uint32_t)(c & 1) * 26624u;
        const uint32_t vB = smBase + VBASE + (uint32_t)(c & 1) * 26624u;
        const float* sbias = reinterpret_cast<const float*>(smem + BBASE + (c & 1) * 256);

        float s[8][4];
        #pragma unroll
        for (int j = 0; j < 8; j++)
            #pragma unroll
            for (int k = 0; k < 4; k++) s[j][k] = 0.f;

        #pragma unroll
        for (int ks = 0; ks < 6; ks++) {
            const uint32_t kcol = (uint32_t)ks * 16u;
            uint32_t qhiF[4], qloF[4], kk[4];
            uint32_t qoff = (aRow + kcol) * 2u;
            ldm_x4(qhiF, smBase + qoff);
            ldm_x4(qloF, smBase + 26624u + qoff);
            #pragma unroll
            for (int g = 0; g < 4; g++) {
                uint32_t off = (bRow + (uint32_t)g * 16u * FA_LDS + kcol) * 2u;
                ldm_x4(kk, kB + off);
                mma16816(s[2 * g],     qhiF, &kk[0]);
                mma16816(s[2 * g + 1], qhiF, &kk[2]);
                mma16816(s[2 * g],     qloF, &kk[0]);
                mma16816(s[2 * g + 1], qloF, &kk[2]);
                ldm_x4(kk, kB + TSTR + off);
                mma16816(s[2 * g],     qhiF, &kk[0]);
                mma16816(s[2 * g + 1], qhiF, &kk[2]);
            }
        }

        float mx0 = -1e30f, mx1 = -1e30f;
        #pragma unroll
        for (int nj = 0; nj < 8; nj++) {
            int cidx = nj * 8 + (lane & 3) * 2;
            float bj0 = sbias[cidx], bj1 = sbias[cidx + 1];
            s[nj][0] = s[nj][0] * scale + bj0;
            s[nj][1] = s[nj][1] * scale + bj1;
            s[nj][2] = s[nj][2] * scale + bj0;
            s[nj][3] = s[nj][3] * scale + bj1;
            mx0 = fmaxf(mx0, fmaxf(s[nj][0], s[nj][1]));
            mx1 = fmaxf(mx1, fmaxf(s[nj][2], s[nj][3]));
        }
        #pragma unroll
        for (int o = 1; o <= 2; o <<= 1) {
            mx0 = fmaxf(mx0, __shfl_xor_sync(0xffffffffu, mx0, o));
            mx1 = fmaxf(mx1, __shfl_xor_sync(0xffffffffu, mx1, o));
        }
        float mn0 = fmaxf(m0, mx0), mn1 = fmaxf(m1, mx1);
        float cor0 = __expf(m0 - mn0), cor1 = __expf(m1 - mn1);
        l0s *= cor0; l1s *= cor1;
        #pragma unroll
        for (int j = 0; j < 12; j++) {
            oacc[j][0] *= cor0; oacc[j][1] *= cor0;
            oacc[j][2] *= cor1; oacc[j][3] *= cor1;
        }
        m0 = mn0; m1 = mn1;

        float rs0 = 0.f, rs1 = 0.f;
        uint32_t phiF[4][4], ploF[4][4];
        #pragma unroll
        for (int t = 0; t < 4; t++) {
            float p00 = __expf(s[2 * t][0] - mn0);
            float p01 = __expf(s[2 * t][1] - mn0);
            float p10 = __expf(s[2 * t][2] - mn1);
            float p11 = __expf(s[2 * t][3] - mn1);
            float p20 = __expf(s[2 * t + 1][0] - mn0);
            float p21 = __expf(s[2 * t + 1][1] - mn0);
            float p30 = __expf(s[2 * t + 1][2] - mn1);
            float p31 = __expf(s[2 * t + 1][3] - mn1);
            rs0 += p00 + p01 + p20 + p21;
            rs1 += p10 + p11 + p30 + p31;
            splitpack(p00, p01, phiF[t][0], ploF[t][0]);
            splitpack(p10, p11, phiF[t][1], ploF[t][1]);
            splitpack(p20, p21, phiF[t][2], ploF[t][2]);
            splitpack(p30, p31, phiF[t][3], ploF[t][3]);
        }
        #pragma unroll
        for (int o = 1; o <= 2; o <<= 1) {
            rs0 += __shfl_xor_sync(0xffffffffu, rs0, o);
            rs1 += __shfl_xor_sync(0xffffffffu, rs1, o);
        }
        l0s += rs0; l1s += rs1;

        #pragma unroll
        for (int t = 0; t < 4; t++) {
            uint32_t vv[4];
            #pragma unroll
            for (int g = 0; g < 6; g++) {
                uint32_t off = (((uint32_t)t * 16u + vLaneRow) * FA_LDS
                                + (uint32_t)g * 16u + vLaneCol) * 2u;
                ldm_x4_t(vv, vB + off);
                mma16816(oacc[2 * g],     phiF[t], &vv[0]);
                mma16816(oacc[2 * g + 1], phiF[t], &vv[2]);
                mma16816(oacc[2 * g],     ploF[t], &vv[0]);
                mma16816(oacc[2 * g + 1], ploF[t], &vv[2]);
                ldm_x4_t(vv, vB + TSTR + off);
                mma16816(oacc[2 * g],     phiF[t], &vv[0]);
                mma16816(oacc[2 * g + 1], phiF[t], &vv[2]);
            }
        }
    }

    float inv0 = 1.0f / l0s, inv1 = 1.0f / l1s;
    const int q = q0 + wid * 16 + (lane >> 2);
    #pragma unroll
    for (int j = 0; j < 12; j++) {
        int n = j * 8 + (lane & 3) * 2;
        size_t o0 = ((size_t)(b * NQ + q)) * DMODEL + hOff + n;
        size_t o1 = o0 + (size_t)8 * DMODEL;
        bf162 h2, l2;
        split2(oacc[j][0] * inv0, oacc[j][1] * inv0, h2, l2);
        *reinterpret_cast<bf162*>(Ohi + o0) = h2;
        *reinterpret_cast<bf162*>(Olo + o0) = l2;
        split2(oacc[j][2] * inv1, oacc[j][3] * inv1, h2, l2);
        *reinterpret_cast<bf162*>(Ohi + o1) = h2;
        *reinterpret_cast<bf162*>(Olo + o1) = l2;
    }
}

// ============================ LayerNorm / misc ============================
__device__ __forceinline__ void ln_stats(const float* __restrict__ xr, int ncols,
                                         float& mu, float& rs, float* s1, float* s2) {
    float sum = 0.f, sumsq = 0.f;
    for (int i = threadIdx.x; i < ncols; i += blockDim.x) {
        float v = xr[i];
        sum += v; sumsq += v * v;
    }
    #pragma unroll
    for (int o = 16; o; o >>= 1) {
        sum   += __shfl_xor_sync(0xffffffffu, sum, o);
        sumsq += __shfl_xor_sync(0xffffffffu, sumsq, o);
    }
    int wid = threadIdx.x >> 5, lid = threadIdx.x & 31;
    if (lid == 0) { s1[wid] = sum; s2[wid] = sumsq; }
    __syncthreads();
    if (threadIdx.x < 32) {
        int nw = blockDim.x >> 5;
        float a = (lid < nw) ? s1[lid] : 0.f;
        float c = (lid < nw) ? s2[lid] : 0.f;
        #pragma unroll
        for (int o = 16; o; o >>= 1) {
            a += __shfl_xor_sync(0xffffffffu, a, o);
            c += __shfl_xor_sync(0xffffffffu, c, o);
        }
        if (lid == 0) { s1[0] = a; s2[0] = c; }
    }
    __syncthreads();
    float inv_n = 1.0f / (float)ncols;
    mu = s1[0] * inv_n;
    float var = s2[0] * inv_n - mu * mu;
    rs = rsqrtf(var + 1e-5f);
}

__global__ void ln_kernel(const float* __restrict__ x, const float* __restrict__ w,
                          const float* __restrict__ b, float* __restrict__ out, int ncols) {
    __shared__ float s1[32], s2[32];
    const size_t row = blockIdx.x;
    const float* xr = x + row * (size_t)ncols;
    float mu, rs;
    ln_stats(xr, ncols, mu, rs, s1, s2);
    float* orow = out + row * (size_t)ncols;
    for (int i = threadIdx.x; i < ncols; i += blockDim.x)
        orow[i] = (xr[i] - mu) * rs * w[i] + b[i];
}

// LN + split into fp16 hi/lo
__global__ void ln_split_h_kernel(const float* __restrict__ x, const float* __restrict__ w,
                                  const float* __restrict__ b,
                                  __half* __restrict__ hi, __half* __restrict__ lo, int ncols) {
    __shared__ float s1[32], s2[32];
    const size_t row = blockIdx.x;
    const float* xr = x + row * (size_t)ncols;
    float mu, rs;
    ln_stats(xr, ncols, mu, rs, s1, s2);
    __half* hrow = hi + row * (size_t)ncols;
    __half* lrow = lo + row * (size_t)ncols;
    for (int i = threadIdx.x; i < ncols; i += blockDim.x) {
        float y = (xr[i] - mu) * rs * w[i] + b[i];
        __half hh = __float2half_rn(y);
        hrow[i] = hh;
        lrow[i] = __float2half_rn(y - __half2float(hh));
    }
}

// f32 -> single fp16
__global__ void cvt_h_kernel(const float* __restrict__ x, __half* __restrict__ o, int n) {
    int i = blockIdx.x * blockDim.x + threadIdx.x;
    if (i < n) o[i] = __float2half_rn(x[i]);
}

__global__ void split_kernel(const float* __restrict__ x,
                             bf16* __restrict__ hi, bf16* __restrict__ lo, int n) {
    int i = blockIdx.x * blockDim.x + threadIdx.x;
    if (i < n) {
        float v = x[i];
        bf16 h = __float2bfloat16(v);
        hi[i] = h;
        lo[i] = __float2bfloat16(v - __bfloat162float(h));
    }
}

__global__ void bias_kernel(const float* __restrict__ size_in, const float* __restrict__ mask,
                            float* __restrict__ bias, int n) {
    int i = blockIdx.x * blockDim.x + threadIdx.x;
    if (i < n) {
        float s = size_in[i];
        s = (s < 0.5f) ? 1.0f : s;
        bias[i] = logf(s) + mask[i];
    }
}

// ============================ SIMT GEMM (Q-proj only) ============================
#define TBM 64
#define TBN 64
#define TBK 16
#define SPAD 4

__global__ void __launch_bounds__(256)
gemm_nt_kernel(const float* __restrict__ A, int lda,
               const float* __restrict__ B, int ldb,
               float* __restrict__ C, int ldc,
               int M, int N, int K, float alpha, const float* __restrict__ bias_n) {
    __shared__ __align__(16) float As[TBK][TBM + SPAD];
    __shared__ __align__(16) float Bs[TBK][TBN + SPAD];
    const int m0 = blockIdx.y * TBM;
    const int n0 = blockIdx.x * TBN;
    const int t  = threadIdx.x;
    const int tx = t & 15, ty = t >> 4;
    float acc[4][4] = {};
    for (int k0 = 0; k0 < K; k0 += TBK) {
        {
            int col = t & 15, rowb = t >> 4;
            #pragma unroll
            for (int i = 0; i < 4; i++) {
                int rr = rowb + i * 16;
                As[col][rr] = A[(size_t)(m0 + rr) * lda + k0 + col];
            }
        }
        {
            int col = t & 15, rowb = t >> 4;
            #pragma unroll
            for (int i = 0; i < 4; i++) {
                int nn = rowb + i * 16;
                Bs[col][nn] = B[(size_t)(n0 + nn) * ldb + k0 + col];
            }
        }
        __syncthreads();
        #pragma unroll
        for (int kk = 0; kk < TBK; kk++) {
            float4 av = *reinterpret_cast<const float4*>(&As[kk][ty * 4]);
            float4 bv = *reinterpret_cast<const float4*>(&Bs[kk][tx * 4]);
            float a[4] = {av.x, av.y, av.z, av.w};
            float b[4] = {bv.x, bv.y, bv.z, bv.w};
            #pragma unroll
            for (int i = 0; i < 4; i++)
                #pragma unroll
                for (int j = 0; j < 4; j++)
                    acc[i][j] += a[i] * b[j];
        }
        __syncthreads();
    }
    #pragma unroll
    for (int i = 0; i < 4; i++) {
        int gm = m0 + ty * 4 + i;
        #pragma unroll
        for (int j = 0; j < 4; j++) {
            int gn = n0 + tx * 4 + j;
            float v = alpha * acc[i][j];
            if (bias_n) v += bias_n[gn];
            C[(size_t)gm * ldc + gn] = v;
        }
    }
}

// ============================ launch ============================
extern "C" void kernel_launch(void* const* d_in, const int* in_sizes, int n_in,
                              void* d_out, int out_size) {
    const float* x     = (const float*)d_in[0];
    const float* sizei = (const float*)d_in[1];
    const float* amask = (const float*)d_in[2];
    const float* query = (const float*)d_in[3];
    const float* ln_q_w = (const float*)d_in[4];
    const float* ln_q_b = (const float*)d_in[5];
    const float* ln_k_w = (const float*)d_in[6];
    const float* ln_k_b = (const float*)d_in[7];
    const float* Wq = (const float*)d_in[8];
    const float* Wk = (const float*)d_in[9];
    const float* Wv = (const float*)d_in[10];
    const float* bq = (const float*)d_in[11];
    const float* bk = (const float*)d_in[12];
    const float* bv = (const float*)d_in[13];
    const float* Wo = (const float*)d_in[14];
    const float* bo = (const float*)d_in[15];
    float* out = (float*)d_out;

    __half *x16hi, *x16lo, *wk16, *wv16;
    bf16 *wohi, *wolo, *khhi, *khlo, *vhhi, *vhlo, *qhhi, *qhlo, *aohi, *aolo;
    float *qln, *qh, *bias;
    cudaGetSymbolAddress((void**)&x16hi, g_x16hi);
    cudaGetSymbolAddress((void**)&x16lo, g_x16lo);
    cudaGetSymbolAddress((void**)&wk16, g_wk16);
    cudaGetSymbolAddress((void**)&wv16, g_wv16);
    cudaGetSymbolAddress((void**)&wohi, g_wohi);
    cudaGetSymbolAddress((void**)&wolo, g_wolo);
    cudaGetSymbolAddress((void**)&khhi, g_khhi);
    cudaGetSymbolAddress((void**)&khlo, g_khlo);
    cudaGetSymbolAddress((void**)&vhhi, g_vhhi);
    cudaGetSymbolAddress((void**)&vhlo, g_vhlo);
    cudaGetSymbolAddress((void**)&qhhi, g_qhhi);
    cudaGetSymbolAddress((void**)&qhlo, g_qhlo);
    cudaGetSymbolAddress((void**)&aohi, g_aohi);
    cudaGetSymbolAddress((void**)&aolo, g_aolo);
    cudaGetSymbolAddress((void**)&qln, g_qln);
    cudaGetSymbolAddress((void**)&qh, g_qh);
    cudaGetSymbolAddress((void**)&bias, g_bias);

    cudaFuncSetAttribute(kv_gemm_h,  cudaFuncAttributeMaxDynamicSharedMemorySize, G2_SMEM);
    cudaFuncSetAttribute(oproj_gemm, cudaFuncAttributeMaxDynamicSharedMemorySize, G3_SMEM);
    cudaFuncSetAttribute(fa_kernel,  cudaFuncAttributeMaxDynamicSharedMemorySize, FA_SMEM);

    const float scale = 0.10206207261596575f;  // 1/sqrt(96)

    // launch order: index 3 (ncu-profiled) = kv_gemm_h(K)
    ln_split_h_kernel<<<MROWS, 256>>>(x, ln_k_w, ln_k_b, x16hi, x16lo, CTXD);          // 0
    cvt_h_kernel<<<(DMODEL * CTXD + 255) / 256, 256>>>(Wk, wk16, DMODEL * CTXD);       // 1
    cvt_h_kernel<<<(DMODEL * CTXD + 255) / 256, 256>>>(Wv, wv16, DMODEL * CTXD);       // 2
    {
        dim3 grid(DMODEL / 128, MROWS / 128);
        kv_gemm_h<<<grid, 256, G2_SMEM>>>(x16hi, x16lo, wk16, bk, khhi, khlo);         // 3 (profiled)
        kv_gemm_h<<<grid, 256, G2_SMEM>>>(x16hi, x16lo, wv16, bv, vhhi, vhlo);         // 4
    }
    ln_kernel<<<NQ, 256>>>(query, ln_q_w, ln_q_b, qln, DMODEL);                        // 5
    split_kernel<<<(DMODEL * DMODEL + 255) / 256, 256>>>(Wo, wohi, wolo, DMODEL * DMODEL); // 6
    bias_kernel<<<(MROWS + 255) / 256, 256>>>(sizei, amask, bias, MROWS);              // 7
    gemm_nt_kernel<<<dim3(DMODEL / TBN, NQ / TBM), 256>>>(                             // 8
        qln, DMODEL, Wq, DMODEL, qh, DMODEL, NQ, DMODEL, DMODEL, 1.0f, bq);
    split_kernel<<<(NQ * DMODEL + 255) / 256, 256>>>(qh, qhhi, qhlo, NQ * DMODEL);     // 9

    fa_kernel<<<dim3(NQ / 128, NZ), 256, FA_SMEM>>>(                                   // 10
        qhhi, qhlo, khhi, khlo, vhhi, vhlo, bias, scale, aohi, aolo);

    oproj_gemm<<<dim3(DMODEL / 128, BATCH * NQ / 128), 256, G3_SMEM>>>(                // 11
        aohi, aolo, wohi, wolo, bo, out);
}

// round 10
// speedup vs baseline: 1.3936x; 1.1281x over previous
#include <cuda_runtime.h>
#include <cuda_bf16.h>
#include <cuda_fp16.h>
#include <cstdint>

#define BATCH     32
#define SEQ       1024
#define CTXD      1024
#define DMODEL    768
#define NHEAD     8
#define HDIM      96
#define NQ        256
#define MROWS     (BATCH * SEQ)   // 32768
#define NZ        (BATCH * NHEAD) // 256

typedef __nv_bfloat16 bf16;
typedef __nv_bfloat162 bf162;

// ============================ device scratch ============================
__device__ __half g_x16hi[MROWS * CTXD];          // LN(x) fp16 hi
__device__ __half g_x16lo[MROWS * CTXD];          // LN(x) fp16 lo
__device__ __half g_wk16[DMODEL * CTXD];          // Wk fp16
__device__ __half g_wv16[DMODEL * CTXD];          // Wv fp16
__device__ __half g_kh16[MROWS * DMODEL];         // K proj, single fp16
__device__ __half g_vh16[MROWS * DMODEL];         // V proj, single fp16
__device__ __half g_qh16hi[NQ * DMODEL];          // Q proj fp16 hi
__device__ __half g_qh16lo[NQ * DMODEL];          // Q proj fp16 lo
__device__ bf16 g_wohi[DMODEL * DMODEL];
__device__ bf16 g_wolo[DMODEL * DMODEL];
__device__ bf16 g_aohi[BATCH * NQ * DMODEL];
__device__ bf16 g_aolo[BATCH * NQ * DMODEL];
__device__ float g_qln[NQ * DMODEL];
__device__ float g_qh[NQ * DMODEL];
__device__ float g_bias[MROWS];

// ============================ asm helpers ============================
__device__ __forceinline__ uint32_t smem_u32(const void* p) {
    uint32_t a;
    asm("{ .reg .u64 t; cvta.to.shared.u64 t, %1; cvt.u32.u64 %0, t; }" : "=r"(a) : "l"(p));
    return a;
}
__device__ __forceinline__ void ldm_x4(uint32_t* r, uint32_t addr) {
    asm volatile("ldmatrix.sync.aligned.m8n8.x4.shared.b16 {%0,%1,%2,%3}, [%4];"
                 : "=r"(r[0]), "=r"(r[1]), "=r"(r[2]), "=r"(r[3]) : "r"(addr));
}
__device__ __forceinline__ void ldm_x4_t(uint32_t* r, uint32_t addr) {
    asm volatile("ldmatrix.sync.aligned.m8n8.x4.trans.shared.b16 {%0,%1,%2,%3}, [%4];"
                 : "=r"(r[0]), "=r"(r[1]), "=r"(r[2]), "=r"(r[3]) : "r"(addr));
}
__device__ __forceinline__ void mma16816(float* c, const uint32_t* a, const uint32_t* b) {
    asm volatile("mma.sync.aligned.m16n8k16.row.col.f32.bf16.bf16.f32 "
                 "{%0,%1,%2,%3}, {%4,%5,%6,%7}, {%8,%9}, {%0,%1,%2,%3};"
                 : "+f"(c[0]), "+f"(c[1]), "+f"(c[2]), "+f"(c[3])
                 : "r"(a[0]), "r"(a[1]), "r"(a[2]), "r"(a[3]), "r"(b[0]), "r"(b[1]));
}
__device__ __forceinline__ void mma16816h(float* c, const uint32_t* a, const uint32_t* b) {
    asm volatile("mma.sync.aligned.m16n8k16.row.col.f32.f16.f16.f32 "
                 "{%0,%1,%2,%3}, {%4,%5,%6,%7}, {%8,%9}, {%0,%1,%2,%3};"
                 : "+f"(c[0]), "+f"(c[1]), "+f"(c[2]), "+f"(c[3])
                 : "r"(a[0]), "r"(a[1]), "r"(a[2]), "r"(a[3]), "r"(b[0]), "r"(b[1]));
}
__device__ __forceinline__ void cp16(uint32_t dst, const void* src) {
    asm volatile("cp.async.cg.shared.global [%0], [%1], 16;" :: "r"(dst), "l"(src));
}
#define CP_COMMIT() asm volatile("cp.async.commit_group;")
#define CP_WAIT0()  asm volatile("cp.async.wait_group 0;")

__device__ __forceinline__ void split2(float v0, float v1, bf162& h2, bf162& l2) {
    bf16 h0 = __float2bfloat16(v0);
    bf16 h1 = __float2bfloat16(v1);
    h2 = bf162(h0, h1);
    l2 = bf162(__float2bfloat16(v0 - __bfloat162float(h0)),
               __float2bfloat16(v1 - __bfloat162float(h1)));
}
__device__ __forceinline__ uint32_t packh2(float v0, float v1) {
    __half2 h = __floats2half2_rn(v0, v1);
    return *reinterpret_cast<uint32_t*>(&h);
}

#define LDS_BF 40

// ============================ fp16 2-term NT GEMM (KV projections) ============================
// C16[M,N] = (Ahi+Alo)[m,k] * B16[n,k]^T + bias_n, single fp16 output.
#define G2_SMEM 61440

__global__ void __launch_bounds__(256, 2)
kv_gemm_h(const __half* __restrict__ Ahi, const __half* __restrict__ Alo,
          const __half* __restrict__ B16,
          const float* __restrict__ bias_n,
          __half* __restrict__ C16) {
    extern __shared__ char smem[];
    const int tid  = threadIdx.x;
    const int wid  = tid >> 5;
    const int lane = tid & 31;
    const int m0 = blockIdx.y * 128;
    const int n0 = blockIdx.x * 128;
    const int wm = (wid & 3) * 32;
    const int wn = (wid >> 2) * 64;

    const uint32_t smBase = smem_u32(smem);
    const uint32_t aRow = (uint32_t)(wm + (lane & 15)) * LDS_BF + (uint32_t)(lane >> 4) * 8u;
    const uint32_t bRow = (uint32_t)(wn + (lane & 7) + ((lane >> 4) * 8)) * LDS_BF
                        + (uint32_t)((lane >> 3) & 1) * 8u;

    float acc[2][8][4];
    #pragma unroll
    for (int i = 0; i < 2; i++)
        #pragma unroll
        for (int j = 0; j < 8; j++)
            #pragma unroll
            for (int k = 0; k < 4; k++) acc[i][j][k] = 0.f;

    const int r  = tid >> 2;
    const int cc = tid & 3;

    auto load_chunk = [&](int k0, int buf) {
        uint32_t aB = smBase + (uint32_t)buf * 20480u;
        uint32_t bB = smBase + 40960u + (uint32_t)buf * 10240u;
        #pragma unroll
        for (int h = 0; h < 2; h++) {
            int rr = r + h * 64;
            uint32_t so = ((uint32_t)rr * LDS_BF + (uint32_t)cc * 8u) * 2u;
            size_t ga = (size_t)(m0 + rr) * CTXD + k0 + cc * 8;
            size_t gb = (size_t)(n0 + rr) * CTXD + k0 + cc * 8;
            cp16(aB + so,          Ahi + ga);
            cp16(aB + 10240u + so, Alo + ga);
            cp16(bB + so,          B16 + gb);
        }
    };

    load_chunk(0, 0);
    CP_COMMIT();

    for (int c = 0; c < CTXD / 32; c++) {
        CP_WAIT0();
        __syncthreads();
        if (c + 1 < CTXD / 32) { load_chunk((c + 1) << 5, (c + 1) & 1); CP_COMMIT(); }

        uint32_t aB = smBase + (uint32_t)(c & 1) * 20480u;
        uint32_t bB = smBase + 40960u + (uint32_t)(c & 1) * 10240u;
        #pragma unroll
        for (int ks = 0; ks < 2; ks++) {
            const uint32_t kcol = (uint32_t)ks * 16u;
            uint32_t ahi[2][4], alo[2][4], b[4][4];
            #pragma unroll
            for (int g = 0; g < 4; g++) {
                uint32_t off = (bRow + (uint32_t)g * 16u * LDS_BF + kcol) * 2u;
                ldm_x4(b[g], bB + off);
            }
            #pragma unroll
            for (int mi = 0; mi < 2; mi++) {
                uint32_t off = (aRow + (uint32_t)mi * 16u * LDS_BF + kcol) * 2u;
                ldm_x4(ahi[mi], aB + off);
                ldm_x4(alo[mi], aB + 10240u + off);
            }
            #pragma unroll
            for (int mi = 0; mi < 2; mi++)
                #pragma unroll
                for (int nj = 0; nj < 8; nj++)
                    mma16816h(acc[mi][nj], ahi[mi], &b[nj >> 1][(nj & 1) * 2]);
            #pragma unroll
            for (int mi = 0; mi < 2; mi++)
                #pragma unroll
                for (int nj = 0; nj < 8; nj++)
                    mma16816h(acc[mi][nj], alo[mi], &b[nj >> 1][(nj & 1) * 2]);
        }
        __syncthreads();
    }

    #pragma unroll
    for (int mi = 0; mi < 2; mi++) {
        int gm = m0 + wm + mi * 16 + (lane >> 2);
        #pragma unroll
        for (int nj = 0; nj < 8; nj++) {
            int gn = n0 + wn + nj * 8 + (lane & 3) * 2;
            float b0 = bias_n[gn], b1 = bias_n[gn + 1];
            uint32_t p0 = packh2(acc[mi][nj][0] + b0, acc[mi][nj][1] + b1);
            uint32_t p1 = packh2(acc[mi][nj][2] + b0, acc[mi][nj][3] + b1);
            *reinterpret_cast<uint32_t*>(C16 + (size_t)gm * DMODEL + gn)       = p0;
            *reinterpret_cast<uint32_t*>(C16 + (size_t)(gm + 8) * DMODEL + gn) = p1;
        }
    }
}

// ============================ split-bf16 3-term NT GEMM (O-proj) ============================
#define G3_SMEM 81920

__global__ void __launch_bounds__(256, 2)
oproj_gemm(const bf16* __restrict__ Ahi, const bf16* __restrict__ Alo,
           const bf16* __restrict__ Bhi, const bf16* __restrict__ Blo,
           const float* __restrict__ bias_n, float* __restrict__ C) {
    extern __shared__ char smem[];
    const int tid  = threadIdx.x;
    const int wid  = tid >> 5;
    const int lane = tid & 31;
    const int m0 = blockIdx.y * 128;
    const int n0 = blockIdx.x * 128;
    const int wm = (wid & 3) * 32;
    const int wn = (wid >> 2) * 64;

    const uint32_t smBase = smem_u32(smem);
    const uint32_t aRow = (uint32_t)(wm + (lane & 15)) * LDS_BF + (uint32_t)(lane >> 4) * 8u;
    const uint32_t bRow = (uint32_t)(wn + (lane & 7) + ((lane >> 4) * 8)) * LDS_BF
                        + (uint32_t)((lane >> 3) & 1) * 8u;

    float acc[2][8][4];
    #pragma unroll
    for (int i = 0; i < 2; i++)
        #pragma unroll
        for (int j = 0; j < 8; j++)
            #pragma unroll
            for (int k = 0; k < 4; k++) acc[i][j][k] = 0.f;

    const int r  = tid >> 2;
    const int cc = tid & 3;

    auto load_chunk = [&](int k0, int buf) {
        uint32_t aB = smBase + (uint32_t)buf * 20480u;
        uint32_t bB = smBase + 40960u + (uint32_t)buf * 20480u;
        #pragma unroll
        for (int h = 0; h < 2; h++) {
            int rr = r + h * 64;
            uint32_t so = ((uint32_t)rr * LDS_BF + (uint32_t)cc * 8u) * 2u;
            size_t ga = (size_t)(m0 + rr) * DMODEL + k0 + cc * 8;
            size_t gb = (size_t)(n0 + rr) * DMODEL + k0 + cc * 8;
            cp16(aB + so,           Ahi + ga);
            cp16(aB + 10240u + so,  Alo + ga);
            cp16(bB + so,           Bhi + gb);
            cp16(bB + 10240u + so,  Blo + gb);
        }
    };

    load_chunk(0, 0);
    CP_COMMIT();

    for (int c = 0; c < DMODEL / 32; c++) {
        CP_WAIT0();
        __syncthreads();
        if (c + 1 < DMODEL / 32) { load_chunk((c + 1) << 5, (c + 1) & 1); CP_COMMIT(); }

        uint32_t aB = smBase + (uint32_t)(c & 1) * 20480u;
        uint32_t bB = smBase + 40960u + (uint32_t)(c & 1) * 20480u;
        #pragma unroll
        for (int ks = 0; ks < 2; ks++) {
            const uint32_t kcol = (uint32_t)ks * 16u;
            uint32_t ahi[2][4], alo[2][4], bhi[4][4], blo[4][4];
            #pragma unroll
            for (int g = 0; g < 4; g++) {
                uint32_t off = (bRow + (uint32_t)g * 16u * LDS_BF + kcol) * 2u;
                ldm_x4(bhi[g], bB + off);
                ldm_x4(blo[g], bB + 10240u + off);
            }
            #pragma unroll
            for (int mi = 0; mi < 2; mi++) {
                uint32_t off = (aRow + (uint32_t)mi * 16u * LDS_BF + kcol) * 2u;
                ldm_x4(ahi[mi], aB + off);
                ldm_x4(alo[mi], aB + 10240u + off);
            }
            #pragma unroll
            for (int mi = 0; mi < 2; mi++)
                #pragma unroll
                for (int nj = 0; nj < 8; nj++)
                    mma16816(acc[mi][nj], ahi[mi], &bhi[nj >> 1][(nj & 1) * 2]);
            #pragma unroll
            for (int mi = 0; mi < 2; mi++)
                #pragma unroll
                for (int nj = 0; nj < 8; nj++)
                    mma16816(acc[mi][nj], alo[mi], &bhi[nj >> 1][(nj & 1) * 2]);
            #pragma unroll
            for (int mi = 0; mi < 2; mi++)
                #pragma unroll
                for (int nj = 0; nj < 8; nj++)
                    mma16816(acc[mi][nj], ahi[mi], &blo[nj >> 1][(nj & 1) * 2]);
        }
        __syncthreads();
    }

    #pragma unroll
    for (int mi = 0; mi < 2; mi++) {
        int gm = m0 + wm + mi * 16 + (lane >> 2);
        #pragma unroll
        for (int nj = 0; nj < 8; nj++) {
            int gn = n0 + wn + nj * 8 + (lane & 3) * 2;
            float b0 = bias_n[gn], b1 = bias_n[gn + 1];
            *reinterpret_cast<float2*>(C + (size_t)gm * DMODEL + gn) =
                make_float2(acc[mi][nj][0] + b0, acc[mi][nj][1] + b1);
            *reinterpret_cast<float2*>(C + (size_t)(gm + 8) * DMODEL + gn) =
                make_float2(acc[mi][nj][2] + b0, acc[mi][nj][3] + b1);
        }
    }
}

// ============================ fused flash attention (fp16) ============================
// Q split fp16 hi/lo; K,V single fp16; P single fp16.
// smem: Qhi @0 (26624), Qlo @26624, K @53248 (2x13312), V @79872 (2x13312), bias @106496 (2x256)
#define FA_SMEM 107008
#define FA_LDS 104

__global__ void __launch_bounds__(256, 1)
fa_kernel(const __half* __restrict__ Qhi, const __half* __restrict__ Qlo,
          const __half* __restrict__ K16, const __half* __restrict__ V16,
          const float* __restrict__ biasBL, float scale,
          bf16* __restrict__ Ohi, bf16* __restrict__ Olo) {
    extern __shared__ char smem[];
    const int tid = threadIdx.x;
    const int wid = tid >> 5, lane = tid & 31;
    const int z = blockIdx.y;
    const int b = z >> 3, h = z & 7;
    const int q0 = blockIdx.x * 128;
    const size_t bSeq = (size_t)b * SEQ;
    const int hOff = h * HDIM;

    const uint32_t smBase = smem_u32(smem);
    const uint32_t KBASE = 53248u, VBASE = 79872u, BBASE = 106496u;

    for (int i = tid; i < 1536; i += 256) {
        int row = i / 12, col = i % 12;
        uint32_t so = ((uint32_t)row * FA_LDS + (uint32_t)col * 8u) * 2u;
        size_t go = (size_t)(q0 + row) * DMODEL + hOff + col * 8;
        cp16(smBase + so,           Qhi + go);
        cp16(smBase + 26624u + so,  Qlo + go);
    }
    CP_COMMIT();

    auto load_kv = [&](int c, int buf) {
        int l0 = c * 64;
        uint32_t kB = smBase + KBASE + (uint32_t)buf * 13312u;
        uint32_t vB = smBase + VBASE + (uint32_t)buf * 13312u;
        for (int i = tid; i < 768; i += 256) {
            int row = i / 12, col = i % 12;
            uint32_t so = ((uint32_t)row * FA_LDS + (uint32_t)col * 8u) * 2u;
            size_t go = (bSeq + l0 + row) * DMODEL + hOff + col * 8;
            cp16(kB + so, K16 + go);
            cp16(vB + so, V16 + go);
        }
        if (tid < 16)
            cp16(smBase + BBASE + (uint32_t)buf * 256u + (uint32_t)tid * 16u,
                 biasBL + bSeq + l0 + tid * 4);
    };
    load_kv(0, 0);
    CP_COMMIT();

    const uint32_t aRow = (uint32_t)(wid * 16 + (lane & 15)) * FA_LDS + (uint32_t)(lane >> 4) * 8u;
    const uint32_t bRow = (uint32_t)((lane & 7) + ((lane >> 4) * 8)) * FA_LDS
                        + (uint32_t)((lane >> 3) & 1) * 8u;
    const uint32_t vLaneRow = (uint32_t)((lane & 7) + ((lane >> 3) & 1) * 8);
    const uint32_t vLaneCol = (uint32_t)(lane >> 4) * 8u;

    float oacc[12][4];
    #pragma unroll
    for (int j = 0; j < 12; j++)
        #pragma unroll
        for (int k = 0; k < 4; k++) oacc[j][k] = 0.f;
    float m0 = -1e30f, m1 = -1e30f, l0s = 0.f, l1s = 0.f;

    for (int c = 0; c < 16; c++) {
        CP_WAIT0();
        __syncthreads();
        if (c + 1 < 16) { load_kv(c + 1, (c + 1) & 1); CP_COMMIT(); }

        const uint32_t kB = smBase + KBASE + (uint32_t)(c & 1) * 13312u;
        const uint32_t vB = smBase + VBASE + (uint32_t)(c & 1) * 13312u;
        const float* sbias = reinterpret_cast<const float*>(smem + BBASE + (c & 1) * 256);

        // ---- S = Q @ K^T (fp16 2-term: Qhi*K + Qlo*K) ----
        float s[8][4];
        #pragma unroll
        for (int j = 0; j < 8; j++)
            #pragma unroll
            for (int k = 0; k < 4; k++) s[j][k] = 0.f;

        #pragma unroll
        for (int ks = 0; ks < 6; ks++) {
            const uint32_t kcol = (uint32_t)ks * 16u;
            uint32_t qhiF[4], qloF[4], kk[4];
            uint32_t qoff = (aRow + kcol) * 2u;
            ldm_x4(qhiF, smBase + qoff);
            ldm_x4(qloF, smBase + 26624u + qoff);
            #pragma unroll
            for (int g = 0; g < 4; g++) {
                uint32_t off = (bRow + (uint32_t)g * 16u * FA_LDS + kcol) * 2u;
                ldm_x4(kk, kB + off);
                mma16816h(s[2 * g],     qhiF, &kk[0]);
                mma16816h(s[2 * g + 1], qhiF, &kk[2]);
                mma16816h(s[2 * g],     qloF, &kk[0]);
                mma16816h(s[2 * g + 1], qloF, &kk[2]);
            }
        }

        // ---- scale + bias, online softmax ----
        float mx0 = -1e30f, mx1 = -1e30f;
        #pragma unroll
        for (int nj = 0; nj < 8; nj++) {
            int cidx = nj * 8 + (lane & 3) * 2;
            float bj0 = sbias[cidx], bj1 = sbias[cidx + 1];
            s[nj][0] = s[nj][0] * scale + bj0;
            s[nj][1] = s[nj][1] * scale + bj1;
            s[nj][2] = s[nj][2] * scale + bj0;
            s[nj][3] = s[nj][3] * scale + bj1;
            mx0 = fmaxf(mx0, fmaxf(s[nj][0], s[nj][1]));
            mx1 = fmaxf(mx1, fmaxf(s[nj][2], s[nj][3]));
        }
        #pragma unroll
        for (int o = 1; o <= 2; o <<= 1) {
            mx0 = fmaxf(mx0, __shfl_xor_sync(0xffffffffu, mx0, o));
            mx1 = fmaxf(mx1, __shfl_xor_sync(0xffffffffu, mx1, o));
        }
        float mn0 = fmaxf(m0, mx0), mn1 = fmaxf(m1, mx1);
        float cor0 = __expf(m0 - mn0), cor1 = __expf(m1 - mn1);
        l0s *= cor0; l1s *= cor1;
        #pragma unroll
        for (int j = 0; j < 12; j++) {
            oacc[j][0] *= cor0; oacc[j][1] *= cor0;
            oacc[j][2] *= cor1; oacc[j][3] *= cor1;
        }
        m0 = mn0; m1 = mn1;

        float rs0 = 0.f, rs1 = 0.f;
        uint32_t pF[4][4];
        #pragma unroll
        for (int t = 0; t < 4; t++) {
            float p00 = __expf(s[2 * t][0] - mn0);
            float p01 = __expf(s[2 * t][1] - mn0);
            float p10 = __expf(s[2 * t][2] - mn1);
            float p11 = __expf(s[2 * t][3] - mn1);
            float p20 = __expf(s[2 * t + 1][0] - mn0);
            float p21 = __expf(s[2 * t + 1][1] - mn0);
            float p30 = __expf(s[2 * t + 1][2] - mn1);
            float p31 = __expf(s[2 * t + 1][3] - mn1);
            rs0 += p00 + p01 + p20 + p21;
            rs1 += p10 + p11 + p30 + p31;
            pF[t][0] = packh2(p00, p01);
            pF[t][1] = packh2(p10, p11);
            pF[t][2] = packh2(p20, p21);
            pF[t][3] = packh2(p30, p31);
        }
        #pragma unroll
        for (int o = 1; o <= 2; o <<= 1) {
            rs0 += __shfl_xor_sync(0xffffffffu, rs0, o);
            rs1 += __shfl_xor_sync(0xffffffffu, rs1, o);
        }
        l0s += rs0; l1s += rs1;

        // ---- O += P @ V (fp16 single term) ----
        #pragma unroll
        for (int t = 0; t < 4; t++) {
            uint32_t vv[4];
            #pragma unroll
            for (int g = 0; g < 6; g++) {
                uint32_t off = (((uint32_t)t * 16u + vLaneRow) * FA_LDS
                                + (uint32_t)g * 16u + vLaneCol) * 2u;
                ldm_x4_t(vv, vB + off);
                mma16816h(oacc[2 * g],     pF[t], &vv[0]);
                mma16816h(oacc[2 * g + 1], pF[t], &vv[2]);
            }
        }
    }

    float inv0 = 1.0f / l0s, inv1 = 1.0f / l1s;
    const int q = q0 + wid * 16 + (lane >> 2);
    #pragma unroll
    for (int j = 0; j < 12; j++) {
        int n = j * 8 + (lane & 3) * 2;
        size_t o0 = ((size_t)(b * NQ + q)) * DMODEL + hOff + n;
        size_t o1 = o0 + (size_t)8 * DMODEL;
        bf162 h2, l2;
        split2(oacc[j][0] * inv0, oacc[j][1] * inv0, h2, l2);
        *reinterpret_cast<bf162*>(Ohi + o0) = h2;
        *reinterpret_cast<bf162*>(Olo + o0) = l2;
        split2(oacc[j][2] * inv1, oacc[j][3] * inv1, h2, l2);
        *reinterpret_cast<bf162*>(Ohi + o1) = h2;
        *reinterpret_cast<bf162*>(Olo + o1) = l2;
    }
}

// ============================ LayerNorm / misc ============================
__device__ __forceinline__ void ln_stats(const float* __restrict__ xr, int ncols,
                                         float& mu, float& rs, float* s1, float* s2) {
    float sum = 0.f, sumsq = 0.f;
    for (int i = threadIdx.x; i < ncols; i += blockDim.x) {
        float v = xr[i];
        sum += v; sumsq += v * v;
    }
    #pragma unroll
    for (int o = 16; o; o >>= 1) {
        sum   += __shfl_xor_sync(0xffffffffu, sum, o);
        sumsq += __shfl_xor_sync(0xffffffffu, sumsq, o);
    }
    int wid = threadIdx.x >> 5, lid = threadIdx.x & 31;
    if (lid == 0) { s1[wid] = sum; s2[wid] = sumsq; }
    __syncthreads();
    if (threadIdx.x < 32) {
        int nw = blockDim.x >> 5;
        float a = (lid < nw) ? s1[lid] : 0.f;
        float c = (lid < nw) ? s2[lid] : 0.f;
        #pragma unroll
        for (int o = 16; o; o >>= 1) {
            a += __shfl_xor_sync(0xffffffffu, a, o);
            c += __shfl_xor_sync(0xffffffffu, c, o);
        }
        if (lid == 0) { s1[0] = a; s2[0] = c; }
    }
    __syncthreads();
    float inv_n = 1.0f / (float)ncols;
    mu = s1[0] * inv_n;
    float var = s2[0] * inv_n - mu * mu;
    rs = rsqrtf(var + 1e-5f);
}

__global__ void ln_kernel(const float* __restrict__ x, const float* __restrict__ w,
                          const float* __restrict__ b, float* __restrict__ out, int ncols) {
    __shared__ float s1[32], s2[32];
    const size_t row = blockIdx.x;
    const float* xr = x + row * (size_t)ncols;
    float mu, rs;
    ln_stats(xr, ncols, mu, rs, s1, s2);
    float* orow = out + row * (size_t)ncols;
    for (int i = threadIdx.x; i < ncols; i += blockDim.x)
        orow[i] = (xr[i] - mu) * rs * w[i] + b[i];
}

__global__ void ln_split_h_kernel(const float* __restrict__ x, const float* __restrict__ w,
                                  const float* __restrict__ b,
                                  __half* __restrict__ hi, __half* __restrict__ lo, int ncols) {
    __shared__ float s1[32], s2[32];
    const size_t row = blockIdx.x;
    const float* xr = x + row * (size_t)ncols;
    float mu, rs;
    ln_stats(xr, ncols, mu, rs, s1, s2);
    __half* hrow = hi + row * (size_t)ncols;
    __half* lrow = lo + row * (size_t)ncols;
    for (int i = threadIdx.x; i < ncols; i += blockDim.x) {
        float y = (xr[i] - mu) * rs * w[i] + b[i];
        __half hh = __float2half_rn(y);
        hrow[i] = hh;
        lrow[i] = __float2half_rn(y - __half2float(hh));
    }
}

__global__ void cvt_h_kernel(const float* __restrict__ x, __half* __restrict__ o, int n) {
    int i = blockIdx.x * blockDim.x + threadIdx.x;
    if (i < n) o[i] = __float2half_rn(x[i]);
}

__global__ void split_h_kernel(const float* __restrict__ x,
                               __half* __restrict__ hi, __half* __restrict__ lo, int n) {
    int i = blockIdx.x * blockDim.x + threadIdx.x;
    if (i < n) {
        float v = x[i];
        __half h = __float2half_rn(v);
        hi[i] = h;
        lo[i] = __float2half_rn(v - __half2float(h));
    }
}

__global__ void split_kernel(const float* __restrict__ x,
                             bf16* __restrict__ hi, bf16* __restrict__ lo, int n) {
    int i = blockIdx.x * blockDim.x + threadIdx.x;
    if (i < n) {
        float v = x[i];
        bf16 h = __float2bfloat16(v);
        hi[i] = h;
        lo[i] = __float2bfloat16(v - __bfloat162float(h));
    }
}

__global__ void bias_kernel(const float* __restrict__ size_in, const float* __restrict__ mask,
                            float* __restrict__ bias, int n) {
    int i = blockIdx.x * blockDim.x + threadIdx.x;
    if (i < n) {
        float s = size_in[i];
        s = (s < 0.5f) ? 1.0f : s;
        bias[i] = logf(s) + mask[i];
    }
}

// ============================ SIMT GEMM (Q-proj only) ============================
#define TBM 64
#define TBN 64
#define TBK 16
#define SPAD 4

__global__ void __launch_bounds__(256)
gemm_nt_kernel(const float* __restrict__ A, int lda,
               const float* __restrict__ B, int ldb,
               float* __restrict__ C, int ldc,
               int M, int N, int K, float alpha, const float* __restrict__ bias_n) {
    __shared__ __align__(16) float As[TBK][TBM + SPAD];
    __shared__ __align__(16) float Bs[TBK][TBN + SPAD];
    const int m0 = blockIdx.y * TBM;
    const int n0 = blockIdx.x * TBN;
    const int t  = threadIdx.x;
    const int tx = t & 15, ty = t >> 4;
    float acc[4][4] = {};
    for (int k0 = 0; k0 < K; k0 += TBK) {
        {
            int col = t & 15, rowb = t >> 4;
            #pragma unroll
            for (int i = 0; i < 4; i++) {
                int rr = rowb + i * 16;
                As[col][rr] = A[(size_t)(m0 + rr) * lda + k0 + col];
            }
        }
        {
            int col = t & 15, rowb = t >> 4;
            #pragma unroll
            for (int i = 0; i < 4; i++) {
                int nn = rowb + i * 16;
                Bs[col][nn] = B[(size_t)(n0 + nn) * ldb + k0 + col];
            }
        }
        __syncthreads();
        #pragma unroll
        for (int kk = 0; kk < TBK; kk++) {
            float4 av = *reinterpret_cast<const float4*>(&As[kk][ty * 4]);
            float4 bv = *reinterpret_cast<const float4*>(&Bs[kk][tx * 4]);
            float a[4] = {av.x, av.y, av.z, av.w};
            float b[4] = {bv.x, bv.y, bv.z, bv.w};
            #pragma unroll
            for (int i = 0; i < 4; i++)
                #pragma unroll
                for (int j = 0; j < 4; j++)
                    acc[i][j] += a[i] * b[j];
        }
        __syncthreads();
    }
    #pragma unroll
    for (int i = 0; i < 4; i++) {
        int gm = m0 + ty * 4 + i;
        #pragma unroll
        for (int j = 0; j < 4; j++) {
            int gn = n0 + tx * 4 + j;
            float v = alpha * acc[i][j];
            if (bias_n) v += bias_n[gn];
            C[(size_t)gm * ldc + gn] = v;
        }
    }
}

// ============================ launch ============================
extern "C" void kernel_launch(void* const* d_in, const int* in_sizes, int n_in,
                              void* d_out, int out_size) {
    const float* x     = (const float*)d_in[0];
    const float* sizei = (const float*)d_in[1];
    const float* amask = (const float*)d_in[2];
    const float* query = (const float*)d_in[3];
    const float* ln_q_w = (const float*)d_in[4];
    const float* ln_q_b = (const float*)d_in[5];
    const float* ln_k_w = (const float*)d_in[6];
    const float* ln_k_b = (const float*)d_in[7];
    const float* Wq = (const float*)d_in[8];
    const float* Wk = (const float*)d_in[9];
    const float* Wv = (const float*)d_in[10];
    const float* bq = (const float*)d_in[11];
    const float* bk = (const float*)d_in[12];
    const float* bv = (const float*)d_in[13];
    const float* Wo = (const float*)d_in[14];
    const float* bo = (const float*)d_in[15];
    float* out = (float*)d_out;

    __half *x16hi, *x16lo, *wk16, *wv16, *kh16, *vh16, *qh16hi, *qh16lo;
    bf16 *wohi, *wolo, *aohi, *aolo;
    float *qln, *qh, *bias;
    cudaGetSymbolAddress((void**)&x16hi, g_x16hi);
    cudaGetSymbolAddress((void**)&x16lo, g_x16lo);
    cudaGetSymbolAddress((void**)&wk16, g_wk16);
    cudaGetSymbolAddress((void**)&wv16, g_wv16);
    cudaGetSymbolAddress((void**)&kh16, g_kh16);
    cudaGetSymbolAddress((void**)&vh16, g_vh16);
    cudaGetSymbolAddress((void**)&qh16hi, g_qh16hi);
    cudaGetSymbolAddress((void**)&qh16lo, g_qh16lo);
    cudaGetSymbolAddress((void**)&wohi, g_wohi);
    cudaGetSymbolAddress((void**)&wolo, g_wolo);
    cudaGetSymbolAddress((void**)&aohi, g_aohi);
    cudaGetSymbolAddress((void**)&aolo, g_aolo);
    cudaGetSymbolAddress((void**)&qln, g_qln);
    cudaGetSymbolAddress((void**)&qh, g_qh);
    cudaGetSymbolAddress((void**)&bias, g_bias);

    cudaFuncSetAttribute(kv_gemm_h,  cudaFuncAttributeMaxDynamicSharedMemorySize, G2_SMEM);
    cudaFuncSetAttribute(oproj_gemm, cudaFuncAttributeMaxDynamicSharedMemorySize, G3_SMEM);
    cudaFuncSetAttribute(fa_kernel,  cudaFuncAttributeMaxDynamicSharedMemorySize, FA_SMEM);

    const float scale = 0.10206207261596575f;  // 1/sqrt(96)

    // launch order: index 3 (ncu-profiled) = kv_gemm_h(K)
    ln_split_h_kernel<<<MROWS, 256>>>(x, ln_k_w, ln_k_b, x16hi, x16lo, CTXD);          // 0
    cvt_h_kernel<<<(DMODEL * CTXD + 255) / 256, 256>>>(Wk, wk16, DMODEL * CTXD);       // 1
    cvt_h_kernel<<<(DMODEL * CTXD + 255) / 256, 256>>>(Wv, wv16, DMODEL * CTXD);       // 2
    {
        dim3 grid(DMODEL / 128, MROWS / 128);
        kv_gemm_h<<<grid, 256, G2_SMEM>>>(x16hi, x16lo, wk16, bk, kh16);               // 3 (profiled)
        kv_gemm_h<<<grid, 256, G2_SMEM>>>(x16hi, x16lo, wv16, bv, vh16);               // 4
    }
    ln_kernel<<<NQ, 256>>>(query, ln_q_w, ln_q_b, qln, DMODEL);                        // 5
    split_kernel<<<(DMODEL * DMODEL + 255) / 256, 256>>>(Wo, wohi, wolo, DMODEL * DMODEL); // 6
    bias_kernel<<<(MROWS + 255) / 256, 256>>>(sizei, amask, bias, MROWS);              // 7
    gemm_nt_kernel<<<dim3(DMODEL / TBN, NQ / TBM), 256>>>(                             // 8
        qln, DMODEL, Wq, DMODEL, qh, DMODEL, NQ, DMODEL, DMODEL, 1.0f, bq);
    split_h_kernel<<<(NQ * DMODEL + 255) / 256, 256>>>(qh, qh16hi, qh16lo, NQ * DMODEL); // 9

    fa_kernel<<<dim3(NQ / 128, NZ), 256, FA_SMEM>>>(                                   // 10
        qh16hi, qh16lo, kh16, vh16, bias, scale, aohi, aolo);

    oproj_gemm<<<dim3(DMODEL / 128, BATCH * NQ / 128), 256, G3_SMEM>>>(                // 11
        aohi, aolo, wohi, wolo, bo, out);
}

// round 11
// speedup vs baseline: 1.6044x; 1.1513x over previous
#include <cuda_runtime.h>
#include <cuda_bf16.h>
#include <cuda_fp16.h>
#include <cstdint>

#define BATCH     32
#define SEQ       1024
#define CTXD      1024
#define DMODEL    768
#define NHEAD     8
#define HDIM      96
#define NQ        256
#define MROWS     (BATCH * SEQ)   // 32768
#define NZ        (BATCH * NHEAD) // 256

typedef __nv_bfloat16 bf16;
typedef __nv_bfloat162 bf162;

// ============================ device scratch ============================
__device__ __half g_x16[MROWS * CTXD];            // LN(x) single fp16
__device__ __half g_wk16[DMODEL * CTXD];          // Wk fp16
__device__ __half g_wv16[DMODEL * CTXD];          // Wv fp16
__device__ __half g_kh16[MROWS * DMODEL];         // K proj, single fp16
__device__ __half g_vh16[MROWS * DMODEL];         // V proj, single fp16
__device__ __half g_qh16hi[NQ * DMODEL];          // Q proj fp16 hi
__device__ __half g_qh16lo[NQ * DMODEL];          // Q proj fp16 lo
__device__ bf16 g_wohi[DMODEL * DMODEL];
__device__ bf16 g_wolo[DMODEL * DMODEL];
__device__ bf16 g_aohi[BATCH * NQ * DMODEL];
__device__ bf16 g_aolo[BATCH * NQ * DMODEL];
__device__ float g_qln[NQ * DMODEL];
__device__ float g_qh[NQ * DMODEL];
__device__ float g_bias[MROWS];

// ============================ asm helpers ============================
__device__ __forceinline__ uint32_t smem_u32(const void* p) {
    uint32_t a;
    asm("{ .reg .u64 t; cvta.to.shared.u64 t, %1; cvt.u32.u64 %0, t; }" : "=r"(a) : "l"(p));
    return a;
}
__device__ __forceinline__ void ldm_x4(uint32_t* r, uint32_t addr) {
    asm volatile("ldmatrix.sync.aligned.m8n8.x4.shared.b16 {%0,%1,%2,%3}, [%4];"
                 : "=r"(r[0]), "=r"(r[1]), "=r"(r[2]), "=r"(r[3]) : "r"(addr));
}
__device__ __forceinline__ void ldm_x4_t(uint32_t* r, uint32_t addr) {
    asm volatile("ldmatrix.sync.aligned.m8n8.x4.trans.shared.b16 {%0,%1,%2,%3}, [%4];"
                 : "=r"(r[0]), "=r"(r[1]), "=r"(r[2]), "=r"(r[3]) : "r"(addr));
}
__device__ __forceinline__ void mma16816(float* c, const uint32_t* a, const uint32_t* b) {
    asm volatile("mma.sync.aligned.m16n8k16.row.col.f32.bf16.bf16.f32 "
                 "{%0,%1,%2,%3}, {%4,%5,%6,%7}, {%8,%9}, {%0,%1,%2,%3};"
                 : "+f"(c[0]), "+f"(c[1]), "+f"(c[2]), "+f"(c[3])
                 : "r"(a[0]), "r"(a[1]), "r"(a[2]), "r"(a[3]), "r"(b[0]), "r"(b[1]));
}
__device__ __forceinline__ void mma16816h(float* c, const uint32_t* a, const uint32_t* b) {
    asm volatile("mma.sync.aligned.m16n8k16.row.col.f32.f16.f16.f32 "
                 "{%0,%1,%2,%3}, {%4,%5,%6,%7}, {%8,%9}, {%0,%1,%2,%3};"
                 : "+f"(c[0]), "+f"(c[1]), "+f"(c[2]), "+f"(c[3])
                 : "r"(a[0]), "r"(a[1]), "r"(a[2]), "r"(a[3]), "r"(b[0]), "r"(b[1]));
}
__device__ __forceinline__ void cp16(uint32_t dst, const void* src) {
    asm volatile("cp.async.cg.shared.global [%0], [%1], 16;" :: "r"(dst), "l"(src));
}
#define CP_COMMIT() asm volatile("cp.async.commit_group;")
#define CP_WAIT0()  asm volatile("cp.async.wait_group 0;")

__device__ __forceinline__ void split2(float v0, float v1, bf162& h2, bf162& l2) {
    bf16 h0 = __float2bfloat16(v0);
    bf16 h1 = __float2bfloat16(v1);
    h2 = bf162(h0, h1);
    l2 = bf162(__float2bfloat16(v0 - __bfloat162float(h0)),
               __float2bfloat16(v1 - __bfloat162float(h1)));
}
__device__ __forceinline__ uint32_t packh2(float v0, float v1) {
    __half2 h = __floats2half2_rn(v0, v1);
    return *reinterpret_cast<uint32_t*>(&h);
}

// ============================ plain fp16 NT GEMM (KV projections) ============================
// C16[M,N] = A16[m,k] * B16[n,k]^T + bias_n.  k-chunk 64, double-buffered, 2 CTAs/SM.
// smem: buffer b at b*36864: A tile (128x64, stride 72) then B tile. Total 73728.
#define G1_SMEM 73728
#define LDS_K 72       // fp16 row stride (144 B, odd 16B-granule count -> conflict-free)
#define TILE72 18432u  // 128 * 72 * 2

__global__ void __launch_bounds__(256, 2)
kv_gemm_h(const __half* __restrict__ A16, const __half* __restrict__ B16,
          const float* __restrict__ bias_n, __half* __restrict__ C16) {
    extern __shared__ char smem[];
    const int tid  = threadIdx.x;
    const int wid  = tid >> 5;
    const int lane = tid & 31;
    const int m0 = blockIdx.y * 128;
    const int n0 = blockIdx.x * 128;
    const int wm = (wid & 3) * 32;
    const int wn = (wid >> 2) * 64;

    const uint32_t smBase = smem_u32(smem);
    const uint32_t aRow = (uint32_t)(wm + (lane & 15)) * LDS_K + (uint32_t)(lane >> 4) * 8u;
    const uint32_t bRow = (uint32_t)(wn + (lane & 7) + ((lane >> 4) * 8)) * LDS_K
                        + (uint32_t)((lane >> 3) & 1) * 8u;

    float acc[2][8][4];
    #pragma unroll
    for (int i = 0; i < 2; i++)
        #pragma unroll
        for (int j = 0; j < 8; j++)
            #pragma unroll
            for (int k = 0; k < 4; k++) acc[i][j][k] = 0.f;

    const int r2 = tid >> 1;    // row 0..127
    const int c2 = tid & 1;     // 16B column base

    auto load_chunk = [&](int k0, int buf) {
        uint32_t aB = smBase + (uint32_t)buf * (2u * TILE72);
        uint32_t bB = aB + TILE72;
        #pragma unroll
        for (int i = 0; i < 4; i++) {
            int col = c2 + i * 2;   // 0..7
            uint32_t so = ((uint32_t)r2 * LDS_K + (uint32_t)col * 8u) * 2u;
            size_t ga = (size_t)(m0 + r2) * CTXD + k0 + col * 8;
            size_t gb = (size_t)(n0 + r2) * CTXD + k0 + col * 8;
            cp16(aB + so, A16 + ga);
            cp16(bB + so, B16 + gb);
        }
    };

    load_chunk(0, 0);
    CP_COMMIT();

    for (int c = 0; c < CTXD / 64; c++) {
        CP_WAIT0();
        __syncthreads();
        if (c + 1 < CTXD / 64) { load_chunk((c + 1) << 6, (c + 1) & 1); CP_COMMIT(); }

        uint32_t aB = smBase + (uint32_t)(c & 1) * (2u * TILE72);
        uint32_t bB = aB + TILE72;
        #pragma unroll
        for (int ks = 0; ks < 4; ks++) {
            const uint32_t kcol = (uint32_t)ks * 16u;
            uint32_t a[2][4], b[4][4];
            #pragma unroll
            for (int g = 0; g < 4; g++) {
                uint32_t off = (bRow + (uint32_t)g * 16u * LDS_K + kcol) * 2u;
                ldm_x4(b[g], bB + off);
            }
            #pragma unroll
            for (int mi = 0; mi < 2; mi++) {
                uint32_t off = (aRow + (uint32_t)mi * 16u * LDS_K + kcol) * 2u;
                ldm_x4(a[mi], aB + off);
            }
            #pragma unroll
            for (int mi = 0; mi < 2; mi++)
                #pragma unroll
                for (int nj = 0; nj < 8; nj++)
                    mma16816h(acc[mi][nj], a[mi], &b[nj >> 1][(nj & 1) * 2]);
        }
        __syncthreads();
    }

    #pragma unroll
    for (int mi = 0; mi < 2; mi++) {
        int gm = m0 + wm + mi * 16 + (lane >> 2);
        #pragma unroll
        for (int nj = 0; nj < 8; nj++) {
            int gn = n0 + wn + nj * 8 + (lane & 3) * 2;
            float b0 = bias_n[gn], b1 = bias_n[gn + 1];
            uint32_t p0 = packh2(acc[mi][nj][0] + b0, acc[mi][nj][1] + b1);
            uint32_t p1 = packh2(acc[mi][nj][2] + b0, acc[mi][nj][3] + b1);
            *reinterpret_cast<uint32_t*>(C16 + (size_t)gm * DMODEL + gn)       = p0;
            *reinterpret_cast<uint32_t*>(C16 + (size_t)(gm + 8) * DMODEL + gn) = p1;
        }
    }
}

// ============================ split-bf16 3-term NT GEMM (O-proj) ============================
#define G3_SMEM 81920
#define LDS_BF 40

__global__ void __launch_bounds__(256, 2)
oproj_gemm(const bf16* __restrict__ Ahi, const bf16* __restrict__ Alo,
           const bf16* __restrict__ Bhi, const bf16* __restrict__ Blo,
           const float* __restrict__ bias_n, float* __restrict__ C) {
    extern __shared__ char smem[];
    const int tid  = threadIdx.x;
    const int wid  = tid >> 5;
    const int lane = tid & 31;
    const int m0 = blockIdx.y * 128;
    const int n0 = blockIdx.x * 128;
    const int wm = (wid & 3) * 32;
    const int wn = (wid >> 2) * 64;

    const uint32_t smBase = smem_u32(smem);
    const uint32_t aRow = (uint32_t)(wm + (lane & 15)) * LDS_BF + (uint32_t)(lane >> 4) * 8u;
    const uint32_t bRow = (uint32_t)(wn + (lane & 7) + ((lane >> 4) * 8)) * LDS_BF
                        + (uint32_t)((lane >> 3) & 1) * 8u;

    float acc[2][8][4];
    #pragma unroll
    for (int i = 0; i < 2; i++)
        #pragma unroll
        for (int j = 0; j < 8; j++)
            #pragma unroll
            for (int k = 0; k < 4; k++) acc[i][j][k] = 0.f;

    const int r  = tid >> 2;
    const int cc = tid & 3;

    auto load_chunk = [&](int k0, int buf) {
        uint32_t aB = smBase + (uint32_t)buf * 20480u;
        uint32_t bB = smBase + 40960u + (uint32_t)buf * 20480u;
        #pragma unroll
        for (int h = 0; h < 2; h++) {
            int rr = r + h * 64;
            uint32_t so = ((uint32_t)rr * LDS_BF + (uint32_t)cc * 8u) * 2u;
            size_t ga = (size_t)(m0 + rr) * DMODEL + k0 + cc * 8;
            size_t gb = (size_t)(n0 + rr) * DMODEL + k0 + cc * 8;
            cp16(aB + so,           Ahi + ga);
            cp16(aB + 10240u + so,  Alo + ga);
            cp16(bB + so,           Bhi + gb);
            cp16(bB + 10240u + so,  Blo + gb);
        }
    };

    load_chunk(0, 0);
    CP_COMMIT();

    for (int c = 0; c < DMODEL / 32; c++) {
        CP_WAIT0();
        __syncthreads();
        if (c + 1 < DMODEL / 32) { load_chunk((c + 1) << 5, (c + 1) & 1); CP_COMMIT(); }

        uint32_t aB = smBase + (uint32_t)(c & 1) * 20480u;
        uint32_t bB = smBase + 40960u + (uint32_t)(c & 1) * 20480u;
        #pragma unroll
        for (int ks = 0; ks < 2; ks++) {
            const uint32_t kcol = (uint32_t)ks * 16u;
            uint32_t ahi[2][4], alo[2][4], bhi[4][4], blo[4][4];
            #pragma unroll
            for (int g = 0; g < 4; g++) {
                uint32_t off = (bRow + (uint32_t)g * 16u * LDS_BF + kcol) * 2u;
                ldm_x4(bhi[g], bB + off);
                ldm_x4(blo[g], bB + 10240u + off);
            }
            #pragma unroll
            for (int mi = 0; mi < 2; mi++) {
                uint32_t off = (aRow + (uint32_t)mi * 16u * LDS_BF + kcol) * 2u;
                ldm_x4(ahi[mi], aB + off);
                ldm_x4(alo[mi], aB + 10240u + off);
            }
            #pragma unroll
            for (int mi = 0; mi < 2; mi++)
                #pragma unroll
                for (int nj = 0; nj < 8; nj++)
                    mma16816(acc[mi][nj], ahi[mi], &bhi[nj >> 1][(nj & 1) * 2]);
            #pragma unroll
            for (int mi = 0; mi < 2; mi++)
                #pragma unroll
                for (int nj = 0; nj < 8; nj++)
                    mma16816(acc[mi][nj], alo[mi], &bhi[nj >> 1][(nj & 1) * 2]);
            #pragma unroll
            for (int mi = 0; mi < 2; mi++)
                #pragma unroll
                for (int nj = 0; nj < 8; nj++)
                    mma16816(acc[mi][nj], ahi[mi], &blo[nj >> 1][(nj & 1) * 2]);
        }
        __syncthreads();
    }

    #pragma unroll
    for (int mi = 0; mi < 2; mi++) {
        int gm = m0 + wm + mi * 16 + (lane >> 2);
        #pragma unroll
        for (int nj = 0; nj < 8; nj++) {
            int gn = n0 + wn + nj * 8 + (lane & 3) * 2;
            float b0 = bias_n[gn], b1 = bias_n[gn + 1];
            *reinterpret_cast<float2*>(C + (size_t)gm * DMODEL + gn) =
                make_float2(acc[mi][nj][0] + b0, acc[mi][nj][1] + b1);
            *reinterpret_cast<float2*>(C + (size_t)(gm + 8) * DMODEL + gn) =
                make_float2(acc[mi][nj][2] + b0, acc[mi][nj][3] + b1);
        }
    }
}

// ============================ fused flash attention (fp16) ============================
#define FA_SMEM 107008
#define FA_LDS 104

__global__ void __launch_bounds__(256, 1)
fa_kernel(const __half* __restrict__ Qhi, const __half* __restrict__ Qlo,
          const __half* __restrict__ K16, const __half* __restrict__ V16,
          const float* __restrict__ biasBL, float scale,
          bf16* __restrict__ Ohi, bf16* __restrict__ Olo) {
    extern __shared__ char smem[];
    const int tid = threadIdx.x;
    const int wid = tid >> 5, lane = tid & 31;
    const int z = blockIdx.y;
    const int b = z >> 3, h = z & 7;
    const int q0 = blockIdx.x * 128;
    const size_t bSeq = (size_t)b * SEQ;
    const int hOff = h * HDIM;

    const uint32_t smBase = smem_u32(smem);
    const uint32_t KBASE = 53248u, VBASE = 79872u, BBASE = 106496u;

    for (int i = tid; i < 1536; i += 256) {
        int row = i / 12, col = i % 12;
        uint32_t so = ((uint32_t)row * FA_LDS + (uint32_t)col * 8u) * 2u;
        size_t go = (size_t)(q0 + row) * DMODEL + hOff + col * 8;
        cp16(smBase + so,           Qhi + go);
        cp16(smBase + 26624u + so,  Qlo + go);
    }
    CP_COMMIT();

    auto load_kv = [&](int c, int buf) {
        int l0 = c * 64;
        uint32_t kB = smBase + KBASE + (uint32_t)buf * 13312u;
        uint32_t vB = smBase + VBASE + (uint32_t)buf * 13312u;
        for (int i = tid; i < 768; i += 256) {
            int row = i / 12, col = i % 12;
            uint32_t so = ((uint32_t)row * FA_LDS + (uint32_t)col * 8u) * 2u;
            size_t go = (bSeq + l0 + row) * DMODEL + hOff + col * 8;
            cp16(kB + so, K16 + go);
            cp16(vB + so, V16 + go);
        }
        if (tid < 16)
            cp16(smBase + BBASE + (uint32_t)buf * 256u + (uint32_t)tid * 16u,
                 biasBL + bSeq + l0 + tid * 4);
    };
    load_kv(0, 0);
    CP_COMMIT();

    const uint32_t aRow = (uint32_t)(wid * 16 + (lane & 15)) * FA_LDS + (uint32_t)(lane >> 4) * 8u;
    const uint32_t bRow = (uint32_t)((lane & 7) + ((lane >> 4) * 8)) * FA_LDS
                        + (uint32_t)((lane >> 3) & 1) * 8u;
    const uint32_t vLaneRow = (uint32_t)((lane & 7) + ((lane >> 3) & 1) * 8);
    const uint32_t vLaneCol = (uint32_t)(lane >> 4) * 8u;

    float oacc[12][4];
    #pragma unroll
    for (int j = 0; j < 12; j++)
        #pragma unroll
        for (int k = 0; k < 4; k++) oacc[j][k] = 0.f;
    float m0 = -1e30f, m1 = -1e30f, l0s = 0.f, l1s = 0.f;

    for (int c = 0; c < 16; c++) {
        CP_WAIT0();
        __syncthreads();
        if (c + 1 < 16) { load_kv(c + 1, (c + 1) & 1); CP_COMMIT(); }

        const uint32_t kB = smBase + KBASE + (uint32_t)(c & 1) * 13312u;
        const uint32_t vB = smBase + VBASE + (uint32_t)(c & 1) * 13312u;
        const float* sbias = reinterpret_cast<const float*>(smem + BBASE + (c & 1) * 256);

        float s[8][4];
        #pragma unroll
        for (int j = 0; j < 8; j++)
            #pragma unroll
            for (int k = 0; k < 4; k++) s[j][k] = 0.f;

        #pragma unroll
        for (int ks = 0; ks < 6; ks++) {
            const uint32_t kcol = (uint32_t)ks * 16u;
            uint32_t qhiF[4], qloF[4], kk[4];
            uint32_t qoff = (aRow + kcol) * 2u;
            ldm_x4(qhiF, smBase + qoff);
            ldm_x4(qloF, smBase + 26624u + qoff);
            #pragma unroll
            for (int g = 0; g < 4; g++) {
                uint32_t off = (bRow + (uint32_t)g * 16u * FA_LDS + kcol) * 2u;
                ldm_x4(kk, kB + off);
                mma16816h(s[2 * g],     qhiF, &kk[0]);
                mma16816h(s[2 * g + 1], qhiF, &kk[2]);
                mma16816h(s[2 * g],     qloF, &kk[0]);
                mma16816h(s[2 * g + 1], qloF, &kk[2]);
            }
        }

        float mx0 = -1e30f, mx1 = -1e30f;
        #pragma unroll
        for (int nj = 0; nj < 8; nj++) {
            int cidx = nj * 8 + (lane & 3) * 2;
            float bj0 = sbias[cidx], bj1 = sbias[cidx + 1];
            s[nj][0] = s[nj][0] * scale + bj0;
            s[nj][1] = s[nj][1] * scale + bj1;
            s[nj][2] = s[nj][2] * scale + bj0;
            s[nj][3] = s[nj][3] * scale + bj1;
            mx0 = fmaxf(mx0, fmaxf(s[nj][0], s[nj][1]));
            mx1 = fmaxf(mx1, fmaxf(s[nj][2], s[nj][3]));
        }
        #pragma unroll
        for (int o = 1; o <= 2; o <<= 1) {
            mx0 = fmaxf(mx0, __shfl_xor_sync(0xffffffffu, mx0, o));
            mx1 = fmaxf(mx1, __shfl_xor_sync(0xffffffffu, mx1, o));
        }
        float mn0 = fmaxf(m0, mx0), mn1 = fmaxf(m1, mx1);
        float cor0 = __expf(m0 - mn0), cor1 = __expf(m1 - mn1);
        l0s *= cor0; l1s *= cor1;
        #pragma unroll
        for (int j = 0; j < 12; j++) {
            oacc[j][0] *= cor0; oacc[j][1] *= cor0;
            oacc[j][2] *= cor1; oacc[j][3] *= cor1;
        }
        m0 = mn0; m1 = mn1;

        float rs0 = 0.f, rs1 = 0.f;
        uint32_t pF[4][4];
        #pragma unroll
        for (int t = 0; t < 4; t++) {
            float p00 = __expf(s[2 * t][0] - mn0);
            float p01 = __expf(s[2 * t][1] - mn0);
            float p10 = __expf(s[2 * t][2] - mn1);
            float p11 = __expf(s[2 * t][3] - mn1);
            float p20 = __expf(s[2 * t + 1][0] - mn0);
            float p21 = __expf(s[2 * t + 1][1] - mn0);
            float p30 = __expf(s[2 * t + 1][2] - mn1);
            float p31 = __expf(s[2 * t + 1][3] - mn1);
            rs0 += p00 + p01 + p20 + p21;
            rs1 += p10 + p11 + p30 + p31;
            pF[t][0] = packh2(p00, p01);
            pF[t][1] = packh2(p10, p11);
            pF[t][2] = packh2(p20, p21);
            pF[t][3] = packh2(p30, p31);
        }
        #pragma unroll
        for (int o = 1; o <= 2; o <<= 1) {
            rs0 += __shfl_xor_sync(0xffffffffu, rs0, o);
            rs1 += __shfl_xor_sync(0xffffffffu, rs1, o);
        }
        l0s += rs0; l1s += rs1;

        #pragma unroll
        for (int t = 0; t < 4; t++) {
            uint32_t vv[4];
            #pragma unroll
            for (int g = 0; g < 6; g++) {
                uint32_t off = (((uint32_t)t * 16u + vLaneRow) * FA_LDS
                                + (uint32_t)g * 16u + vLaneCol) * 2u;
                ldm_x4_t(vv, vB + off);
                mma16816h(oacc[2 * g],     pF[t], &vv[0]);
                mma16816h(oacc[2 * g + 1], pF[t], &vv[2]);
            }
        }
    }

    float inv0 = 1.0f / l0s, inv1 = 1.0f / l1s;
    const int q = q0 + wid * 16 + (lane >> 2);
    #pragma unroll
    for (int j = 0; j < 12; j++) {
        int n = j * 8 + (lane & 3) * 2;
        size_t o0 = ((size_t)(b * NQ + q)) * DMODEL + hOff + n;
        size_t o1 = o0 + (size_t)8 * DMODEL;
        bf162 h2, l2;
        split2(oacc[j][0] * inv0, oacc[j][1] * inv0, h2, l2);
        *reinterpret_cast<bf162*>(Ohi + o0) = h2;
        *reinterpret_cast<bf162*>(Olo + o0) = l2;
        split2(oacc[j][2] * inv1, oacc[j][3] * inv1, h2, l2);
        *reinterpret_cast<bf162*>(Ohi + o1) = h2;
        *reinterpret_cast<bf162*>(Olo + o1) = l2;
    }
}

// ============================ LayerNorm / misc ============================
__device__ __forceinline__ void ln_stats(const float* __restrict__ xr, int ncols,
                                         float& mu, float& rs, float* s1, float* s2) {
    float sum = 0.f, sumsq = 0.f;
    for (int i = threadIdx.x; i < ncols; i += blockDim.x) {
        float v = xr[i];
        sum += v; sumsq += v * v;
    }
    #pragma unroll
    for (int o = 16; o; o >>= 1) {
        sum   += __shfl_xor_sync(0xffffffffu, sum, o);
        sumsq += __shfl_xor_sync(0xffffffffu, sumsq, o);
    }
    int wid = threadIdx.x >> 5, lid = threadIdx.x & 31;
    if (lid == 0) { s1[wid] = sum; s2[wid] = sumsq; }
    __syncthreads();
    if (threadIdx.x < 32) {
        int nw = blockDim.x >> 5;
        float a = (lid < nw) ? s1[lid] : 0.f;
        float c = (lid < nw) ? s2[lid] : 0.f;
        #pragma unroll
        for (int o = 16; o; o >>= 1) {
            a += __shfl_xor_sync(0xffffffffu, a, o);
            c += __shfl_xor_sync(0xffffffffu, c, o);
        }
        if (lid == 0) { s1[0] = a; s2[0] = c; }
    }
    __syncthreads();
    float inv_n = 1.0f / (float)ncols;
    mu = s1[0] * inv_n;
    float var = s2[0] * inv_n - mu * mu;
    rs = rsqrtf(var + 1e-5f);
}

__global__ void ln_kernel(const float* __restrict__ x, const float* __restrict__ w,
                          const float* __restrict__ b, float* __restrict__ out, int ncols) {
    __shared__ float s1[32], s2[32];
    const size_t row = blockIdx.x;
    const float* xr = x + row * (size_t)ncols;
    float mu, rs;
    ln_stats(xr, ncols, mu, rs, s1, s2);
    float* orow = out + row * (size_t)ncols;
    for (int i = threadIdx.x; i < ncols; i += blockDim.x)
        orow[i] = (xr[i] - mu) * rs * w[i] + b[i];
}

// LN -> single fp16
__global__ void ln_h_kernel(const float* __restrict__ x, const float* __restrict__ w,
                            const float* __restrict__ b,
                            __half* __restrict__ o16, int ncols) {
    __shared__ float s1[32], s2[32];
    const size_t row = blockIdx.x;
    const float* xr = x + row * (size_t)ncols;
    float mu, rs;
    ln_stats(xr, ncols, mu, rs, s1, s2);
    __half* orow = o16 + row * (size_t)ncols;
    for (int i = threadIdx.x; i < ncols; i += blockDim.x) {
        float y = (xr[i] - mu) * rs * w[i] + b[i];
        orow[i] = __float2half_rn(y);
    }
}

__global__ void cvt_h_kernel(const float* __restrict__ x, __half* __restrict__ o, int n) {
    int i = blockIdx.x * blockDim.x + threadIdx.x;
    if (i < n) o[i] = __float2half_rn(x[i]);
}

__global__ void split_h_kernel(const float* __restrict__ x,
                               __half* __restrict__ hi, __half* __restrict__ lo, int n) {
    int i = blockIdx.x * blockDim.x + threadIdx.x;
    if (i < n) {
        float v = x[i];
        __half h = __float2half_rn(v);
        hi[i] = h;
        lo[i] = __float2half_rn(v - __half2float(h));
    }
}

__global__ void split_kernel(const float* __restrict__ x,
                             bf16* __restrict__ hi, bf16* __restrict__ lo, int n) {
    int i = blockIdx.x * blockDim.x + threadIdx.x;
    if (i < n) {
        float v = x[i];
        bf16 h = __float2bfloat16(v);
        hi[i] = h;
        lo[i] = __float2bfloat16(v - __bfloat162float(h));
    }
}

__global__ void bias_kernel(const float* __restrict__ size_in, const float* __restrict__ mask,
                            float* __restrict__ bias, int n) {
    int i = blockIdx.x * blockDim.x + threadIdx.x;
    if (i < n) {
        float s = size_in[i];
        s = (s < 0.5f) ? 1.0f : s;
        bias[i] = logf(s) + mask[i];
    }
}

// ============================ SIMT GEMM (Q-proj only) ============================
#define TBM 64
#define TBN 64
#define TBK 16
#define SPAD 4

__global__ void __launch_bounds__(256)
gemm_nt_kernel(const float* __restrict__ A, int lda,
               const float* __restrict__ B, int ldb,
               float* __restrict__ C, int ldc,
               int M, int N, int K, float alpha, const float* __restrict__ bias_n) {
    __shared__ __align__(16) float As[TBK][TBM + SPAD];
    __shared__ __align__(16) float Bs[TBK][TBN + SPAD];
    const int m0 = blockIdx.y * TBM;
    const int n0 = blockIdx.x * TBN;
    const int t  = threadIdx.x;
    const int tx = t & 15, ty = t >> 4;
    float acc[4][4] = {};
    for (int k0 = 0; k0 < K; k0 += TBK) {
        {
            int col = t & 15, rowb = t >> 4;
            #pragma unroll
            for (int i = 0; i < 4; i++) {
                int rr = rowb + i * 16;
                As[col][rr] = A[(size_t)(m0 + rr) * lda + k0 + col];
            }
        }
        {
            int col = t & 15, rowb = t >> 4;
            #pragma unroll
            for (int i = 0; i < 4; i++) {
                int nn = rowb + i * 16;
                Bs[col][nn] = B[(size_t)(n0 + nn) * ldb + k0 + col];
            }
        }
        __syncthreads();
        #pragma unroll
        for (int kk = 0; kk < TBK; kk++) {
            float4 av = *reinterpret_cast<const float4*>(&As[kk][ty * 4]);
            float4 bv = *reinterpret_cast<const float4*>(&Bs[kk][tx * 4]);
            float a[4] = {av.x, av.y, av.z, av.w};
            float b[4] = {bv.x, bv.y, bv.z, bv.w};
            #pragma unroll
            for (int i = 0; i < 4; i++)
                #pragma unroll
                for (int j = 0; j < 4; j++)
                    acc[i][j] += a[i] * b[j];
        }
        __syncthreads();
    }
    #pragma unroll
    for (int i = 0; i < 4; i++) {
        int gm = m0 + ty * 4 + i;
        #pragma unroll
        for (int j = 0; j < 4; j++) {
            int gn = n0 + tx * 4 + j;
            float v = alpha * acc[i][j];
            if (bias_n) v += bias_n[gn];
            C[(size_t)gm * ldc + gn] = v;
        }
    }
}

// ============================ launch ============================
extern "C" void kernel_launch(void* const* d_in, const int* in_sizes, int n_in,
                              void* d_out, int out_size) {
    const float* x     = (const float*)d_in[0];
    const float* sizei = (const float*)d_in[1];
    const float* amask = (const float*)d_in[2];
    const float* query = (const float*)d_in[3];
    const float* ln_q_w = (const float*)d_in[4];
    const float* ln_q_b = (const float*)d_in[5];
    const float* ln_k_w = (const float*)d_in[6];
    const float* ln_k_b = (const float*)d_in[7];
    const float* Wq = (const float*)d_in[8];
    const float* Wk = (const float*)d_in[9];
    const float* Wv = (const float*)d_in[10];
    const float* bq = (const float*)d_in[11];
    const float* bk = (const float*)d_in[12];
    const float* bv = (const float*)d_in[13];
    const float* Wo = (const float*)d_in[14];
    const float* bo = (const float*)d_in[15];
    float* out = (float*)d_out;

    __half *x16, *wk16, *wv16, *kh16, *vh16, *qh16hi, *qh16lo;
    bf16 *wohi, *wolo, *aohi, *aolo;
    float *qln, *qh, *bias;
    cudaGetSymbolAddress((void**)&x16, g_x16);
    cudaGetSymbolAddress((void**)&wk16, g_wk16);
    cudaGetSymbolAddress((void**)&wv16, g_wv16);
    cudaGetSymbolAddress((void**)&kh16, g_kh16);
    cudaGetSymbolAddress((void**)&vh16, g_vh16);
    cudaGetSymbolAddress((void**)&qh16hi, g_qh16hi);
    cudaGetSymbolAddress((void**)&qh16lo, g_qh16lo);
    cudaGetSymbolAddress((void**)&wohi, g_wohi);
    cudaGetSymbolAddress((void**)&wolo, g_wolo);
    cudaGetSymbolAddress((void**)&aohi, g_aohi);
    cudaGetSymbolAddress((void**)&aolo, g_aolo);
    cudaGetSymbolAddress((void**)&qln, g_qln);
    cudaGetSymbolAddress((void**)&qh, g_qh);
    cudaGetSymbolAddress((void**)&bias, g_bias);

    cudaFuncSetAttribute(kv_gemm_h,  cudaFuncAttributeMaxDynamicSharedMemorySize, G1_SMEM);
    cudaFuncSetAttribute(oproj_gemm, cudaFuncAttributeMaxDynamicSharedMemorySize, G3_SMEM);
    cudaFuncSetAttribute(fa_kernel,  cudaFuncAttributeMaxDynamicSharedMemorySize, FA_SMEM);

    const float scale = 0.10206207261596575f;  // 1/sqrt(96)

    // launch order: index 3 (ncu-profiled) = kv_gemm_h(K)
    ln_h_kernel<<<MROWS, 256>>>(x, ln_k_w, ln_k_b, x16, CTXD);                         // 0
    cvt_h_kernel<<<(DMODEL * CTXD + 255) / 256, 256>>>(Wk, wk16, DMODEL * CTXD);       // 1
    cvt_h_kernel<<<(DMODEL * CTXD + 255) / 256, 256>>>(Wv, wv16, DMODEL * CTXD);       // 2
    {
        dim3 grid(DMODEL / 128, MROWS / 128);
        kv_gemm_h<<<grid, 256, G1_SMEM>>>(x16, wk16, bk, kh16);                        // 3 (profiled)
        kv_gemm_h<<<grid, 256, G1_SMEM>>>(x16, wv16, bv, vh16);                        // 4
    }
    ln_kernel<<<NQ, 256>>>(query, ln_q_w, ln_q_b, qln, DMODEL);                        // 5
    split_kernel<<<(DMODEL * DMODEL + 255) / 256, 256>>>(Wo, wohi, wolo, DMODEL * DMODEL); // 6
    bias_kernel<<<(MROWS + 255) / 256, 256>>>(sizei, amask, bias, MROWS);              // 7
    gemm_nt_kernel<<<dim3(DMODEL / TBN, NQ / TBM), 256>>>(                             // 8
        qln, DMODEL, Wq, DMODEL, qh, DMODEL, NQ, DMODEL, DMODEL, 1.0f, bq);
    split_h_kernel<<<(NQ * DMODEL + 255) / 256, 256>>>(qh, qh16hi, qh16lo, NQ * DMODEL); // 9

    fa_kernel<<<dim3(NQ / 128, NZ), 256, FA_SMEM>>>(                                   // 10
        qh16hi, qh16lo, kh16, vh16, bias, scale, aohi, aolo);

    oproj_gemm<<<dim3(DMODEL / 128, BATCH * NQ / 128), 256, G3_SMEM>>>(                // 11
        aohi, aolo, wohi, wolo, bo, out);
}

// round 13
// speedup vs baseline: 1.7907x; 1.1162x over previous
#include <cuda_runtime.h>
#include <cuda_bf16.h>
#include <cuda_fp16.h>
#include <cstdint>

#define BATCH     32
#define SEQ       1024
#define CTXD      1024
#define DMODEL    768
#define NHEAD     8
#define HDIM      96
#define NQ        256
#define MROWS     (BATCH * SEQ)   // 32768
#define NZ        (BATCH * NHEAD) // 256

typedef __nv_bfloat16 bf16;
typedef __nv_bfloat162 bf162;

// ============================ device scratch ============================
__device__ __half g_x16[MROWS * CTXD];            // LN(x) single fp16
__device__ __half g_wk16[DMODEL * CTXD];          // Wk fp16
__device__ __half g_wv16[DMODEL * CTXD];          // Wv fp16
__device__ __half g_kh16[MROWS * DMODEL];         // K proj fp16
__device__ __half g_vh16[MROWS * DMODEL];         // V proj fp16
__device__ __half g_qh16[NQ * DMODEL];            // Q proj fp16
__device__ bf16 g_wohi[DMODEL * DMODEL];
__device__ bf16 g_wolo[DMODEL * DMODEL];
__device__ bf16 g_aohi[BATCH * NQ * DMODEL];
__device__ bf16 g_aolo[BATCH * NQ * DMODEL];
__device__ float g_qln[NQ * DMODEL];
__device__ float g_qh[NQ * DMODEL];
__device__ float g_bias[MROWS];

// ============================ asm helpers ============================
__device__ __forceinline__ uint32_t smem_u32(const void* p) {
    uint32_t a;
    asm("{ .reg .u64 t; cvta.to.shared.u64 t, %1; cvt.u32.u64 %0, t; }" : "=r"(a) : "l"(p));
    return a;
}
__device__ __forceinline__ void ldm_x4(uint32_t* r, uint32_t addr) {
    asm volatile("ldmatrix.sync.aligned.m8n8.x4.shared.b16 {%0,%1,%2,%3}, [%4];"
                 : "=r"(r[0]), "=r"(r[1]), "=r"(r[2]), "=r"(r[3]) : "r"(addr));
}
__device__ __forceinline__ void ldm_x4_t(uint32_t* r, uint32_t addr) {
    asm volatile("ldmatrix.sync.aligned.m8n8.x4.trans.shared.b16 {%0,%1,%2,%3}, [%4];"
                 : "=r"(r[0]), "=r"(r[1]), "=r"(r[2]), "=r"(r[3]) : "r"(addr));
}
__device__ __forceinline__ void mma16816(float* c, const uint32_t* a, const uint32_t* b) {
    asm volatile("mma.sync.aligned.m16n8k16.row.col.f32.bf16.bf16.f32 "
                 "{%0,%1,%2,%3}, {%4,%5,%6,%7}, {%8,%9}, {%0,%1,%2,%3};"
                 : "+f"(c[0]), "+f"(c[1]), "+f"(c[2]), "+f"(c[3])
                 : "r"(a[0]), "r"(a[1]), "r"(a[2]), "r"(a[3]), "r"(b[0]), "r"(b[1]));
}
__device__ __forceinline__ void mma16816h(float* c, const uint32_t* a, const uint32_t* b) {
    asm volatile("mma.sync.aligned.m16n8k16.row.col.f32.f16.f16.f32 "
                 "{%0,%1,%2,%3}, {%4,%5,%6,%7}, {%8,%9}, {%0,%1,%2,%3};"
                 : "+f"(c[0]), "+f"(c[1]), "+f"(c[2]), "+f"(c[3])
                 : "r"(a[0]), "r"(a[1]), "r"(a[2]), "r"(a[3]), "r"(b[0]), "r"(b[1]));
}
__device__ __forceinline__ void cp16(uint32_t dst, const void* src) {
    asm volatile("cp.async.cg.shared.global [%0], [%1], 16;" :: "r"(dst), "l"(src));
}
#define CP_COMMIT() asm volatile("cp.async.commit_group;")
#define CP_WAIT0()  asm volatile("cp.async.wait_group 0;")

__device__ __forceinline__ void split2(float v0, float v1, bf162& h2, bf162& l2) {
    bf16 h0 = __float2bfloat16(v0);
    bf16 h1 = __float2bfloat16(v1);
    h2 = bf162(h0, h1);
    l2 = bf162(__float2bfloat16(v0 - __bfloat162float(h0)),
               __float2bfloat16(v1 - __bfloat162float(h1)));
}
__device__ __forceinline__ uint32_t packh2(float v0, float v1) {
    __half2 h = __floats2half2_rn(v0, v1);
    return *reinterpret_cast<uint32_t*>(&h);
}

#define LDS_BF 40

// ============================ fused K+V fp16 GEMM ============================
// One CTA (512 thr) computes K[128x128] AND V[128x128] from a SHARED A tile.
// Warps 0-7: K (Bk), warps 8-15: V (Bv). k-chunk 32, double-buffered.
// smem per buffer (30720B): A @0, Bk @10240, Bv @20480. Total 61440.
#define KVF_SMEM 61440

__global__ void __launch_bounds__(512, 1)
kvfused_gemm(const __half* __restrict__ A16,
             const __half* __restrict__ Bk16, const __half* __restrict__ Bv16,
             const float* __restrict__ bias_k, const float* __restrict__ bias_v,
             __half* __restrict__ Ck, __half* __restrict__ Cv) {
    extern __shared__ char smem[];
    const int tid  = threadIdx.x;
    const int wid  = tid >> 5;
    const int lane = tid & 31;
    const int grp  = wid >> 3;          // 0 = K, 1 = V
    const int wg   = wid & 7;
    const int m0 = blockIdx.y * 128;
    const int n0 = blockIdx.x * 128;
    const int wm = (wg & 3) * 32;
    const int wn = (wg >> 2) * 64;

    const uint32_t smBase = smem_u32(smem);
    const uint32_t aRow = (uint32_t)(wm + (lane & 15)) * LDS_BF + (uint32_t)(lane >> 4) * 8u;
    const uint32_t bRow = (uint32_t)(wn + (lane & 7) + ((lane >> 4) * 8)) * LDS_BF
                        + (uint32_t)((lane >> 3) & 1) * 8u;
    const uint32_t bTileOff = 10240u + (uint32_t)grp * 10240u;

    float acc[2][8][4];
    #pragma unroll
    for (int i = 0; i < 2; i++)
        #pragma unroll
        for (int j = 0; j < 8; j++)
            #pragma unroll
            for (int k = 0; k < 4; k++) acc[i][j][k] = 0.f;

    const int r  = tid >> 2;    // 0..127
    const int cc = tid & 3;     // 16B col

    auto load_chunk = [&](int k0, int buf) {
        uint32_t base = smBase + (uint32_t)buf * 30720u;
        uint32_t so = ((uint32_t)r * LDS_BF + (uint32_t)cc * 8u) * 2u;
        size_t ga = (size_t)(m0 + r) * CTXD + k0 + cc * 8;
        size_t gb = (size_t)(n0 + r) * CTXD + k0 + cc * 8;
        cp16(base + so,           A16  + ga);
        cp16(base + 10240u + so,  Bk16 + gb);
        cp16(base + 20480u + so,  Bv16 + gb);
    };

    load_chunk(0, 0);
    CP_COMMIT();

    for (int c = 0; c < CTXD / 32; c++) {
        CP_WAIT0();
        __syncthreads();
        if (c + 1 < CTXD / 32) { load_chunk((c + 1) << 5, (c + 1) & 1); CP_COMMIT(); }

        uint32_t base = smBase + (uint32_t)(c & 1) * 30720u;
        uint32_t bB = base + bTileOff;
        #pragma unroll
        for (int ks = 0; ks < 2; ks++) {
            const uint32_t kcol = (uint32_t)ks * 16u;
            uint32_t a[2][4], b[4][4];
            #pragma unroll
            for (int g = 0; g < 4; g++) {
                uint32_t off = (bRow + (uint32_t)g * 16u * LDS_BF + kcol) * 2u;
                ldm_x4(b[g], bB + off);
            }
            #pragma unroll
            for (int mi = 0; mi < 2; mi++) {
                uint32_t off = (aRow + (uint32_t)mi * 16u * LDS_BF + kcol) * 2u;
                ldm_x4(a[mi], base + off);
            }
            #pragma unroll
            for (int mi = 0; mi < 2; mi++)
                #pragma unroll
                for (int nj = 0; nj < 8; nj++)
                    mma16816h(acc[mi][nj], a[mi], &b[nj >> 1][(nj & 1) * 2]);
        }
        __syncthreads();
    }

    const float* bias_n = grp ? bias_v : bias_k;
    __half* C16 = grp ? Cv : Ck;
    #pragma unroll
    for (int mi = 0; mi < 2; mi++) {
        int gm = m0 + wm + mi * 16 + (lane >> 2);
        #pragma unroll
        for (int nj = 0; nj < 8; nj++) {
            int gn = n0 + wn + nj * 8 + (lane & 3) * 2;
            float b0 = bias_n[gn], b1 = bias_n[gn + 1];
            uint32_t p0 = packh2(acc[mi][nj][0] + b0, acc[mi][nj][1] + b1);
            uint32_t p1 = packh2(acc[mi][nj][2] + b0, acc[mi][nj][3] + b1);
            *reinterpret_cast<uint32_t*>(C16 + (size_t)gm * DMODEL + gn)       = p0;
            *reinterpret_cast<uint32_t*>(C16 + (size_t)(gm + 8) * DMODEL + gn) = p1;
        }
    }
}

// ============================ split-bf16 3-term NT GEMM (O-proj) ============================
#define G3_SMEM 81920

__global__ void __launch_bounds__(256, 2)
oproj_gemm(const bf16* __restrict__ Ahi, const bf16* __restrict__ Alo,
           const bf16* __restrict__ Bhi, const bf16* __restrict__ Blo,
           const float* __restrict__ bias_n, float* __restrict__ C) {
    extern __shared__ char smem[];
    const int tid  = threadIdx.x;
    const int wid  = tid >> 5;
    const int lane = tid & 31;
    const int m0 = blockIdx.y * 128;
    const int n0 = blockIdx.x * 128;
    const int wm = (wid & 3) * 32;
    const int wn = (wid >> 2) * 64;

    const uint32_t smBase = smem_u32(smem);
    const uint32_t aRow = (uint32_t)(wm + (lane & 15)) * LDS_BF + (uint32_t)(lane >> 4) * 8u;
    const uint32_t bRow = (uint32_t)(wn + (lane & 7) + ((lane >> 4) * 8)) * LDS_BF
                        + (uint32_t)((lane >> 3) & 1) * 8u;

    float acc[2][8][4];
    #pragma unroll
    for (int i = 0; i < 2; i++)
        #pragma unroll
        for (int j = 0; j < 8; j++)
            #pragma unroll
            for (int k = 0; k < 4; k++) acc[i][j][k] = 0.f;

    const int r  = tid >> 2;
    const int cc = tid & 3;

    auto load_chunk = [&](int k0, int buf) {
        uint32_t aB = smBase + (uint32_t)buf * 20480u;
        uint32_t bB = smBase + 40960u + (uint32_t)buf * 20480u;
        #pragma unroll
        for (int h = 0; h < 2; h++) {
            int rr = r + h * 64;
            uint32_t so = ((uint32_t)rr * LDS_BF + (uint32_t)cc * 8u) * 2u;
            size_t ga = (size_t)(m0 + rr) * DMODEL + k0 + cc * 8;
            size_t gb = (size_t)(n0 + rr) * DMODEL + k0 + cc * 8;
            cp16(aB + so,           Ahi + ga);
            cp16(aB + 10240u + so,  Alo + ga);
            cp16(bB + so,           Bhi + gb);
            cp16(bB + 10240u + so,  Blo + gb);
        }
    };

    load_chunk(0, 0);
    CP_COMMIT();

    for (int c = 0; c < DMODEL / 32; c++) {
        CP_WAIT0();
        __syncthreads();
        if (c + 1 < DMODEL / 32) { load_chunk((c + 1) << 5, (c + 1) & 1); CP_COMMIT(); }

        uint32_t aB = smBase + (uint32_t)(c & 1) * 20480u;
        uint32_t bB = smBase + 40960u + (uint32_t)(c & 1) * 20480u;
        #pragma unroll
        for (int ks = 0; ks < 2; ks++) {
            const uint32_t kcol = (uint32_t)ks * 16u;
            uint32_t ahi[2][4], alo[2][4], bhi[4][4], blo[4][4];
            #pragma unroll
            for (int g = 0; g < 4; g++) {
                uint32_t off = (bRow + (uint32_t)g * 16u * LDS_BF + kcol) * 2u;
                ldm_x4(bhi[g], bB + off);
                ldm_x4(blo[g], bB + 10240u + off);
            }
            #pragma unroll
            for (int mi = 0; mi < 2; mi++) {
                uint32_t off = (aRow + (uint32_t)mi * 16u * LDS_BF + kcol) * 2u;
                ldm_x4(ahi[mi], aB + off);
                ldm_x4(alo[mi], aB + 10240u + off);
            }
            #pragma unroll
            for (int mi = 0; mi < 2; mi++)
                #pragma unroll
                for (int nj = 0; nj < 8; nj++)
                    mma16816(acc[mi][nj], ahi[mi], &bhi[nj >> 1][(nj & 1) * 2]);
            #pragma unroll
            for (int mi = 0; mi < 2; mi++)
                #pragma unroll
                for (int nj = 0; nj < 8; nj++)
                    mma16816(acc[mi][nj], alo[mi], &bhi[nj >> 1][(nj & 1) * 2]);
            #pragma unroll
            for (int mi = 0; mi < 2; mi++)
                #pragma unroll
                for (int nj = 0; nj < 8; nj++)
                    mma16816(acc[mi][nj], ahi[mi], &blo[nj >> 1][(nj & 1) * 2]);
        }
        __syncthreads();
    }

    #pragma unroll
    for (int mi = 0; mi < 2; mi++) {
        int gm = m0 + wm + mi * 16 + (lane >> 2);
        #pragma unroll
        for (int nj = 0; nj < 8; nj++) {
            int gn = n0 + wn + nj * 8 + (lane & 3) * 2;
            float b0 = bias_n[gn], b1 = bias_n[gn + 1];
            *reinterpret_cast<float2*>(C + (size_t)gm * DMODEL + gn) =
                make_float2(acc[mi][nj][0] + b0, acc[mi][nj][1] + b1);
            *reinterpret_cast<float2*>(C + (size_t)(gm + 8) * DMODEL + gn) =
                make_float2(acc[mi][nj][2] + b0, acc[mi][nj][3] + b1);
        }
    }
}

// ============================ fused flash attention (all fp16) ============================
// Q,K,V,P single fp16. smem: Q @0 (26624), K @26624 (2x13312), V @53248 (2x13312), bias @79872.
#define FA_SMEM 80384
#define FA_LDS 104

__global__ void __launch_bounds__(256, 1)
fa_kernel(const __half* __restrict__ Q16,
          const __half* __restrict__ K16, const __half* __restrict__ V16,
          const float* __restrict__ biasBL, float scale,
          bf16* __restrict__ Ohi, bf16* __restrict__ Olo) {
    extern __shared__ char smem[];
    const int tid = threadIdx.x;
    const int wid = tid >> 5, lane = tid & 31;
    const int z = blockIdx.y;
    const int b = z >> 3, h = z & 7;
    const int q0 = blockIdx.x * 128;
    const size_t bSeq = (size_t)b * SEQ;
    const int hOff = h * HDIM;

    const uint32_t smBase = smem_u32(smem);
    const uint32_t KBASE = 26624u, VBASE = 53248u, BBASE = 79872u;

    for (int i = tid; i < 1536; i += 256) {
        int row = i / 12, col = i % 12;
        uint32_t so = ((uint32_t)row * FA_LDS + (uint32_t)col * 8u) * 2u;
        size_t go = (size_t)(q0 + row) * DMODEL + hOff + col * 8;
        cp16(smBase + so, Q16 + go);
    }
    CP_COMMIT();

    auto load_kv = [&](int c, int buf) {
        int l0 = c * 64;
        uint32_t kB = smBase + KBASE + (uint32_t)buf * 13312u;
        uint32_t vB = smBase + VBASE + (uint32_t)buf * 13312u;
        for (int i = tid; i < 768; i += 256) {
            int row = i / 12, col = i % 12;
            uint32_t so = ((uint32_t)row * FA_LDS + (uint32_t)col * 8u) * 2u;
            size_t go = (bSeq + l0 + row) * DMODEL + hOff + col * 8;
            cp16(kB + so, K16 + go);
            cp16(vB + so, V16 + go);
        }
        if (tid < 16)
            cp16(smBase + BBASE + (uint32_t)buf * 256u + (uint32_t)tid * 16u,
                 biasBL + bSeq + l0 + tid * 4);
    };
    load_kv(0, 0);
    CP_COMMIT();

    const uint32_t aRow = (uint32_t)(wid * 16 + (lane & 15)) * FA_LDS + (uint32_t)(lane >> 4) * 8u;
    const uint32_t bRow = (uint32_t)((lane & 7) + ((lane >> 4) * 8)) * FA_LDS
                        + (uint32_t)((lane >> 3) & 1) * 8u;
    const uint32_t vLaneRow = (uint32_t)((lane & 7) + ((lane >> 3) & 1) * 8);
    const uint32_t vLaneCol = (uint32_t)(lane >> 4) * 8u;

    float oacc[12][4];
    #pragma unroll
    for (int j = 0; j < 12; j++)
        #pragma unroll
        for (int k = 0; k < 4; k++) oacc[j][k] = 0.f;
    float m0 = -1e30f, m1 = -1e30f, l0s = 0.f, l1s = 0.f;

    for (int c = 0; c < 16; c++) {
        CP_WAIT0();
        __syncthreads();
        if (c + 1 < 16) { load_kv(c + 1, (c + 1) & 1); CP_COMMIT(); }

        const uint32_t kB = smBase + KBASE + (uint32_t)(c & 1) * 13312u;
        const uint32_t vB = smBase + VBASE + (uint32_t)(c & 1) * 13312u;
        const float* sbias = reinterpret_cast<const float*>(smem + BBASE + (c & 1) * 256);

        float s[8][4];
        #pragma unroll
        for (int j = 0; j < 8; j++)
            #pragma unroll
            for (int k = 0; k < 4; k++) s[j][k] = 0.f;

        #pragma unroll
        for (int ks = 0; ks < 6; ks++) {
            const uint32_t kcol = (uint32_t)ks * 16u;
            uint32_t qF[4], kk[4];
            ldm_x4(qF, smBase + (aRow + kcol) * 2u);
            #pragma unroll
            for (int g = 0; g < 4; g++) {
                uint32_t off = (bRow + (uint32_t)g * 16u * FA_LDS + kcol) * 2u;
                ldm_x4(kk, kB + off);
                mma16816h(s[2 * g],     qF, &kk[0]);
                mma16816h(s[2 * g + 1], qF, &kk[2]);
            }
        }

        float mx0 = -1e30f, mx1 = -1e30f;
        #pragma unroll
        for (int nj = 0; nj < 8; nj++) {
            int cidx = nj * 8 + (lane & 3) * 2;
            float bj0 = sbias[cidx], bj1 = sbias[cidx + 1];
            s[nj][0] = s[nj][0] * scale + bj0;
            s[nj][1] = s[nj][1] * scale + bj1;
            s[nj][2] = s[nj][2] * scale + bj0;
            s[nj][3] = s[nj][3] * scale + bj1;
            mx0 = fmaxf(mx0, fmaxf(s[nj][0], s[nj][1]));
            mx1 = fmaxf(mx1, fmaxf(s[nj][2], s[nj][3]));
        }
        #pragma unroll
        for (int o = 1; o <= 2; o <<= 1) {
            mx0 = fmaxf(mx0, __shfl_xor_sync(0xffffffffu, mx0, o));
            mx1 = fmaxf(mx1, __shfl_xor_sync(0xffffffffu, mx1, o));
        }
        float mn0 = fmaxf(m0, mx0), mn1 = fmaxf(m1, mx1);
        float cor0 = __expf(m0 - mn0), cor1 = __expf(m1 - mn1);
        l0s *= cor0; l1s *= cor1;
        #pragma unroll
        for (int j = 0; j < 12; j++) {
            oacc[j][0] *= cor0; oacc[j][1] *= cor0;
            oacc[j][2] *= cor1; oacc[j][3] *= cor1;
        }
        m0 = mn0; m1 = mn1;

        float rs0 = 0.f, rs1 = 0.f;
        uint32_t pF[4][4];
        #pragma unroll
        for (int t = 0; t < 4; t++) {
            float p00 = __expf(s[2 * t][0] - mn0);
            float p01 = __expf(s[2 * t][1] - mn0);
            float p10 = __expf(s[2 * t][2] - mn1);
            float p11 = __expf(s[2 * t][3] - mn1);
            float p20 = __expf(s[2 * t + 1][0] - mn0);
            float p21 = __expf(s[2 * t + 1][1] - mn0);
            float p30 = __expf(s[2 * t + 1][2] - mn1);
            float p31 = __expf(s[2 * t + 1][3] - mn1);
            rs0 += p00 + p01 + p20 + p21;
            rs1 += p10 + p11 + p30 + p31;
            pF[t][0] = packh2(p00, p01);
            pF[t][1] = packh2(p10, p11);
            pF[t][2] = packh2(p20, p21);
            pF[t][3] = packh2(p30, p31);
        }
        #pragma unroll
        for (int o = 1; o <= 2; o <<= 1) {
            rs0 += __shfl_xor_sync(0xffffffffu, rs0, o);
            rs1 += __shfl_xor_sync(0xffffffffu, rs1, o);
        }
        l0s += rs0; l1s += rs1;

        #pragma unroll
        for (int t = 0; t < 4; t++) {
            uint32_t vv[4];
            #pragma unroll
            for (int g = 0; g < 6; g++) {
                uint32_t off = (((uint32_t)t * 16u + vLaneRow) * FA_LDS
                                + (uint32_t)g * 16u + vLaneCol) * 2u;
                ldm_x4_t(vv, vB + off);
                mma16816h(oacc[2 * g],     pF[t], &vv[0]);
                mma16816h(oacc[2 * g + 1], pF[t], &vv[2]);
            }
        }
    }

    float inv0 = 1.0f / l0s, inv1 = 1.0f / l1s;
    const int q = q0 + wid * 16 + (lane >> 2);
    #pragma unroll
    for (int j = 0; j < 12; j++) {
        int n = j * 8 + (lane & 3) * 2;
        size_t o0 = ((size_t)(b * NQ + q)) * DMODEL + hOff + n;
        size_t o1 = o0 + (size_t)8 * DMODEL;
        bf162 h2, l2;
        split2(oacc[j][0] * inv0, oacc[j][1] * inv0, h2, l2);
        *reinterpret_cast<bf162*>(Ohi + o0) = h2;
        *reinterpret_cast<bf162*>(Olo + o0) = l2;
        split2(oacc[j][2] * inv1, oacc[j][3] * inv1, h2, l2);
        *reinterpret_cast<bf162*>(Ohi + o1) = h2;
        *reinterpret_cast<bf162*>(Olo + o1) = l2;
    }
}

// ============================ LayerNorm / misc ============================
__device__ __forceinline__ void ln_stats(const float* __restrict__ xr, int ncols,
                                         float& mu, float& rs, float* s1, float* s2) {
    float sum = 0.f, sumsq = 0.f;
    for (int i = threadIdx.x; i < ncols; i += blockDim.x) {
        float v = xr[i];
        sum += v; sumsq += v * v;
    }
    #pragma unroll
    for (int o = 16; o; o >>= 1) {
        sum   += __shfl_xor_sync(0xffffffffu, sum, o);
        sumsq += __shfl_xor_sync(0xffffffffu, sumsq, o);
    }
    int wid = threadIdx.x >> 5, lid = threadIdx.x & 31;
    if (lid == 0) { s1[wid] = sum; s2[wid] = sumsq; }
    __syncthreads();
    if (threadIdx.x < 32) {
        int nw = blockDim.x >> 5;
        float a = (lid < nw) ? s1[lid] : 0.f;
        float c = (lid < nw) ? s2[lid] : 0.f;
        #pragma unroll
        for (int o = 16; o; o >>= 1) {
            a += __shfl_xor_sync(0xffffffffu, a, o);
            c += __shfl_xor_sync(0xffffffffu, c, o);
        }
        if (lid == 0) { s1[0] = a; s2[0] = c; }
    }
    __syncthreads();
    float inv_n = 1.0f / (float)ncols;
    mu = s1[0] * inv_n;
    float var = s2[0] * inv_n - mu * mu;
    rs = rsqrtf(var + 1e-5f);
}

__global__ void ln_kernel(const float* __restrict__ x, const float* __restrict__ w,
                          const float* __restrict__ b, float* __restrict__ out, int ncols) {
    __shared__ float s1[32], s2[32];
    const size_t row = blockIdx.x;
    const float* xr = x + row * (size_t)ncols;
    float mu, rs;
    ln_stats(xr, ncols, mu, rs, s1, s2);
    float* orow = out + row * (size_t)ncols;
    for (int i = threadIdx.x; i < ncols; i += blockDim.x)
        orow[i] = (xr[i] - mu) * rs * w[i] + b[i];
}

__global__ void ln_h_kernel(const float* __restrict__ x, const float* __restrict__ w,
                            const float* __restrict__ b,
                            __half* __restrict__ o16, int ncols) {
    __shared__ float s1[32], s2[32];
    const size_t row = blockIdx.x;
    const float* xr = x + row * (size_t)ncols;
    float mu, rs;
    ln_stats(xr, ncols, mu, rs, s1, s2);
    __half* orow = o16 + row * (size_t)ncols;
    for (int i = threadIdx.x; i < ncols; i += blockDim.x) {
        float y = (xr[i] - mu) * rs * w[i] + b[i];
        orow[i] = __float2half_rn(y);
    }
}

__global__ void cvt_h_kernel(const float* __restrict__ x, __half* __restrict__ o, int n) {
    int i = blockIdx.x * blockDim.x + threadIdx.x;
    if (i < n) o[i] = __float2half_rn(x[i]);
}

__global__ void split_kernel(const float* __restrict__ x,
                             bf16* __restrict__ hi, bf16* __restrict__ lo, int n) {
    int i = blockIdx.x * blockDim.x + threadIdx.x;
    if (i < n) {
        float v = x[i];
        bf16 h = __float2bfloat16(v);
        hi[i] = h;
        lo[i] = __float2bfloat16(v - __bfloat162float(h));
    }
}

__global__ void bias_kernel(const float* __restrict__ size_in, const float* __restrict__ mask,
                            float* __restrict__ bias, int n) {
    int i = blockIdx.x * blockDim.x + threadIdx.x;
    if (i < n) {
        float s = size_in[i];
        s = (s < 0.5f) ? 1.0f : s;
        bias[i] = logf(s) + mask[i];
    }
}

// ============================ SIMT GEMM (Q-proj only) ============================
#define TBM 64
#define TBN 64
#define TBK 16
#define SPAD 4

__global__ void __launch_bounds__(256)
gemm_nt_kernel(const float* __restrict__ A, int lda,
               const float* __restrict__ B, int ldb,
               float* __restrict__ C, int ldc,
               int M, int N, int K, float alpha, const float* __restrict__ bias_n) {
    __shared__ __align__(16) float As[TBK][TBM + SPAD];
    __shared__ __align__(16) float Bs[TBK][TBN + SPAD];
    const int m0 = blockIdx.y * TBM;
    const int n0 = blockIdx.x * TBN;
    const int t  = threadIdx.x;
    const int tx = t & 15, ty = t >> 4;
    float acc[4][4] = {};
    for (int k0 = 0; k0 < K; k0 += TBK) {
        {
            int col = t & 15, rowb = t >> 4;
            #pragma unroll
            for (int i = 0; i < 4; i++) {
                int rr = rowb + i * 16;
                As[col][rr] = A[(size_t)(m0 + rr) * lda + k0 + col];
            }
        }
        {
            int col = t & 15, rowb = t >> 4;
            #pragma unroll
            for (int i = 0; i < 4; i++) {
                int nn = rowb + i * 16;
                Bs[col][nn] = B[(size_t)(n0 + nn) * ldb + k0 + col];
            }
        }
        __syncthreads();
        #pragma unroll
        for (int kk = 0; kk < TBK; kk++) {
            float4 av = *reinterpret_cast<const float4*>(&As[kk][ty * 4]);
            float4 bv = *reinterpret_cast<const float4*>(&Bs[kk][tx * 4]);
            float a[4] = {av.x, av.y, av.z, av.w};
            float b[4] = {bv.x, bv.y, bv.z, bv.w};
            #pragma unroll
            for (int i = 0; i < 4; i++)
                #pragma unroll
                for (int j = 0; j < 4; j++)
                    acc[i][j] += a[i] * b[j];
        }
        __syncthreads();
    }
    #pragma unroll
    for (int i = 0; i < 4; i++) {
        int gm = m0 + ty * 4 + i;
        #pragma unroll
        for (int j = 0; j < 4; j++) {
            int gn = n0 + tx * 4 + j;
            float v = alpha * acc[i][j];
            if (bias_n) v += bias_n[gn];
            C[(size_t)gm * ldc + gn] = v;
        }
    }
}

// ============================ launch ============================
extern "C" void kernel_launch(void* const* d_in, const int* in_sizes, int n_in,
                              void* d_out, int out_size) {
    const float* x     = (const float*)d_in[0];
    const float* sizei = (const float*)d_in[1];
    const float* amask = (const float*)d_in[2];
    const float* query = (const float*)d_in[3];
    const float* ln_q_w = (const float*)d_in[4];
    const float* ln_q_b = (const float*)d_in[5];
    const float* ln_k_w = (const float*)d_in[6];
    const float* ln_k_b = (const float*)d_in[7];
    const float* Wq = (const float*)d_in[8];
    const float* Wk = (const float*)d_in[9];
    const float* Wv = (const float*)d_in[10];
    const float* bq = (const float*)d_in[11];
    const float* bk = (const float*)d_in[12];
    const float* bv = (const float*)d_in[13];
    const float* Wo = (const float*)d_in[14];
    const float* bo = (const float*)d_in[15];
    float* out = (float*)d_out;

    __half *x16, *wk16, *wv16, *kh16, *vh16, *qh16;
    bf16 *wohi, *wolo, *aohi, *aolo;
    float *qln, *qh, *bias;
    cudaGetSymbolAddress((void**)&x16, g_x16);
    cudaGetSymbolAddress((void**)&wk16, g_wk16);
    cudaGetSymbolAddress((void**)&wv16, g_wv16);
    cudaGetSymbolAddress((void**)&kh16, g_kh16);
    cudaGetSymbolAddress((void**)&vh16, g_vh16);
    cudaGetSymbolAddress((void**)&qh16, g_qh16);
    cudaGetSymbolAddress((void**)&wohi, g_wohi);
    cudaGetSymbolAddress((void**)&wolo, g_wolo);
    cudaGetSymbolAddress((void**)&aohi, g_aohi);
    cudaGetSymbolAddress((void**)&aolo, g_aolo);
    cudaGetSymbolAddress((void**)&qln, g_qln);
    cudaGetSymbolAddress((void**)&qh, g_qh);
    cudaGetSymbolAddress((void**)&bias, g_bias);

    cudaFuncSetAttribute(kvfused_gemm, cudaFuncAttributeMaxDynamicSharedMemorySize, KVF_SMEM);
    cudaFuncSetAttribute(oproj_gemm,   cudaFuncAttributeMaxDynamicSharedMemorySize, G3_SMEM);
    cudaFuncSetAttribute(fa_kernel,    cudaFuncAttributeMaxDynamicSharedMemorySize, FA_SMEM);

    const float scale = 0.10206207261596575f;  // 1/sqrt(96)

    // launch order: index 3 (ncu-profiled) = kvfused_gemm
    ln_h_kernel<<<MROWS, 256>>>(x, ln_k_w, ln_k_b, x16, CTXD);                         // 0
    cvt_h_kernel<<<(DMODEL * CTXD + 255) / 256, 256>>>(Wk, wk16, DMODEL * CTXD);       // 1
    cvt_h_kernel<<<(DMODEL * CTXD + 255) / 256, 256>>>(Wv, wv16, DMODEL * CTXD);       // 2
    kvfused_gemm<<<dim3(DMODEL / 128, MROWS / 128), 512, KVF_SMEM>>>(                  // 3 (profiled)
        x16, wk16, wv16, bk, bv, kh16, vh16);
    ln_kernel<<<NQ, 256>>>(query, ln_q_w, ln_q_b, qln, DMODEL);                        // 4
    split_kernel<<<(DMODEL * DMODEL + 255) / 256, 256>>>(Wo, wohi, wolo, DMODEL * DMODEL); // 5
    bias_kernel<<<(MROWS + 255) / 256, 256>>>(sizei, amask, bias, MROWS);              // 6
    gemm_nt_kernel<<<dim3(DMODEL / TBN, NQ / TBM), 256>>>(                             // 7
        qln, DMODEL, Wq, DMODEL, qh, DMODEL, NQ, DMODEL, DMODEL, 1.0f, bq);
    cvt_h_kernel<<<(NQ * DMODEL + 255) / 256, 256>>>(qh, qh16, NQ * DMODEL);           // 8

    fa_kernel<<<dim3(NQ / 128, NZ), 256, FA_SMEM>>>(                                   // 9
        qh16, kh16, vh16, bias, scale, aohi, aolo);

    oproj_gemm<<<dim3(DMODEL / 128, BATCH * NQ / 128), 256, G3_SMEM>>>(                // 10
        aohi, aolo, wohi, wolo, bo, out);
}

// round 14
// speedup vs baseline: 1.7937x; 1.0017x over previous
#include <cuda_runtime.h>
#include <cuda_bf16.h>
#include <cuda_fp16.h>
#include <cstdint>

#define BATCH     32
#define SEQ       1024
#define CTXD      1024
#define DMODEL    768
#define NHEAD     8
#define HDIM      96
#define NQ        256
#define MROWS     (BATCH * SEQ)   // 32768
#define NZ        (BATCH * NHEAD) // 256

typedef __nv_bfloat16 bf16;
typedef __nv_bfloat162 bf162;

// ============================ device scratch ============================
__device__ __half g_x16[MROWS * CTXD];            // LN(x) single fp16
__device__ __half g_wk16[DMODEL * CTXD];          // Wk fp16
__device__ __half g_wv16[DMODEL * CTXD];          // Wv fp16
__device__ __half g_kh16[MROWS * DMODEL];         // K proj fp16
__device__ __half g_vh16[MROWS * DMODEL];         // V proj fp16
__device__ __half g_qh16[NQ * DMODEL];            // Q proj fp16
__device__ bf16 g_wohi[DMODEL * DMODEL];
__device__ bf16 g_wolo[DMODEL * DMODEL];
__device__ bf16 g_aohi[BATCH * NQ * DMODEL];
__device__ bf16 g_aolo[BATCH * NQ * DMODEL];
__device__ float g_qln[NQ * DMODEL];
__device__ float g_qh[NQ * DMODEL];
__device__ float g_bias[MROWS];

// ============================ asm helpers ============================
__device__ __forceinline__ uint32_t smem_u32(const void* p) {
    uint32_t a;
    asm("{ .reg .u64 t; cvta.to.shared.u64 t, %1; cvt.u32.u64 %0, t; }" : "=r"(a) : "l"(p));
    return a;
}
__device__ __forceinline__ void ldm_x4(uint32_t* r, uint32_t addr) {
    asm volatile("ldmatrix.sync.aligned.m8n8.x4.shared.b16 {%0,%1,%2,%3}, [%4];"
                 : "=r"(r[0]), "=r"(r[1]), "=r"(r[2]), "=r"(r[3]) : "r"(addr));
}
__device__ __forceinline__ void ldm_x4_t(uint32_t* r, uint32_t addr) {
    asm volatile("ldmatrix.sync.aligned.m8n8.x4.trans.shared.b16 {%0,%1,%2,%3}, [%4];"
                 : "=r"(r[0]), "=r"(r[1]), "=r"(r[2]), "=r"(r[3]) : "r"(addr));
}
__device__ __forceinline__ void mma16816(float* c, const uint32_t* a, const uint32_t* b) {
    asm volatile("mma.sync.aligned.m16n8k16.row.col.f32.bf16.bf16.f32 "
                 "{%0,%1,%2,%3}, {%4,%5,%6,%7}, {%8,%9}, {%0,%1,%2,%3};"
                 : "+f"(c[0]), "+f"(c[1]), "+f"(c[2]), "+f"(c[3])
                 : "r"(a[0]), "r"(a[1]), "r"(a[2]), "r"(a[3]), "r"(b[0]), "r"(b[1]));
}
__device__ __forceinline__ void mma16816h(float* c, const uint32_t* a, const uint32_t* b) {
    asm volatile("mma.sync.aligned.m16n8k16.row.col.f32.f16.f16.f32 "
                 "{%0,%1,%2,%3}, {%4,%5,%6,%7}, {%8,%9}, {%0,%1,%2,%3};"
                 : "+f"(c[0]), "+f"(c[1]), "+f"(c[2]), "+f"(c[3])
                 : "r"(a[0]), "r"(a[1]), "r"(a[2]), "r"(a[3]), "r"(b[0]), "r"(b[1]));
}
__device__ __forceinline__ void cp16(uint32_t dst, const void* src) {
    asm volatile("cp.async.cg.shared.global [%0], [%1], 16;" :: "r"(dst), "l"(src));
}
#define CP_COMMIT() asm volatile("cp.async.commit_group;")
#define CP_WAIT0()  asm volatile("cp.async.wait_group 0;")

__device__ __forceinline__ void split2(float v0, float v1, bf162& h2, bf162& l2) {
    bf16 h0 = __float2bfloat16(v0);
    bf16 h1 = __float2bfloat16(v1);
    h2 = bf162(h0, h1);
    l2 = bf162(__float2bfloat16(v0 - __bfloat162float(h0)),
               __float2bfloat16(v1 - __bfloat162float(h1)));
}
__device__ __forceinline__ uint32_t packh2(float v0, float v1) {
    __half2 h = __floats2half2_rn(v0, v1);
    return *reinterpret_cast<uint32_t*>(&h);
}

#define LDS_BF 40

// ============================ fused K+V fp16 GEMM (k-chunk 64) ============================
// One CTA (512 thr) computes K[128x128] AND V[128x128] from a SHARED A tile.
// Warps 0-7: K, warps 8-15: V. k-chunk 64, double-buffered (2 x 54KB smem).
// Per buffer (55296B): A @0 (18432), Bk @18432, Bv @36864.
#define KVF_SMEM 110592
#define LDS_K 72        // fp16 row stride (144B, odd 16B-granule count -> conflict-free)
#define TILE72 18432u   // 128 * 72 * 2

__global__ void __launch_bounds__(512, 1)
kvfused_gemm(const __half* __restrict__ A16,
             const __half* __restrict__ Bk16, const __half* __restrict__ Bv16,
             const float* __restrict__ bias_k, const float* __restrict__ bias_v,
             __half* __restrict__ Ck, __half* __restrict__ Cv) {
    extern __shared__ char smem[];
    const int tid  = threadIdx.x;
    const int wid  = tid >> 5;
    const int lane = tid & 31;
    const int grp  = wid >> 3;          // 0 = K, 1 = V
    const int wg   = wid & 7;
    const int m0 = blockIdx.y * 128;
    const int n0 = blockIdx.x * 128;
    const int wm = (wg & 3) * 32;
    const int wn = (wg >> 2) * 64;

    const uint32_t smBase = smem_u32(smem);
    const uint32_t aRow = (uint32_t)(wm + (lane & 15)) * LDS_K + (uint32_t)(lane >> 4) * 8u;
    const uint32_t bRow = (uint32_t)(wn + (lane & 7) + ((lane >> 4) * 8)) * LDS_K
                        + (uint32_t)((lane >> 3) & 1) * 8u;
    const uint32_t bTileOff = TILE72 + (uint32_t)grp * TILE72;

    float acc[2][8][4];
    #pragma unroll
    for (int i = 0; i < 2; i++)
        #pragma unroll
        for (int j = 0; j < 8; j++)
            #pragma unroll
            for (int k = 0; k < 4; k++) acc[i][j][k] = 0.f;

    const int r  = tid >> 2;    // 0..127
    const int cc = tid & 3;     // base 16B col (0..3); also loads cc+4

    auto load_chunk = [&](int k0, int buf) {
        uint32_t base = smBase + (uint32_t)buf * (3u * TILE72);
        #pragma unroll
        for (int p = 0; p < 2; p++) {
            int col = cc + p * 4;   // 0..7
            uint32_t so = ((uint32_t)r * LDS_K + (uint32_t)col * 8u) * 2u;
            size_t ga = (size_t)(m0 + r) * CTXD + k0 + col * 8;
            size_t gb = (size_t)(n0 + r) * CTXD + k0 + col * 8;
            cp16(base + so,              A16  + ga);
            cp16(base + TILE72 + so,     Bk16 + gb);
            cp16(base + 2u * TILE72 + so, Bv16 + gb);
        }
    };

    load_chunk(0, 0);
    CP_COMMIT();

    for (int c = 0; c < CTXD / 64; c++) {
        CP_WAIT0();
        __syncthreads();
        if (c + 1 < CTXD / 64) { load_chunk((c + 1) << 6, (c + 1) & 1); CP_COMMIT(); }

        uint32_t base = smBase + (uint32_t)(c & 1) * (3u * TILE72);
        uint32_t bB = base + bTileOff;
        #pragma unroll
        for (int ks = 0; ks < 4; ks++) {
            const uint32_t kcol = (uint32_t)ks * 16u;
            uint32_t a[2][4], b[4][4];
            #pragma unroll
            for (int g = 0; g < 4; g++) {
                uint32_t off = (bRow + (uint32_t)g * 16u * LDS_K + kcol) * 2u;
                ldm_x4(b[g], bB + off);
            }
            #pragma unroll
            for (int mi = 0; mi < 2; mi++) {
                uint32_t off = (aRow + (uint32_t)mi * 16u * LDS_K + kcol) * 2u;
                ldm_x4(a[mi], base + off);
            }
            #pragma unroll
            for (int mi = 0; mi < 2; mi++)
                #pragma unroll
                for (int nj = 0; nj < 8; nj++)
                    mma16816h(acc[mi][nj], a[mi], &b[nj >> 1][(nj & 1) * 2]);
        }
        __syncthreads();
    }

    const float* bias_n = grp ? bias_v : bias_k;
    __half* C16 = grp ? Cv : Ck;
    #pragma unroll
    for (int mi = 0; mi < 2; mi++) {
        int gm = m0 + wm + mi * 16 + (lane >> 2);
        #pragma unroll
        for (int nj = 0; nj < 8; nj++) {
            int gn = n0 + wn + nj * 8 + (lane & 3) * 2;
            float b0 = bias_n[gn], b1 = bias_n[gn + 1];
            uint32_t p0 = packh2(acc[mi][nj][0] + b0, acc[mi][nj][1] + b1);
            uint32_t p1 = packh2(acc[mi][nj][2] + b0, acc[mi][nj][3] + b1);
            *reinterpret_cast<uint32_t*>(C16 + (size_t)gm * DMODEL + gn)       = p0;
            *reinterpret_cast<uint32_t*>(C16 + (size_t)(gm + 8) * DMODEL + gn) = p1;
        }
    }
}

// ============================ split-bf16 3-term NT GEMM (O-proj) ============================
#define G3_SMEM 81920

__global__ void __launch_bounds__(256, 2)
oproj_gemm(const bf16* __restrict__ Ahi, const bf16* __restrict__ Alo,
           const bf16* __restrict__ Bhi, const bf16* __restrict__ Blo,
           const float* __restrict__ bias_n, float* __restrict__ C) {
    extern __shared__ char smem[];
    const int tid  = threadIdx.x;
    const int wid  = tid >> 5;
    const int lane = tid & 31;
    const int m0 = blockIdx.y * 128;
    const int n0 = blockIdx.x * 128;
    const int wm = (wid & 3) * 32;
    const int wn = (wid >> 2) * 64;

    const uint32_t smBase = smem_u32(smem);
    const uint32_t aRow = (uint32_t)(wm + (lane & 15)) * LDS_BF + (uint32_t)(lane >> 4) * 8u;
    const uint32_t bRow = (uint32_t)(wn + (lane & 7) + ((lane >> 4) * 8)) * LDS_BF
                        + (uint32_t)((lane >> 3) & 1) * 8u;

    float acc[2][8][4];
    #pragma unroll
    for (int i = 0; i < 2; i++)
        #pragma unroll
        for (int j = 0; j < 8; j++)
            #pragma unroll
            for (int k = 0; k < 4; k++) acc[i][j][k] = 0.f;

    const int r  = tid >> 2;
    const int cc = tid & 3;

    auto load_chunk = [&](int k0, int buf) {
        uint32_t aB = smBase + (uint32_t)buf * 20480u;
        uint32_t bB = smBase + 40960u + (uint32_t)buf * 20480u;
        #pragma unroll
        for (int h = 0; h < 2; h++) {
            int rr = r + h * 64;
            uint32_t so = ((uint32_t)rr * LDS_BF + (uint32_t)cc * 8u) * 2u;
            size_t ga = (size_t)(m0 + rr) * DMODEL + k0 + cc * 8;
            size_t gb = (size_t)(n0 + rr) * DMODEL + k0 + cc * 8;
            cp16(aB + so,           Ahi + ga);
            cp16(aB + 10240u + so,  Alo + ga);
            cp16(bB + so,           Bhi + gb);
            cp16(bB + 10240u + so,  Blo + gb);
        }
    };

    load_chunk(0, 0);
    CP_COMMIT();

    for (int c = 0; c < DMODEL / 32; c++) {
        CP_WAIT0();
        __syncthreads();
        if (c + 1 < DMODEL / 32) { load_chunk((c + 1) << 5, (c + 1) & 1); CP_COMMIT(); }

        uint32_t aB = smBase + (uint32_t)(c & 1) * 20480u;
        uint32_t bB = smBase + 40960u + (uint32_t)(c & 1) * 20480u;
        #pragma unroll
        for (int ks = 0; ks < 2; ks++) {
            const uint32_t kcol = (uint32_t)ks * 16u;
            uint32_t ahi[2][4], alo[2][4], bhi[4][4], blo[4][4];
            #pragma unroll
            for (int g = 0; g < 4; g++) {
                uint32_t off = (bRow + (uint32_t)g * 16u * LDS_BF + kcol) * 2u;
                ldm_x4(bhi[g], bB + off);
                ldm_x4(blo[g], bB + 10240u + off);
            }
            #pragma unroll
            for (int mi = 0; mi < 2; mi++) {
                uint32_t off = (aRow + (uint32_t)mi * 16u * LDS_BF + kcol) * 2u;
                ldm_x4(ahi[mi], aB + off);
                ldm_x4(alo[mi], aB + 10240u + off);
            }
            #pragma unroll
            for (int mi = 0; mi < 2; mi++)
                #pragma unroll
                for (int nj = 0; nj < 8; nj++)
                    mma16816(acc[mi][nj], ahi[mi], &bhi[nj >> 1][(nj & 1) * 2]);
            #pragma unroll
            for (int mi = 0; mi < 2; mi++)
                #pragma unroll
                for (int nj = 0; nj < 8; nj++)
                    mma16816(acc[mi][nj], alo[mi], &bhi[nj >> 1][(nj & 1) * 2]);
            #pragma unroll
            for (int mi = 0; mi < 2; mi++)
                #pragma unroll
                for (int nj = 0; nj < 8; nj++)
                    mma16816(acc[mi][nj], ahi[mi], &blo[nj >> 1][(nj & 1) * 2]);
        }
        __syncthreads();
    }

    #pragma unroll
    for (int mi = 0; mi < 2; mi++) {
        int gm = m0 + wm + mi * 16 + (lane >> 2);
        #pragma unroll
        for (int nj = 0; nj < 8; nj++) {
            int gn = n0 + wn + nj * 8 + (lane & 3) * 2;
            float b0 = bias_n[gn], b1 = bias_n[gn + 1];
            *reinterpret_cast<float2*>(C + (size_t)gm * DMODEL + gn) =
                make_float2(acc[mi][nj][0] + b0, acc[mi][nj][1] + b1);
            *reinterpret_cast<float2*>(C + (size_t)(gm + 8) * DMODEL + gn) =
                make_float2(acc[mi][nj][2] + b0, acc[mi][nj][3] + b1);
        }
    }
}

// ============================ fused flash attention (all fp16) ============================
#define FA_SMEM 80384
#define FA_LDS 104

__global__ void __launch_bounds__(256, 1)
fa_kernel(const __half* __restrict__ Q16,
          const __half* __restrict__ K16, const __half* __restrict__ V16,
          const float* __restrict__ biasBL, float scale,
          bf16* __restrict__ Ohi, bf16* __restrict__ Olo) {
    extern __shared__ char smem[];
    const int tid = threadIdx.x;
    const int wid = tid >> 5, lane = tid & 31;
    const int z = blockIdx.y;
    const int b = z >> 3, h = z & 7;
    const int q0 = blockIdx.x * 128;
    const size_t bSeq = (size_t)b * SEQ;
    const int hOff = h * HDIM;

    const uint32_t smBase = smem_u32(smem);
    const uint32_t KBASE = 26624u, VBASE = 53248u, BBASE = 79872u;

    for (int i = tid; i < 1536; i += 256) {
        int row = i / 12, col = i % 12;
        uint32_t so = ((uint32_t)row * FA_LDS + (uint32_t)col * 8u) * 2u;
        size_t go = (size_t)(q0 + row) * DMODEL + hOff + col * 8;
        cp16(smBase + so, Q16 + go);
    }
    CP_COMMIT();

    auto load_kv = [&](int c, int buf) {
        int l0 = c * 64;
        uint32_t kB = smBase + KBASE + (uint32_t)buf * 13312u;
        uint32_t vB = smBase + VBASE + (uint32_t)buf * 13312u;
        for (int i = tid; i < 768; i += 256) {
            int row = i / 12, col = i % 12;
            uint32_t so = ((uint32_t)row * FA_LDS + (uint32_t)col * 8u) * 2u;
            size_t go = (bSeq + l0 + row) * DMODEL + hOff + col * 8;
            cp16(kB + so, K16 + go);
            cp16(vB + so, V16 + go);
        }
        if (tid < 16)
            cp16(smBase + BBASE + (uint32_t)buf * 256u + (uint32_t)tid * 16u,
                 biasBL + bSeq + l0 + tid * 4);
    };
    load_kv(0, 0);
    CP_COMMIT();

    const uint32_t aRow = (uint32_t)(wid * 16 + (lane & 15)) * FA_LDS + (uint32_t)(lane >> 4) * 8u;
    const uint32_t bRow = (uint32_t)((lane & 7) + ((lane >> 4) * 8)) * FA_LDS
                        + (uint32_t)((lane >> 3) & 1) * 8u;
    const uint32_t vLaneRow = (uint32_t)((lane & 7) + ((lane >> 3) & 1) * 8);
    const uint32_t vLaneCol = (uint32_t)(lane >> 4) * 8u;

    float oacc[12][4];
    #pragma unroll
    for (int j = 0; j < 12; j++)
        #pragma unroll
        for (int k = 0; k < 4; k++) oacc[j][k] = 0.f;
    float m0 = -1e30f, m1 = -1e30f, l0s = 0.f, l1s = 0.f;

    for (int c = 0; c < 16; c++) {
        CP_WAIT0();
        __syncthreads();
        if (c + 1 < 16) { load_kv(c + 1, (c + 1) & 1); CP_COMMIT(); }

        const uint32_t kB = smBase + KBASE + (uint32_t)(c & 1) * 13312u;
        const uint32_t vB = smBase + VBASE + (uint32_t)(c & 1) * 13312u;
        const float* sbias = reinterpret_cast<const float*>(smem + BBASE + (c & 1) * 256);

        float s[8][4];
        #pragma unroll
        for (int j = 0; j < 8; j++)
            #pragma unroll
            for (int k = 0; k < 4; k++) s[j][k] = 0.f;

        #pragma unroll
        for (int ks = 0; ks < 6; ks++) {
            const uint32_t kcol = (uint32_t)ks * 16u;
            uint32_t qF[4], kk[4];
            ldm_x4(qF, smBase + (aRow + kcol) * 2u);
            #pragma unroll
            for (int g = 0; g < 4; g++) {
                uint32_t off = (bRow + (uint32_t)g * 16u * FA_LDS + kcol) * 2u;
                ldm_x4(kk, kB + off);
                mma16816h(s[2 * g],     qF, &kk[0]);
                mma16816h(s[2 * g + 1], qF, &kk[2]);
            }
        }

        float mx0 = -1e30f, mx1 = -1e30f;
        #pragma unroll
        for (int nj = 0; nj < 8; nj++) {
            int cidx = nj * 8 + (lane & 3) * 2;
            float bj0 = sbias[cidx], bj1 = sbias[cidx + 1];
            s[nj][0] = s[nj][0] * scale + bj0;
            s[nj][1] = s[nj][1] * scale + bj1;
            s[nj][2] = s[nj][2] * scale + bj0;
            s[nj][3] = s[nj][3] * scale + bj1;
            mx0 = fmaxf(mx0, fmaxf(s[nj][0], s[nj][1]));
            mx1 = fmaxf(mx1, fmaxf(s[nj][2], s[nj][3]));
        }
        #pragma unroll
        for (int o = 1; o <= 2; o <<= 1) {
            mx0 = fmaxf(mx0, __shfl_xor_sync(0xffffffffu, mx0, o));
            mx1 = fmaxf(mx1, __shfl_xor_sync(0xffffffffu, mx1, o));
        }
        float mn0 = fmaxf(m0, mx0), mn1 = fmaxf(m1, mx1);
        float cor0 = __expf(m0 - mn0), cor1 = __expf(m1 - mn1);
        l0s *= cor0; l1s *= cor1;
        #pragma unroll
        for (int j = 0; j < 12; j++) {
            oacc[j][0] *= cor0; oacc[j][1] *= cor0;
            oacc[j][2] *= cor1; oacc[j][3] *= cor1;
        }
        m0 = mn0; m1 = mn1;

        float rs0 = 0.f, rs1 = 0.f;
        uint32_t pF[4][4];
        #pragma unroll
        for (int t = 0; t < 4; t++) {
            float p00 = __expf(s[2 * t][0] - mn0);
            float p01 = __expf(s[2 * t][1] - mn0);
            float p10 = __expf(s[2 * t][2] - mn1);
            float p11 = __expf(s[2 * t][3] - mn1);
            float p20 = __expf(s[2 * t + 1][0] - mn0);
            float p21 = __expf(s[2 * t + 1][1] - mn0);
            float p30 = __expf(s[2 * t + 1][2] - mn1);
            float p31 = __expf(s[2 * t + 1][3] - mn1);
            rs0 += p00 + p01 + p20 + p21;
            rs1 += p10 + p11 + p30 + p31;
            pF[t][0] = packh2(p00, p01);
            pF[t][1] = packh2(p10, p11);
            pF[t][2] = packh2(p20, p21);
            pF[t][3] = packh2(p30, p31);
        }
        #pragma unroll
        for (int o = 1; o <= 2; o <<= 1) {
            rs0 += __shfl_xor_sync(0xffffffffu, rs0, o);
            rs1 += __shfl_xor_sync(0xffffffffu, rs1, o);
        }
        l0s += rs0; l1s += rs1;

        #pragma unroll
        for (int t = 0; t < 4; t++) {
            uint32_t vv[4];
            #pragma unroll
            for (int g = 0; g < 6; g++) {
                uint32_t off = (((uint32_t)t * 16u + vLaneRow) * FA_LDS
                                + (uint32_t)g * 16u + vLaneCol) * 2u;
                ldm_x4_t(vv, vB + off);
                mma16816h(oacc[2 * g],     pF[t], &vv[0]);
                mma16816h(oacc[2 * g + 1], pF[t], &vv[2]);
            }
        }
    }

    float inv0 = 1.0f / l0s, inv1 = 1.0f / l1s;
    const int q = q0 + wid * 16 + (lane >> 2);
    #pragma unroll
    for (int j = 0; j < 12; j++) {
        int n = j * 8 + (lane & 3) * 2;
        size_t o0 = ((size_t)(b * NQ + q)) * DMODEL + hOff + n;
        size_t o1 = o0 + (size_t)8 * DMODEL;
        bf162 h2, l2;
        split2(oacc[j][0] * inv0, oacc[j][1] * inv0, h2, l2);
        *reinterpret_cast<bf162*>(Ohi + o0) = h2;
        *reinterpret_cast<bf162*>(Olo + o0) = l2;
        split2(oacc[j][2] * inv1, oacc[j][3] * inv1, h2, l2);
        *reinterpret_cast<bf162*>(Ohi + o1) = h2;
        *reinterpret_cast<bf162*>(Olo + o1) = l2;
    }
}

// ============================ LayerNorm / misc ============================
__device__ __forceinline__ void ln_stats(const float* __restrict__ xr, int ncols,
                                         float& mu, float& rs, float* s1, float* s2) {
    float sum = 0.f, sumsq = 0.f;
    for (int i = threadIdx.x; i < ncols; i += blockDim.x) {
        float v = xr[i];
        sum += v; sumsq += v * v;
    }
    #pragma unroll
    for (int o = 16; o; o >>= 1) {
        sum   += __shfl_xor_sync(0xffffffffu, sum, o);
        sumsq += __shfl_xor_sync(0xffffffffu, sumsq, o);
    }
    int wid = threadIdx.x >> 5, lid = threadIdx.x & 31;
    if (lid == 0) { s1[wid] = sum; s2[wid] = sumsq; }
    __syncthreads();
    if (threadIdx.x < 32) {
        int nw = blockDim.x >> 5;
        float a = (lid < nw) ? s1[lid] : 0.f;
        float c = (lid < nw) ? s2[lid] : 0.f;
        #pragma unroll
        for (int o = 16; o; o >>= 1) {
            a += __shfl_xor_sync(0xffffffffu, a, o);
            c += __shfl_xor_sync(0xffffffffu, c, o);
        }
        if (lid == 0) { s1[0] = a; s2[0] = c; }
    }
    __syncthreads();
    float inv_n = 1.0f / (float)ncols;
    mu = s1[0] * inv_n;
    float var = s2[0] * inv_n - mu * mu;
    rs = rsqrtf(var + 1e-5f);
}

__global__ void ln_kernel(const float* __restrict__ x, const float* __restrict__ w,
                          const float* __restrict__ b, float* __restrict__ out, int ncols) {
    __shared__ float s1[32], s2[32];
    const size_t row = blockIdx.x;
    const float* xr = x + row * (size_t)ncols;
    float mu, rs;
    ln_stats(xr, ncols, mu, rs, s1, s2);
    float* orow = out + row * (size_t)ncols;
    for (int i = threadIdx.x; i < ncols; i += blockDim.x)
        orow[i] = (xr[i] - mu) * rs * w[i] + b[i];
}

__global__ void ln_h_kernel(const float* __restrict__ x, const float* __restrict__ w,
                            const float* __restrict__ b,
                            __half* __restrict__ o16, int ncols) {
    __shared__ float s1[32], s2[32];
    const size_t row = blockIdx.x;
    const float* xr = x + row * (size_t)ncols;
    float mu, rs;
    ln_stats(xr, ncols, mu, rs, s1, s2);
    __half* orow = o16 + row * (size_t)ncols;
    for (int i = threadIdx.x; i < ncols; i += blockDim.x) {
        float y = (xr[i] - mu) * rs * w[i] + b[i];
        orow[i] = __float2half_rn(y);
    }
}

__global__ void cvt_h_kernel(const float* __restrict__ x, __half* __restrict__ o, int n) {
    int i = blockIdx.x * blockDim.x + threadIdx.x;
    if (i < n) o[i] = __float2half_rn(x[i]);
}

__global__ void split_kernel(const float* __restrict__ x,
                             bf16* __restrict__ hi, bf16* __restrict__ lo, int n) {
    int i = blockIdx.x * blockDim.x + threadIdx.x;
    if (i < n) {
        float v = x[i];
        bf16 h = __float2bfloat16(v);
        hi[i] = h;
        lo[i] = __float2bfloat16(v - __bfloat162float(h));
    }
}

__global__ void bias_kernel(const float* __restrict__ size_in, const float* __restrict__ mask,
                            float* __restrict__ bias, int n) {
    int i = blockIdx.x * blockDim.x + threadIdx.x;
    if (i < n) {
        float s = size_in[i];
        s = (s < 0.5f) ? 1.0f : s;
        bias[i] = logf(s) + mask[i];
    }
}

// ============================ SIMT GEMM (Q-proj only) ============================
#define TBM 64
#define TBN 64
#define TBK 16
#define SPAD 4

__global__ void __launch_bounds__(256)
gemm_nt_kernel(const float* __restrict__ A, int lda,
               const float* __restrict__ B, int ldb,
               float* __restrict__ C, int ldc,
               int M, int N, int K, float alpha, const float* __restrict__ bias_n) {
    __shared__ __align__(16) float As[TBK][TBM + SPAD];
    __shared__ __align__(16) float Bs[TBK][TBN + SPAD];
    const int m0 = blockIdx.y * TBM;
    const int n0 = blockIdx.x * TBN;
    const int t  = threadIdx.x;
    const int tx = t & 15, ty = t >> 4;
    float acc[4][4] = {};
    for (int k0 = 0; k0 < K; k0 += TBK) {
        {
            int col = t & 15, rowb = t >> 4;
            #pragma unroll
            for (int i = 0; i < 4; i++) {
                int rr = rowb + i * 16;
                As[col][rr] = A[(size_t)(m0 + rr) * lda + k0 + col];
            }
        }
        {
            int col = t & 15, rowb = t >> 4;
            #pragma unroll
            for (int i = 0; i < 4; i++) {
                int nn = rowb + i * 16;
                Bs[col][nn] = B[(size_t)(n0 + nn) * ldb + k0 + col];
            }
        }
        __syncthreads();
        #pragma unroll
        for (int kk = 0; kk < TBK; kk++) {
            float4 av = *reinterpret_cast<const float4*>(&As[kk][ty * 4]);
            float4 bv = *reinterpret_cast<const float4*>(&Bs[kk][tx * 4]);
            float a[4] = {av.x, av.y, av.z, av.w};
            float b[4] = {bv.x, bv.y, bv.z, bv.w};
            #pragma unroll
            for (int i = 0; i < 4; i++)
                #pragma unroll
                for (int j = 0; j < 4; j++)
                    acc[i][j] += a[i] * b[j];
        }
        __syncthreads();
    }
    #pragma unroll
    for (int i = 0; i < 4; i++) {
        int gm = m0 + ty * 4 + i;
        #pragma unroll
        for (int j = 0; j < 4; j++) {
            int gn = n0 + tx * 4 + j;
            float v = alpha * acc[i][j];
            if (bias_n) v += bias_n[gn];
            C[(size_t)gm * ldc + gn] = v;
        }
    }
}

// ============================ launch ============================
extern "C" void kernel_launch(void* const* d_in, const int* in_sizes, int n_in,
                              void* d_out, int out_size) {
    const float* x     = (const float*)d_in[0];
    const float* sizei = (const float*)d_in[1];
    const float* amask = (const float*)d_in[2];
    const float* query = (const float*)d_in[3];
    const float* ln_q_w = (const float*)d_in[4];
    const float* ln_q_b = (const float*)d_in[5];
    const float* ln_k_w = (const float*)d_in[6];
    const float* ln_k_b = (const float*)d_in[7];
    const float* Wq = (const float*)d_in[8];
    const float* Wk = (const float*)d_in[9];
    const float* Wv = (const float*)d_in[10];
    const float* bq = (const float*)d_in[11];
    const float* bk = (const float*)d_in[12];
    const float* bv = (const float*)d_in[13];
    const float* Wo = (const float*)d_in[14];
    const float* bo = (const float*)d_in[15];
    float* out = (float*)d_out;

    __half *x16, *wk16, *wv16, *kh16, *vh16, *qh16;
    bf16 *wohi, *wolo, *aohi, *aolo;
    float *qln, *qh, *bias;
    cudaGetSymbolAddress((void**)&x16, g_x16);
    cudaGetSymbolAddress((void**)&wk16, g_wk16);
    cudaGetSymbolAddress((void**)&wv16, g_wv16);
    cudaGetSymbolAddress((void**)&kh16, g_kh16);
    cudaGetSymbolAddress((void**)&vh16, g_vh16);
    cudaGetSymbolAddress((void**)&qh16, g_qh16);
    cudaGetSymbolAddress((void**)&wohi, g_wohi);
    cudaGetSymbolAddress((void**)&wolo, g_wolo);
    cudaGetSymbolAddress((void**)&aohi, g_aohi);
    cudaGetSymbolAddress((void**)&aolo, g_aolo);
    cudaGetSymbolAddress((void**)&qln, g_qln);
    cudaGetSymbolAddress((void**)&qh, g_qh);
    cudaGetSymbolAddress((void**)&bias, g_bias);

    cudaFuncSetAttribute(kvfused_gemm, cudaFuncAttributeMaxDynamicSharedMemorySize, KVF_SMEM);
    cudaFuncSetAttribute(oproj_gemm,   cudaFuncAttributeMaxDynamicSharedMemorySize, G3_SMEM);
    cudaFuncSetAttribute(fa_kernel,    cudaFuncAttributeMaxDynamicSharedMemorySize, FA_SMEM);

    const float scale = 0.10206207261596575f;  // 1/sqrt(96)

    // launch order: index 3 (ncu-profiled) = kvfused_gemm
    ln_h_kernel<<<MROWS, 256>>>(x, ln_k_w, ln_k_b, x16, CTXD);                         // 0
    cvt_h_kernel<<<(DMODEL * CTXD + 255) / 256, 256>>>(Wk, wk16, DMODEL * CTXD);       // 1
    cvt_h_kernel<<<(DMODEL * CTXD + 255) / 256, 256>>>(Wv, wv16, DMODEL * CTXD);       // 2
    kvfused_gemm<<<dim3(DMODEL / 128, MROWS / 128), 512, KVF_SMEM>>>(                  // 3 (profiled)
        x16, wk16, wv16, bk, bv, kh16, vh16);
    ln_kernel<<<NQ, 256>>>(query, ln_q_w, ln_q_b, qln, DMODEL);                        // 4
    split_kernel<<<(DMODEL * DMODEL + 255) / 256, 256>>>(Wo, wohi, wolo, DMODEL * DMODEL); // 5
    bias_kernel<<<(MROWS + 255) / 256, 256>>>(sizei, amask, bias, MROWS);              // 6
    gemm_nt_kernel<<<dim3(DMODEL / TBN, NQ / TBM), 256>>>(                             // 7
        qln, DMODEL, Wq, DMODEL, qh, DMODEL, NQ, DMODEL, DMODEL, 1.0f, bq);
    cvt_h_kernel<<<(NQ * DMODEL + 255) / 256, 256>>>(qh, qh16, NQ * DMODEL);           // 8

    fa_kernel<<<dim3(NQ / 128, NZ), 256, FA_SMEM>>>(                                   // 9
        qh16, kh16, vh16, bias, scale, aohi, aolo);

    oproj_gemm<<<dim3(DMODEL / 128, BATCH * NQ / 128), 256, G3_SMEM>>>(                // 10
        aohi, aolo, wohi, wolo, bo, out);
}

// round 15
// speedup vs baseline: 2.2401x; 1.2488x over previous
#include <cuda_runtime.h>
#include <cuda_bf16.h>
#include <cuda_fp16.h>
#include <cstdint>

#define BATCH     32
#define SEQ       1024
#define CTXD      1024
#define DMODEL    768
#define NHEAD     8
#define HDIM      96
#define NQ        256
#define MROWS     (BATCH * SEQ)   // 32768
#define NZ        (BATCH * NHEAD) // 256

typedef __nv_bfloat16 bf16;
typedef __nv_bfloat162 bf162;

// ============================ device scratch ============================
__device__ __half g_x16[MROWS * CTXD];            // LN(x) fp16
__device__ __half g_wk16[DMODEL * CTXD];
__device__ __half g_wv16[DMODEL * CTXD];
__device__ __half g_wo16[DMODEL * DMODEL];
__device__ __half g_kh16[MROWS * DMODEL];
__device__ __half g_vh16[MROWS * DMODEL];
__device__ __half g_qh16[NQ * DMODEL];
__device__ __half g_ao16[BATCH * NQ * DMODEL];    // attnout fp16
__device__ float g_qln[NQ * DMODEL];
__device__ float g_qh[NQ * DMODEL];
__device__ float g_bias[MROWS];

// ============================ asm helpers ============================
__device__ __forceinline__ uint32_t smem_u32(const void* p) {
    uint32_t a;
    asm("{ .reg .u64 t; cvta.to.shared.u64 t, %1; cvt.u32.u64 %0, t; }" : "=r"(a) : "l"(p));
    return a;
}
__device__ __forceinline__ void ldm_x4(uint32_t* r, uint32_t addr) {
    asm volatile("ldmatrix.sync.aligned.m8n8.x4.shared.b16 {%0,%1,%2,%3}, [%4];"
                 : "=r"(r[0]), "=r"(r[1]), "=r"(r[2]), "=r"(r[3]) : "r"(addr));
}
__device__ __forceinline__ void ldm_x4_t(uint32_t* r, uint32_t addr) {
    asm volatile("ldmatrix.sync.aligned.m8n8.x4.trans.shared.b16 {%0,%1,%2,%3}, [%4];"
                 : "=r"(r[0]), "=r"(r[1]), "=r"(r[2]), "=r"(r[3]) : "r"(addr));
}
__device__ __forceinline__ void mma16816h(float* c, const uint32_t* a, const uint32_t* b) {
    asm volatile("mma.sync.aligned.m16n8k16.row.col.f32.f16.f16.f32 "
                 "{%0,%1,%2,%3}, {%4,%5,%6,%7}, {%8,%9}, {%0,%1,%2,%3};"
                 : "+f"(c[0]), "+f"(c[1]), "+f"(c[2]), "+f"(c[3])
                 : "r"(a[0]), "r"(a[1]), "r"(a[2]), "r"(a[3]), "r"(b[0]), "r"(b[1]));
}
__device__ __forceinline__ void cp16(uint32_t dst, const void* src) {
    asm volatile("cp.async.cg.shared.global [%0], [%1], 16;" :: "r"(dst), "l"(src));
}
#define CP_COMMIT() asm volatile("cp.async.commit_group;")
#define CP_WAIT0()  asm volatile("cp.async.wait_group 0;")

__device__ __forceinline__ uint32_t packh2(float v0, float v1) {
    __half2 h = __floats2half2_rn(v0, v1);
    return *reinterpret_cast<uint32_t*>(&h);
}

#define LDS_K 72        // fp16 row stride (144B, odd 16B-granule count -> conflict-free)
#define ATILE 18432u    // 128 * 72 * 2
#define BTILE 9216u     // 64 * 72 * 2

// ============================ fused K+V fp16 GEMM (256 thr, 2 CTAs/SM) ============================
// CTA computes K[128x64] and V[128x64] from a SHARED A tile.
// Warps 0-3: K (warp tile 32x64), warps 4-7: V. k-chunk 64, double-buffered.
// smem per buffer (36864B): A @0, Bk @18432, Bv @27648. Total 73728.
#define KVF_SMEM 73728

__global__ void __launch_bounds__(256, 2)
kvfused_gemm(const __half* __restrict__ A16,
             const __half* __restrict__ Bk16, const __half* __restrict__ Bv16,
             const float* __restrict__ bias_k, const float* __restrict__ bias_v,
             __half* __restrict__ Ck, __half* __restrict__ Cv) {
    extern __shared__ char smem[];
    const int tid  = threadIdx.x;
    const int wid  = tid >> 5;
    const int lane = tid & 31;
    const int grp  = wid >> 2;          // 0 = K, 1 = V
    const int wg   = wid & 3;
    const int m0 = blockIdx.y * 128;
    const int n0 = blockIdx.x * 64;
    const int wm = wg * 32;

    const uint32_t smBase = smem_u32(smem);
    const uint32_t aRow = (uint32_t)(wm + (lane & 15)) * LDS_K + (uint32_t)(lane >> 4) * 8u;
    const uint32_t bRow = (uint32_t)((lane & 7) + ((lane >> 4) * 8)) * LDS_K
                        + (uint32_t)((lane >> 3) & 1) * 8u;
    const uint32_t bOff = ATILE + (uint32_t)grp * BTILE;

    float acc[2][8][4];
    #pragma unroll
    for (int i = 0; i < 2; i++)
        #pragma unroll
        for (int j = 0; j < 8; j++)
            #pragma unroll
            for (int k = 0; k < 4; k++) acc[i][j][k] = 0.f;

    auto load_chunk = [&](int k0, int buf) {
        uint32_t base = smBase + (uint32_t)buf * 36864u;
        // A: 128 rows x 8 cols of 16B = 1024 lines (4 per thread)
        #pragma unroll
        for (int i = 0; i < 4; i++) {
            int idx = tid + i * 256;
            int row = idx >> 3, col = idx & 7;
            uint32_t so = ((uint32_t)row * LDS_K + (uint32_t)col * 8u) * 2u;
            cp16(base + so, A16 + (size_t)(m0 + row) * CTXD + k0 + col * 8);
        }
        // Bk, Bv: 64 rows x 8 cols = 512 lines each (2 per thread)
        #pragma unroll
        for (int i = 0; i < 2; i++) {
            int idx = tid + i * 256;
            int row = idx >> 3, col = idx & 7;
            uint32_t so = ((uint32_t)row * LDS_K + (uint32_t)col * 8u) * 2u;
            size_t gb = (size_t)(n0 + row) * CTXD + k0 + col * 8;
            cp16(base + ATILE + so,         Bk16 + gb);
            cp16(base + ATILE + BTILE + so, Bv16 + gb);
        }
    };

    load_chunk(0, 0);
    CP_COMMIT();

    for (int c = 0; c < CTXD / 64; c++) {
        CP_WAIT0();
        __syncthreads();
        if (c + 1 < CTXD / 64) { load_chunk((c + 1) << 6, (c + 1) & 1); CP_COMMIT(); }

        uint32_t base = smBase + (uint32_t)(c & 1) * 36864u;
        uint32_t bB = base + bOff;
        #pragma unroll
        for (int ks = 0; ks < 4; ks++) {
            const uint32_t kcol = (uint32_t)ks * 16u;
            uint32_t a[2][4], b[4][4];
            #pragma unroll
            for (int g = 0; g < 4; g++) {
                uint32_t off = (bRow + (uint32_t)g * 16u * LDS_K + kcol) * 2u;
                ldm_x4(b[g], bB + off);
            }
            #pragma unroll
            for (int mi = 0; mi < 2; mi++) {
                uint32_t off = (aRow + (uint32_t)mi * 16u * LDS_K + kcol) * 2u;
                ldm_x4(a[mi], base + off);
            }
            #pragma unroll
            for (int mi = 0; mi < 2; mi++)
                #pragma unroll
                for (int nj = 0; nj < 8; nj++)
                    mma16816h(acc[mi][nj], a[mi], &b[nj >> 1][(nj & 1) * 2]);
        }
        __syncthreads();
    }

    const float* bias_n = grp ? bias_v : bias_k;
    __half* C16 = grp ? Cv : Ck;
    #pragma unroll
    for (int mi = 0; mi < 2; mi++) {
        int gm = m0 + wm + mi * 16 + (lane >> 2);
        #pragma unroll
        for (int nj = 0; nj < 8; nj++) {
            int gn = n0 + nj * 8 + (lane & 3) * 2;
            float b0 = bias_n[gn], b1 = bias_n[gn + 1];
            uint32_t p0 = packh2(acc[mi][nj][0] + b0, acc[mi][nj][1] + b1);
            uint32_t p1 = packh2(acc[mi][nj][2] + b0, acc[mi][nj][3] + b1);
            *reinterpret_cast<uint32_t*>(C16 + (size_t)gm * DMODEL + gn)       = p0;
            *reinterpret_cast<uint32_t*>(C16 + (size_t)(gm + 8) * DMODEL + gn) = p1;
        }
    }
}

// ============================ plain fp16 NT GEMM (O-proj) ============================
// C[M,N] = A16[m,k] * B16[n,k]^T + bias_n (fp32 out). k-chunk 64, 2 CTAs/SM.
// smem per buffer (36864B): A @0, B @18432. Total 73728.
#define OP_SMEM 73728

__global__ void __launch_bounds__(256, 2)
oproj_h(const __half* __restrict__ A16, const __half* __restrict__ B16,
        const float* __restrict__ bias_n, float* __restrict__ C) {
    extern __shared__ char smem[];
    const int tid  = threadIdx.x;
    const int wid  = tid >> 5;
    const int lane = tid & 31;
    const int m0 = blockIdx.y * 128;
    const int n0 = blockIdx.x * 128;
    const int wm = (wid & 3) * 32;
    const int wn = (wid >> 2) * 64;

    const uint32_t smBase = smem_u32(smem);
    const uint32_t aRow = (uint32_t)(wm + (lane & 15)) * LDS_K + (uint32_t)(lane >> 4) * 8u;
    const uint32_t bRow = (uint32_t)(wn + (lane & 7) + ((lane >> 4) * 8)) * LDS_K
                        + (uint32_t)((lane >> 3) & 1) * 8u;

    float acc[2][8][4];
    #pragma unroll
    for (int i = 0; i < 2; i++)
        #pragma unroll
        for (int j = 0; j < 8; j++)
            #pragma unroll
            for (int k = 0; k < 4; k++) acc[i][j][k] = 0.f;

    auto load_chunk = [&](int k0, int buf) {
        uint32_t base = smBase + (uint32_t)buf * 36864u;
        #pragma unroll
        for (int i = 0; i < 4; i++) {
            int idx = tid + i * 256;
            int row = idx >> 3, col = idx & 7;
            uint32_t so = ((uint32_t)row * LDS_K + (uint32_t)col * 8u) * 2u;
            cp16(base + so,         A16 + (size_t)(m0 + row) * DMODEL + k0 + col * 8);
            cp16(base + ATILE + so, B16 + (size_t)(n0 + row) * DMODEL + k0 + col * 8);
        }
    };

    load_chunk(0, 0);
    CP_COMMIT();

    for (int c = 0; c < DMODEL / 64; c++) {
        CP_WAIT0();
        __syncthreads();
        if (c + 1 < DMODEL / 64) { load_chunk((c + 1) << 6, (c + 1) & 1); CP_COMMIT(); }

        uint32_t base = smBase + (uint32_t)(c & 1) * 36864u;
        uint32_t bB = base + ATILE;
        #pragma unroll
        for (int ks = 0; ks < 4; ks++) {
            const uint32_t kcol = (uint32_t)ks * 16u;
            uint32_t a[2][4], b[4][4];
            #pragma unroll
            for (int g = 0; g < 4; g++) {
                uint32_t off = (bRow + (uint32_t)g * 16u * LDS_K + kcol) * 2u;
                ldm_x4(b[g], bB + off);
            }
            #pragma unroll
            for (int mi = 0; mi < 2; mi++) {
                uint32_t off = (aRow + (uint32_t)mi * 16u * LDS_K + kcol) * 2u;
                ldm_x4(a[mi], base + off);
            }
            #pragma unroll
            for (int mi = 0; mi < 2; mi++)
                #pragma unroll
                for (int nj = 0; nj < 8; nj++)
                    mma16816h(acc[mi][nj], a[mi], &b[nj >> 1][(nj & 1) * 2]);
        }
        __syncthreads();
    }

    #pragma unroll
    for (int mi = 0; mi < 2; mi++) {
        int gm = m0 + wm + mi * 16 + (lane >> 2);
        #pragma unroll
        for (int nj = 0; nj < 8; nj++) {
            int gn = n0 + wn + nj * 8 + (lane & 3) * 2;
            float b0 = bias_n[gn], b1 = bias_n[gn + 1];
            *reinterpret_cast<float2*>(C + (size_t)gm * DMODEL + gn) =
                make_float2(acc[mi][nj][0] + b0, acc[mi][nj][1] + b1);
            *reinterpret_cast<float2*>(C + (size_t)(gm + 8) * DMODEL + gn) =
                make_float2(acc[mi][nj][2] + b0, acc[mi][nj][3] + b1);
        }
    }
}

// ============================ fused flash attention (all fp16, fp16 out) ============================
#define FA_SMEM 80384
#define FA_LDS 104

__global__ void __launch_bounds__(256, 1)
fa_kernel(const __half* __restrict__ Q16,
          const __half* __restrict__ K16, const __half* __restrict__ V16,
          const float* __restrict__ biasBL, float scale,
          __half* __restrict__ O16) {
    extern __shared__ char smem[];
    const int tid = threadIdx.x;
    const int wid = tid >> 5, lane = tid & 31;
    const int z = blockIdx.y;
    const int b = z >> 3, h = z & 7;
    const int q0 = blockIdx.x * 128;
    const size_t bSeq = (size_t)b * SEQ;
    const int hOff = h * HDIM;

    const uint32_t smBase = smem_u32(smem);
    const uint32_t KBASE = 26624u, VBASE = 53248u, BBASE = 79872u;

    for (int i = tid; i < 1536; i += 256) {
        int row = i / 12, col = i % 12;
        uint32_t so = ((uint32_t)row * FA_LDS + (uint32_t)col * 8u) * 2u;
        size_t go = (size_t)(q0 + row) * DMODEL + hOff + col * 8;
        cp16(smBase + so, Q16 + go);
    }
    CP_COMMIT();

    auto load_kv = [&](int c, int buf) {
        int l0 = c * 64;
        uint32_t kB = smBase + KBASE + (uint32_t)buf * 13312u;
        uint32_t vB = smBase + VBASE + (uint32_t)buf * 13312u;
        for (int i = tid; i < 768; i += 256) {
            int row = i / 12, col = i % 12;
            uint32_t so = ((uint32_t)row * FA_LDS + (uint32_t)col * 8u) * 2u;
            size_t go = (bSeq + l0 + row) * DMODEL + hOff + col * 8;
            cp16(kB + so, K16 + go);
            cp16(vB + so, V16 + go);
        }
        if (tid < 16)
            cp16(smBase + BBASE + (uint32_t)buf * 256u + (uint32_t)tid * 16u,
                 biasBL + bSeq + l0 + tid * 4);
    };
    load_kv(0, 0);
    CP_COMMIT();

    const uint32_t aRow = (uint32_t)(wid * 16 + (lane & 15)) * FA_LDS + (uint32_t)(lane >> 4) * 8u;
    const uint32_t bRow = (uint32_t)((lane & 7) + ((lane >> 4) * 8)) * FA_LDS
                        + (uint32_t)((lane >> 3) & 1) * 8u;
    const uint32_t vLaneRow = (uint32_t)((lane & 7) + ((lane >> 3) & 1) * 8);
    const uint32_t vLaneCol = (uint32_t)(lane >> 4) * 8u;

    float oacc[12][4];
    #pragma unroll
    for (int j = 0; j < 12; j++)
        #pragma unroll
        for (int k = 0; k < 4; k++) oacc[j][k] = 0.f;
    float m0 = -1e30f, m1 = -1e30f, l0s = 0.f, l1s = 0.f;

    for (int c = 0; c < 16; c++) {
        CP_WAIT0();
        __syncthreads();
        if (c + 1 < 16) { load_kv(c + 1, (c + 1) & 1); CP_COMMIT(); }

        const uint32_t kB = smBase + KBASE + (uint32_t)(c & 1) * 13312u;
        const uint32_t vB = smBase + VBASE + (uint32_t)(c & 1) * 13312u;
        const float* sbias = reinterpret_cast<const float*>(smem + BBASE + (c & 1) * 256);

        float s[8][4];
        #pragma unroll
        for (int j = 0; j < 8; j++)
            #pragma unroll
            for (int k = 0; k < 4; k++) s[j][k] = 0.f;

        #pragma unroll
        for (int ks = 0; ks < 6; ks++) {
            const uint32_t kcol = (uint32_t)ks * 16u;
            uint32_t qF[4], kk[4];
            ldm_x4(qF, smBase + (aRow + kcol) * 2u);
            #pragma unroll
            for (int g = 0; g < 4; g++) {
                uint32_t off = (bRow + (uint32_t)g * 16u * FA_LDS + kcol) * 2u;
                ldm_x4(kk, kB + off);
                mma16816h(s[2 * g],     qF, &kk[0]);
                mma16816h(s[2 * g + 1], qF, &kk[2]);
            }
        }

        float mx0 = -1e30f, mx1 = -1e30f;
        #pragma unroll
        for (int nj = 0; nj < 8; nj++) {
            int cidx = nj * 8 + (lane & 3) * 2;
            float bj0 = sbias[cidx], bj1 = sbias[cidx + 1];
            s[nj][0] = s[nj][0] * scale + bj0;
            s[nj][1] = s[nj][1] * scale + bj1;
            s[nj][2] = s[nj][2] * scale + bj0;
            s[nj][3] = s[nj][3] * scale + bj1;
            mx0 = fmaxf(mx0, fmaxf(s[nj][0], s[nj][1]));
            mx1 = fmaxf(mx1, fmaxf(s[nj][2], s[nj][3]));
        }
        #pragma unroll
        for (int o = 1; o <= 2; o <<= 1) {
            mx0 = fmaxf(mx0, __shfl_xor_sync(0xffffffffu, mx0, o));
            mx1 = fmaxf(mx1, __shfl_xor_sync(0xffffffffu, mx1, o));
        }
        float mn0 = fmaxf(m0, mx0), mn1 = fmaxf(m1, mx1);
        float cor0 = __expf(m0 - mn0), cor1 = __expf(m1 - mn1);
        l0s *= cor0; l1s *= cor1;
        #pragma unroll
        for (int j = 0; j < 12; j++) {
            oacc[j][0] *= cor0; oacc[j][1] *= cor0;
            oacc[j][2] *= cor1; oacc[j][3] *= cor1;
        }
        m0 = mn0; m1 = mn1;

        float rs0 = 0.f, rs1 = 0.f;
        uint32_t pF[4][4];
        #pragma unroll
        for (int t = 0; t < 4; t++) {
            float p00 = __expf(s[2 * t][0] - mn0);
            float p01 = __expf(s[2 * t][1] - mn0);
            float p10 = __expf(s[2 * t][2] - mn1);
            float p11 = __expf(s[2 * t][3] - mn1);
            float p20 = __expf(s[2 * t + 1][0] - mn0);
            float p21 = __expf(s[2 * t + 1][1] - mn0);
            float p30 = __expf(s[2 * t + 1][2] - mn1);
            float p31 = __expf(s[2 * t + 1][3] - mn1);
            rs0 += p00 + p01 + p20 + p21;
            rs1 += p10 + p11 + p30 + p31;
            pF[t][0] = packh2(p00, p01);
            pF[t][1] = packh2(p10, p11);
            pF[t][2] = packh2(p20, p21);
            pF[t][3] = packh2(p30, p31);
        }
        #pragma unroll
        for (int o = 1; o <= 2; o <<= 1) {
            rs0 += __shfl_xor_sync(0xffffffffu, rs0, o);
            rs1 += __shfl_xor_sync(0xffffffffu, rs1, o);
        }
        l0s += rs0; l1s += rs1;

        #pragma unroll
        for (int t = 0; t < 4; t++) {
            uint32_t vv[4];
            #pragma unroll
            for (int g = 0; g < 6; g++) {
                uint32_t off = (((uint32_t)t * 16u + vLaneRow) * FA_LDS
                                + (uint32_t)g * 16u + vLaneCol) * 2u;
                ldm_x4_t(vv, vB + off);
                mma16816h(oacc[2 * g],     pF[t], &vv[0]);
                mma16816h(oacc[2 * g + 1], pF[t], &vv[2]);
            }
        }
    }

    float inv0 = 1.0f / l0s, inv1 = 1.0f / l1s;
    const int q = q0 + wid * 16 + (lane >> 2);
    #pragma unroll
    for (int j = 0; j < 12; j++) {
        int n = j * 8 + (lane & 3) * 2;
        size_t o0 = ((size_t)(b * NQ + q)) * DMODEL + hOff + n;
        size_t o1 = o0 + (size_t)8 * DMODEL;
        *reinterpret_cast<uint32_t*>(O16 + o0) = packh2(oacc[j][0] * inv0, oacc[j][1] * inv0);
        *reinterpret_cast<uint32_t*>(O16 + o1) = packh2(oacc[j][2] * inv1, oacc[j][3] * inv1);
    }
}

// ============================ LayerNorm / misc ============================
__device__ __forceinline__ void ln_stats(const float* __restrict__ xr, int ncols,
                                         float& mu, float& rs, float* s1, float* s2) {
    float sum = 0.f, sumsq = 0.f;
    for (int i = threadIdx.x; i < ncols; i += blockDim.x) {
        float v = xr[i];
        sum += v; sumsq += v * v;
    }
    #pragma unroll
    for (int o = 16; o; o >>= 1) {
        sum   += __shfl_xor_sync(0xffffffffu, sum, o);
        sumsq += __shfl_xor_sync(0xffffffffu, sumsq, o);
    }
    int wid = threadIdx.x >> 5, lid = threadIdx.x & 31;
    if (lid == 0) { s1[wid] = sum; s2[wid] = sumsq; }
    __syncthreads();
    if (threadIdx.x < 32) {
        int nw = blockDim.x >> 5;
        float a = (lid < nw) ? s1[lid] : 0.f;
        float c = (lid < nw) ? s2[lid] : 0.f;
        #pragma unroll
        for (int o = 16; o; o >>= 1) {
            a += __shfl_xor_sync(0xffffffffu, a, o);
            c += __shfl_xor_sync(0xffffffffu, c, o);
        }
        if (lid == 0) { s1[0] = a; s2[0] = c; }
    }
    __syncthreads();
    float inv_n = 1.0f / (float)ncols;
    mu = s1[0] * inv_n;
    float var = s2[0] * inv_n - mu * mu;
    rs = rsqrtf(var + 1e-5f);
}

__global__ void ln_kernel(const float* __restrict__ x, const float* __restrict__ w,
                          const float* __restrict__ b, float* __restrict__ out, int ncols) {
    __shared__ float s1[32], s2[32];
    const size_t row = blockIdx.x;
    const float* xr = x + row * (size_t)ncols;
    float mu, rs;
    ln_stats(xr, ncols, mu, rs, s1, s2);
    float* orow = out + row * (size_t)ncols;
    for (int i = threadIdx.x; i < ncols; i += blockDim.x)
        orow[i] = (xr[i] - mu) * rs * w[i] + b[i];
}

__global__ void ln_h_kernel(const float* __restrict__ x, const float* __restrict__ w,
                            const float* __restrict__ b,
                            __half* __restrict__ o16, int ncols) {
    __shared__ float s1[32], s2[32];
    const size_t row = blockIdx.x;
    const float* xr = x + row * (size_t)ncols;
    float mu, rs;
    ln_stats(xr, ncols, mu, rs, s1, s2);
    __half* orow = o16 + row * (size_t)ncols;
    for (int i = threadIdx.x; i < ncols; i += blockDim.x) {
        float y = (xr[i] - mu) * rs * w[i] + b[i];
        orow[i] = __float2half_rn(y);
    }
}

__global__ void cvt_h_kernel(const float* __restrict__ x, __half* __restrict__ o, int n) {
    int i = blockIdx.x * blockDim.x + threadIdx.x;
    if (i < n) o[i] = __float2half_rn(x[i]);
}

__global__ void bias_kernel(const float* __restrict__ size_in, const float* __restrict__ mask,
                            float* __restrict__ bias, int n) {
    int i = blockIdx.x * blockDim.x + threadIdx.x;
    if (i < n) {
        float s = size_in[i];
        s = (s < 0.5f) ? 1.0f : s;
        bias[i] = logf(s) + mask[i];
    }
}

// ============================ SIMT GEMM (Q-proj only) ============================
#define TBM 64
#define TBN 64
#define TBK 16
#define SPAD 4

__global__ void __launch_bounds__(256)
gemm_nt_kernel(const float* __restrict__ A, int lda,
               const float* __restrict__ B, int ldb,
               float* __restrict__ C, int ldc,
               int M, int N, int K, float alpha, const float* __restrict__ bias_n) {
    __shared__ __align__(16) float As[TBK][TBM + SPAD];
    __shared__ __align__(16) float Bs[TBK][TBN + SPAD];
    const int m0 = blockIdx.y * TBM;
    const int n0 = blockIdx.x * TBN;
    const int t  = threadIdx.x;
    const int tx = t & 15, ty = t >> 4;
    float acc[4][4] = {};
    for (int k0 = 0; k0 < K; k0 += TBK) {
        {
            int col = t & 15, rowb = t >> 4;
            #pragma unroll
            for (int i = 0; i < 4; i++) {
                int rr = rowb + i * 16;
                As[col][rr] = A[(size_t)(m0 + rr) * lda + k0 + col];
            }
        }
        {
            int col = t & 15, rowb = t >> 4;
            #pragma unroll
            for (int i = 0; i < 4; i++) {
                int nn = rowb + i * 16;
                Bs[col][nn] = B[(size_t)(n0 + nn) * ldb + k0 + col];
            }
        }
        __syncthreads();
        #pragma unroll
        for (int kk = 0; kk < TBK; kk++) {
            float4 av = *reinterpret_cast<const float4*>(&As[kk][ty * 4]);
            float4 bv = *reinterpret_cast<const float4*>(&Bs[kk][tx * 4]);
            float a[4] = {av.x, av.y, av.z, av.w};
            float b[4] = {bv.x, bv.y, bv.z, bv.w};
            #pragma unroll
            for (int i = 0; i < 4; i++)
                #pragma unroll
                for (int j = 0; j < 4; j++)
                    acc[i][j] += a[i] * b[j];
        }
        __syncthreads();
    }
    #pragma unroll
    for (int i = 0; i < 4; i++) {
        int gm = m0 + ty * 4 + i;
        #pragma unroll
        for (int j = 0; j < 4; j++) {
            int gn = n0 + tx * 4 + j;
            float v = alpha * acc[i][j];
            if (bias_n) v += bias_n[gn];
            C[(size_t)gm * ldc + gn] = v;
        }
    }
}

// ============================ launch ============================
extern "C" void kernel_launch(void* const* d_in, const int* in_sizes, int n_in,
                              void* d_out, int out_size) {
    const float* x     = (const float*)d_in[0];
    const float* sizei = (const float*)d_in[1];
    const float* amask = (const float*)d_in[2];
    const float* query = (const float*)d_in[3];
    const float* ln_q_w = (const float*)d_in[4];
    const float* ln_q_b = (const float*)d_in[5];
    const float* ln_k_w = (const float*)d_in[6];
    const float* ln_k_b = (const float*)d_in[7];
    const float* Wq = (const float*)d_in[8];
    const float* Wk = (const float*)d_in[9];
    const float* Wv = (const float*)d_in[10];
    const float* bq = (const float*)d_in[11];
    const float* bk = (const float*)d_in[12];
    const float* bv = (const float*)d_in[13];
    const float* Wo = (const float*)d_in[14];
    const float* bo = (const float*)d_in[15];
    float* out = (float*)d_out;

    __half *x16, *wk16, *wv16, *wo16, *kh16, *vh16, *qh16, *ao16;
    float *qln, *qh, *bias;
    cudaGetSymbolAddress((void**)&x16, g_x16);
    cudaGetSymbolAddress((void**)&wk16, g_wk16);
    cudaGetSymbolAddress((void**)&wv16, g_wv16);
    cudaGetSymbolAddress((void**)&wo16, g_wo16);
    cudaGetSymbolAddress((void**)&kh16, g_kh16);
    cudaGetSymbolAddress((void**)&vh16, g_vh16);
    cudaGetSymbolAddress((void**)&qh16, g_qh16);
    cudaGetSymbolAddress((void**)&ao16, g_ao16);
    cudaGetSymbolAddress((void**)&qln, g_qln);
    cudaGetSymbolAddress((void**)&qh, g_qh);
    cudaGetSymbolAddress((void**)&bias, g_bias);

    cudaFuncSetAttribute(kvfused_gemm, cudaFuncAttributeMaxDynamicSharedMemorySize, KVF_SMEM);
    cudaFuncSetAttribute(oproj_h,      cudaFuncAttributeMaxDynamicSharedMemorySize, OP_SMEM);
    cudaFuncSetAttribute(fa_kernel,    cudaFuncAttributeMaxDynamicSharedMemorySize, FA_SMEM);

    const float scale = 0.10206207261596575f;  // 1/sqrt(96)

    // launch order: index 3 (ncu-profiled) = kvfused_gemm
    ln_h_kernel<<<MROWS, 256>>>(x, ln_k_w, ln_k_b, x16, CTXD);                         // 0
    cvt_h_kernel<<<(DMODEL * CTXD + 255) / 256, 256>>>(Wk, wk16, DMODEL * CTXD);       // 1
    cvt_h_kernel<<<(DMODEL * CTXD + 255) / 256, 256>>>(Wv, wv16, DMODEL * CTXD);       // 2
    kvfused_gemm<<<dim3(DMODEL / 64, MROWS / 128), 256, KVF_SMEM>>>(                   // 3 (profiled)
        x16, wk16, wv16, bk, bv, kh16, vh16);
    ln_kernel<<<NQ, 256>>>(query, ln_q_w, ln_q_b, qln, DMODEL);                        // 4
    cvt_h_kernel<<<(DMODEL * DMODEL + 255) / 256, 256>>>(Wo, wo16, DMODEL * DMODEL);   // 5
    bias_kernel<<<(MROWS + 255) / 256, 256>>>(sizei, amask, bias, MROWS);              // 6
    gemm_nt_kernel<<<dim3(DMODEL / TBN, NQ / TBM), 256>>>(                             // 7
        qln, DMODEL, Wq, DMODEL, qh, DMODEL, NQ, DMODEL, DMODEL, 1.0f, bq);
    cvt_h_kernel<<<(NQ * DMODEL + 255) / 256, 256>>>(qh, qh16, NQ * DMODEL);           // 8

    fa_kernel<<<dim3(NQ / 128, NZ), 256, FA_SMEM>>>(                                   // 9
        qh16, kh16, vh16, bias, scale, ao16);

    oproj_h<<<dim3(DMODEL / 128, BATCH * NQ / 128), 256, OP_SMEM>>>(                   // 10
        ao16, wo16, bo, out);
}

// round 16
// speedup vs baseline: 2.4374x; 1.0881x over previous
#include <cuda_runtime.h>
#include <cuda_bf16.h>
#include <cuda_fp16.h>
#include <cstdint>

#define BATCH     32
#define SEQ       1024
#define CTXD      1024
#define DMODEL    768
#define NHEAD     8
#define HDIM      96
#define NQ        256
#define MROWS     (BATCH * SEQ)   // 32768
#define NZ        (BATCH * NHEAD) // 256

typedef __nv_bfloat16 bf16;

// ============================ device scratch ============================
__device__ __half g_x16[MROWS * CTXD];            // LN(x) fp16
__device__ __half g_wk16[DMODEL * CTXD];
__device__ __half g_wv16[DMODEL * CTXD];
__device__ __half g_wq16[DMODEL * DMODEL];
__device__ __half g_wo16[DMODEL * DMODEL];
__device__ __half g_kh16[MROWS * DMODEL];
__device__ __half g_vh16[MROWS * DMODEL];
__device__ __half g_qln16[NQ * DMODEL];           // LN(query) fp16
__device__ __half g_qh16[NQ * DMODEL];            // Q proj fp16
__device__ __half g_ao16[BATCH * NQ * DMODEL];    // attnout fp16
__device__ float g_bias[MROWS];

// ============================ asm helpers ============================
__device__ __forceinline__ uint32_t smem_u32(const void* p) {
    uint32_t a;
    asm("{ .reg .u64 t; cvta.to.shared.u64 t, %1; cvt.u32.u64 %0, t; }" : "=r"(a) : "l"(p));
    return a;
}
__device__ __forceinline__ void ldm_x4(uint32_t* r, uint32_t addr) {
    asm volatile("ldmatrix.sync.aligned.m8n8.x4.shared.b16 {%0,%1,%2,%3}, [%4];"
                 : "=r"(r[0]), "=r"(r[1]), "=r"(r[2]), "=r"(r[3]) : "r"(addr));
}
__device__ __forceinline__ void ldm_x4_t(uint32_t* r, uint32_t addr) {
    asm volatile("ldmatrix.sync.aligned.m8n8.x4.trans.shared.b16 {%0,%1,%2,%3}, [%4];"
                 : "=r"(r[0]), "=r"(r[1]), "=r"(r[2]), "=r"(r[3]) : "r"(addr));
}
__device__ __forceinline__ void mma16816h(float* c, const uint32_t* a, const uint32_t* b) {
    asm volatile("mma.sync.aligned.m16n8k16.row.col.f32.f16.f16.f32 "
                 "{%0,%1,%2,%3}, {%4,%5,%6,%7}, {%8,%9}, {%0,%1,%2,%3};"
                 : "+f"(c[0]), "+f"(c[1]), "+f"(c[2]), "+f"(c[3])
                 : "r"(a[0]), "r"(a[1]), "r"(a[2]), "r"(a[3]), "r"(b[0]), "r"(b[1]));
}
__device__ __forceinline__ void cp16(uint32_t dst, const void* src) {
    asm volatile("cp.async.cg.shared.global [%0], [%1], 16;" :: "r"(dst), "l"(src));
}
#define CP_COMMIT() asm volatile("cp.async.commit_group;")
#define CP_WAIT0()  asm volatile("cp.async.wait_group 0;")

__device__ __forceinline__ uint32_t packh2(float v0, float v1) {
    __half2 h = __floats2half2_rn(v0, v1);
    return *reinterpret_cast<uint32_t*>(&h);
}

#define LDS_K 72        // fp16 row stride (144B, odd 16B-granule count -> conflict-free)
#define ATILE 18432u    // 128 * 72 * 2
#define BTILE 9216u     // 64 * 72 * 2

// ============================ fused K+V fp16 GEMM (256 thr, 2 CTAs/SM) ============================
#define KVF_SMEM 73728

__global__ void __launch_bounds__(256, 2)
kvfused_gemm(const __half* __restrict__ A16,
             const __half* __restrict__ Bk16, const __half* __restrict__ Bv16,
             const float* __restrict__ bias_k, const float* __restrict__ bias_v,
             __half* __restrict__ Ck, __half* __restrict__ Cv) {
    extern __shared__ char smem[];
    const int tid  = threadIdx.x;
    const int wid  = tid >> 5;
    const int lane = tid & 31;
    const int grp  = wid >> 2;          // 0 = K, 1 = V
    const int wg   = wid & 3;
    const int m0 = blockIdx.y * 128;
    const int n0 = blockIdx.x * 64;
    const int wm = wg * 32;

    const uint32_t smBase = smem_u32(smem);
    const uint32_t aRow = (uint32_t)(wm + (lane & 15)) * LDS_K + (uint32_t)(lane >> 4) * 8u;
    const uint32_t bRow = (uint32_t)((lane & 7) + ((lane >> 4) * 8)) * LDS_K
                        + (uint32_t)((lane >> 3) & 1) * 8u;
    const uint32_t bOff = ATILE + (uint32_t)grp * BTILE;

    float acc[2][8][4];
    #pragma unroll
    for (int i = 0; i < 2; i++)
        #pragma unroll
        for (int j = 0; j < 8; j++)
            #pragma unroll
            for (int k = 0; k < 4; k++) acc[i][j][k] = 0.f;

    auto load_chunk = [&](int k0, int buf) {
        uint32_t base = smBase + (uint32_t)buf * 36864u;
        #pragma unroll
        for (int i = 0; i < 4; i++) {
            int idx = tid + i * 256;
            int row = idx >> 3, col = idx & 7;
            uint32_t so = ((uint32_t)row * LDS_K + (uint32_t)col * 8u) * 2u;
            cp16(base + so, A16 + (size_t)(m0 + row) * CTXD + k0 + col * 8);
        }
        #pragma unroll
        for (int i = 0; i < 2; i++) {
            int idx = tid + i * 256;
            int row = idx >> 3, col = idx & 7;
            uint32_t so = ((uint32_t)row * LDS_K + (uint32_t)col * 8u) * 2u;
            size_t gb = (size_t)(n0 + row) * CTXD + k0 + col * 8;
            cp16(base + ATILE + so,         Bk16 + gb);
            cp16(base + ATILE + BTILE + so, Bv16 + gb);
        }
    };

    load_chunk(0, 0);
    CP_COMMIT();

    for (int c = 0; c < CTXD / 64; c++) {
        CP_WAIT0();
        __syncthreads();
        if (c + 1 < CTXD / 64) { load_chunk((c + 1) << 6, (c + 1) & 1); CP_COMMIT(); }

        uint32_t base = smBase + (uint32_t)(c & 1) * 36864u;
        uint32_t bB = base + bOff;
        #pragma unroll
        for (int ks = 0; ks < 4; ks++) {
            const uint32_t kcol = (uint32_t)ks * 16u;
            uint32_t a[2][4], b[4][4];
            #pragma unroll
            for (int g = 0; g < 4; g++) {
                uint32_t off = (bRow + (uint32_t)g * 16u * LDS_K + kcol) * 2u;
                ldm_x4(b[g], bB + off);
            }
            #pragma unroll
            for (int mi = 0; mi < 2; mi++) {
                uint32_t off = (aRow + (uint32_t)mi * 16u * LDS_K + kcol) * 2u;
                ldm_x4(a[mi], base + off);
            }
            #pragma unroll
            for (int mi = 0; mi < 2; mi++)
                #pragma unroll
                for (int nj = 0; nj < 8; nj++)
                    mma16816h(acc[mi][nj], a[mi], &b[nj >> 1][(nj & 1) * 2]);
        }
        __syncthreads();
    }

    const float* bias_n = grp ? bias_v : bias_k;
    __half* C16 = grp ? Cv : Ck;
    #pragma unroll
    for (int mi = 0; mi < 2; mi++) {
        int gm = m0 + wm + mi * 16 + (lane >> 2);
        #pragma unroll
        for (int nj = 0; nj < 8; nj++) {
            int gn = n0 + nj * 8 + (lane & 3) * 2;
            float b0 = bias_n[gn], b1 = bias_n[gn + 1];
            uint32_t p0 = packh2(acc[mi][nj][0] + b0, acc[mi][nj][1] + b1);
            uint32_t p1 = packh2(acc[mi][nj][2] + b0, acc[mi][nj][3] + b1);
            *reinterpret_cast<uint32_t*>(C16 + (size_t)gm * DMODEL + gn)       = p0;
            *reinterpret_cast<uint32_t*>(C16 + (size_t)(gm + 8) * DMODEL + gn) = p1;
        }
    }
}

// ============================ plain fp16 NT GEMM (O-proj fp32 out / Q-proj fp16 out) ============================
#define OP_SMEM 73728

template<int EPI>  // 0: fp32 out, 1: fp16 out
__device__ __forceinline__ void gemm_h_dev(
    char* smem, const __half* __restrict__ A16, const __half* __restrict__ B16,
    int K, int m0, int n0,
    const float* __restrict__ bias_n, float* __restrict__ Cf, __half* __restrict__ Ch) {
    const int tid  = threadIdx.x;
    const int wid  = tid >> 5;
    const int lane = tid & 31;
    const int wm = (wid & 3) * 32;
    const int wn = (wid >> 2) * 64;

    const uint32_t smBase = smem_u32(smem);
    const uint32_t aRow = (uint32_t)(wm + (lane & 15)) * LDS_K + (uint32_t)(lane >> 4) * 8u;
    const uint32_t bRow = (uint32_t)(wn + (lane & 7) + ((lane >> 4) * 8)) * LDS_K
                        + (uint32_t)((lane >> 3) & 1) * 8u;

    float acc[2][8][4];
    #pragma unroll
    for (int i = 0; i < 2; i++)
        #pragma unroll
        for (int j = 0; j < 8; j++)
            #pragma unroll
            for (int k = 0; k < 4; k++) acc[i][j][k] = 0.f;

    auto load_chunk = [&](int k0, int buf) {
        uint32_t base = smBase + (uint32_t)buf * 36864u;
        #pragma unroll
        for (int i = 0; i < 4; i++) {
            int idx = tid + i * 256;
            int row = idx >> 3, col = idx & 7;
            uint32_t so = ((uint32_t)row * LDS_K + (uint32_t)col * 8u) * 2u;
            cp16(base + so,         A16 + (size_t)(m0 + row) * K + k0 + col * 8);
            cp16(base + ATILE + so, B16 + (size_t)(n0 + row) * K + k0 + col * 8);
        }
    };

    load_chunk(0, 0);
    CP_COMMIT();

    for (int c = 0; c < K / 64; c++) {
        CP_WAIT0();
        __syncthreads();
        if (c + 1 < K / 64) { load_chunk((c + 1) << 6, (c + 1) & 1); CP_COMMIT(); }

        uint32_t base = smBase + (uint32_t)(c & 1) * 36864u;
        uint32_t bB = base + ATILE;
        #pragma unroll
        for (int ks = 0; ks < 4; ks++) {
            const uint32_t kcol = (uint32_t)ks * 16u;
            uint32_t a[2][4], b[4][4];
            #pragma unroll
            for (int g = 0; g < 4; g++) {
                uint32_t off = (bRow + (uint32_t)g * 16u * LDS_K + kcol) * 2u;
                ldm_x4(b[g], bB + off);
            }
            #pragma unroll
            for (int mi = 0; mi < 2; mi++) {
                uint32_t off = (aRow + (uint32_t)mi * 16u * LDS_K + kcol) * 2u;
                ldm_x4(a[mi], base + off);
            }
            #pragma unroll
            for (int mi = 0; mi < 2; mi++)
                #pragma unroll
                for (int nj = 0; nj < 8; nj++)
                    mma16816h(acc[mi][nj], a[mi], &b[nj >> 1][(nj & 1) * 2]);
        }
        __syncthreads();
    }

    #pragma unroll
    for (int mi = 0; mi < 2; mi++) {
        int gm = m0 + wm + mi * 16 + (lane >> 2);
        #pragma unroll
        for (int nj = 0; nj < 8; nj++) {
            int gn = n0 + wn + nj * 8 + (lane & 3) * 2;
            float b0 = bias_n[gn], b1 = bias_n[gn + 1];
            float v00 = acc[mi][nj][0] + b0, v01 = acc[mi][nj][1] + b1;
            float v10 = acc[mi][nj][2] + b0, v11 = acc[mi][nj][3] + b1;
            if (EPI == 0) {
                *reinterpret_cast<float2*>(Cf + (size_t)gm * DMODEL + gn) = make_float2(v00, v01);
                *reinterpret_cast<float2*>(Cf + (size_t)(gm + 8) * DMODEL + gn) = make_float2(v10, v11);
            } else {
                *reinterpret_cast<uint32_t*>(Ch + (size_t)gm * DMODEL + gn)       = packh2(v00, v01);
                *reinterpret_cast<uint32_t*>(Ch + (size_t)(gm + 8) * DMODEL + gn) = packh2(v10, v11);
            }
        }
    }
}

__global__ void __launch_bounds__(256, 2)
oproj_h(const __half* __restrict__ A16, const __half* __restrict__ B16,
        const float* __restrict__ bias_n, float* __restrict__ C) {
    extern __shared__ char smem[];
    gemm_h_dev<0>(smem, A16, B16, DMODEL, blockIdx.y * 128, blockIdx.x * 128,
                  bias_n, C, nullptr);
}

__global__ void __launch_bounds__(256, 2)
qproj_h(const __half* __restrict__ A16, const __half* __restrict__ B16,
        const float* __restrict__ bias_n, __half* __restrict__ C) {
    extern __shared__ char smem[];
    gemm_h_dev<1>(smem, A16, B16, DMODEL, blockIdx.y * 128, blockIdx.x * 128,
                  bias_n, nullptr, C);
}

// ============================ fused flash attention (all fp16, 2 CTAs/SM) ============================
#define FA_SMEM 80384
#define FA_LDS 104

__global__ void __launch_bounds__(256, 2)
fa_kernel(const __half* __restrict__ Q16,
          const __half* __restrict__ K16, const __half* __restrict__ V16,
          const float* __restrict__ biasBL, float scale,
          __half* __restrict__ O16) {
    extern __shared__ char smem[];
    const int tid = threadIdx.x;
    const int wid = tid >> 5, lane = tid & 31;
    const int z = blockIdx.y;
    const int b = z >> 3, h = z & 7;
    const int q0 = blockIdx.x * 128;
    const size_t bSeq = (size_t)b * SEQ;
    const int hOff = h * HDIM;

    const uint32_t smBase = smem_u32(smem);
    const uint32_t KBASE = 26624u, VBASE = 53248u, BBASE = 79872u;

    for (int i = tid; i < 1536; i += 256) {
        int row = i / 12, col = i % 12;
        uint32_t so = ((uint32_t)row * FA_LDS + (uint32_t)col * 8u) * 2u;
        size_t go = (size_t)(q0 + row) * DMODEL + hOff + col * 8;
        cp16(smBase + so, Q16 + go);
    }
    CP_COMMIT();

    auto load_kv = [&](int c, int buf) {
        int l0 = c * 64;
        uint32_t kB = smBase + KBASE + (uint32_t)buf * 13312u;
        uint32_t vB = smBase + VBASE + (uint32_t)buf * 13312u;
        for (int i = tid; i < 768; i += 256) {
            int row = i / 12, col = i % 12;
            uint32_t so = ((uint32_t)row * FA_LDS + (uint32_t)col * 8u) * 2u;
            size_t go = (bSeq + l0 + row) * DMODEL + hOff + col * 8;
            cp16(kB + so, K16 + go);
            cp16(vB + so, V16 + go);
        }
        if (tid < 16)
            cp16(smBase + BBASE + (uint32_t)buf * 256u + (uint32_t)tid * 16u,
                 biasBL + bSeq + l0 + tid * 4);
    };
    load_kv(0, 0);
    CP_COMMIT();

    const uint32_t aRow = (uint32_t)(wid * 16 + (lane & 15)) * FA_LDS + (uint32_t)(lane >> 4) * 8u;
    const uint32_t bRow = (uint32_t)((lane & 7) + ((lane >> 4) * 8)) * FA_LDS
                        + (uint32_t)((lane >> 3) & 1) * 8u;
    const uint32_t vLaneRow = (uint32_t)((lane & 7) + ((lane >> 3) & 1) * 8);
    const uint32_t vLaneCol = (uint32_t)(lane >> 4) * 8u;

    float oacc[12][4];
    #pragma unroll
    for (int j = 0; j < 12; j++)
        #pragma unroll
        for (int k = 0; k < 4; k++) oacc[j][k] = 0.f;
    float m0 = -1e30f, m1 = -1e30f, l0s = 0.f, l1s = 0.f;

    for (int c = 0; c < 16; c++) {
        CP_WAIT0();
        __syncthreads();
        if (c + 1 < 16) { load_kv(c + 1, (c + 1) & 1); CP_COMMIT(); }

        const uint32_t kB = smBase + KBASE + (uint32_t)(c & 1) * 13312u;
        const uint32_t vB = smBase + VBASE + (uint32_t)(c & 1) * 13312u;
        const float* sbias = reinterpret_cast<const float*>(smem + BBASE + (c & 1) * 256);

        float s[8][4];
        #pragma unroll
        for (int j = 0; j < 8; j++)
            #pragma unroll
            for (int k = 0; k < 4; k++) s[j][k] = 0.f;

        #pragma unroll
        for (int ks = 0; ks < 6; ks++) {
            const uint32_t kcol = (uint32_t)ks * 16u;
            uint32_t qF[4], kk[4];
            ldm_x4(qF, smBase + (aRow + kcol) * 2u);
            #pragma unroll
            for (int g = 0; g < 4; g++) {
                uint32_t off = (bRow + (uint32_t)g * 16u * FA_LDS + kcol) * 2u;
                ldm_x4(kk, kB + off);
                mma16816h(s[2 * g],     qF, &kk[0]);
                mma16816h(s[2 * g + 1], qF, &kk[2]);
            }
        }

        float mx0 = -1e30f, mx1 = -1e30f;
        #pragma unroll
        for (int nj = 0; nj < 8; nj++) {
            int cidx = nj * 8 + (lane & 3) * 2;
            float bj0 = sbias[cidx], bj1 = sbias[cidx + 1];
            s[nj][0] = s[nj][0] * scale + bj0;
            s[nj][1] = s[nj][1] * scale + bj1;
            s[nj][2] = s[nj][2] * scale + bj0;
            s[nj][3] = s[nj][3] * scale + bj1;
            mx0 = fmaxf(mx0, fmaxf(s[nj][0], s[nj][1]));
            mx1 = fmaxf(mx1, fmaxf(s[nj][2], s[nj][3]));
        }
        #pragma unroll
        for (int o = 1; o <= 2; o <<= 1) {
            mx0 = fmaxf(mx0, __shfl_xor_sync(0xffffffffu, mx0, o));
            mx1 = fmaxf(mx1, __shfl_xor_sync(0xffffffffu, mx1, o));
        }
        float mn0 = fmaxf(m0, mx0), mn1 = fmaxf(m1, mx1);
        float cor0 = __expf(m0 - mn0), cor1 = __expf(m1 - mn1);
        l0s *= cor0; l1s *= cor1;
        #pragma unroll
        for (int j = 0; j < 12; j++) {
            oacc[j][0] *= cor0; oacc[j][1] *= cor0;
            oacc[j][2] *= cor1; oacc[j][3] *= cor1;
        }
        m0 = mn0; m1 = mn1;

        float rs0 = 0.f, rs1 = 0.f;
        uint32_t pF[4][4];
        #pragma unroll
        for (int t = 0; t < 4; t++) {
            float p00 = __expf(s[2 * t][0] - mn0);
            float p01 = __expf(s[2 * t][1] - mn0);
            float p10 = __expf(s[2 * t][2] - mn1);
            float p11 = __expf(s[2 * t][3] - mn1);
            float p20 = __expf(s[2 * t + 1][0] - mn0);
            float p21 = __expf(s[2 * t + 1][1] - mn0);
            float p30 = __expf(s[2 * t + 1][2] - mn1);
            float p31 = __expf(s[2 * t + 1][3] - mn1);
            rs0 += p00 + p01 + p20 + p21;
            rs1 += p10 + p11 + p30 + p31;
            pF[t][0] = packh2(p00, p01);
            pF[t][1] = packh2(p10, p11);
            pF[t][2] = packh2(p20, p21);
            pF[t][3] = packh2(p30, p31);
        }
        #pragma unroll
        for (int o = 1; o <= 2; o <<= 1) {
            rs0 += __shfl_xor_sync(0xffffffffu, rs0, o);
            rs1 += __shfl_xor_sync(0xffffffffu, rs1, o);
        }
        l0s += rs0; l1s += rs1;

        #pragma unroll
        for (int t = 0; t < 4; t++) {
            uint32_t vv[4];
            #pragma unroll
            for (int g = 0; g < 6; g++) {
                uint32_t off = (((uint32_t)t * 16u + vLaneRow) * FA_LDS
                                + (uint32_t)g * 16u + vLaneCol) * 2u;
                ldm_x4_t(vv, vB + off);
                mma16816h(oacc[2 * g],     pF[t], &vv[0]);
                mma16816h(oacc[2 * g + 1], pF[t], &vv[2]);
            }
        }
    }

    float inv0 = 1.0f / l0s, inv1 = 1.0f / l1s;
    const int q = q0 + wid * 16 + (lane >> 2);
    #pragma unroll
    for (int j = 0; j < 12; j++) {
        int n = j * 8 + (lane & 3) * 2;
        size_t o0 = ((size_t)(b * NQ + q)) * DMODEL + hOff + n;
        size_t o1 = o0 + (size_t)8 * DMODEL;
        *reinterpret_cast<uint32_t*>(O16 + o0) = packh2(oacc[j][0] * inv0, oacc[j][1] * inv0);
        *reinterpret_cast<uint32_t*>(O16 + o1) = packh2(oacc[j][2] * inv1, oacc[j][3] * inv1);
    }
}

// ============================ LayerNorm / misc ============================
__device__ __forceinline__ void ln_stats(const float* __restrict__ xr, int ncols,
                                         float& mu, float& rs, float* s1, float* s2) {
    float sum = 0.f, sumsq = 0.f;
    for (int i = threadIdx.x; i < ncols; i += blockDim.x) {
        float v = xr[i];
        sum += v; sumsq += v * v;
    }
    #pragma unroll
    for (int o = 16; o; o >>= 1) {
        sum   += __shfl_xor_sync(0xffffffffu, sum, o);
        sumsq += __shfl_xor_sync(0xffffffffu, sumsq, o);
    }
    int wid = threadIdx.x >> 5, lid = threadIdx.x & 31;
    if (lid == 0) { s1[wid] = sum; s2[wid] = sumsq; }
    __syncthreads();
    if (threadIdx.x < 32) {
        int nw = blockDim.x >> 5;
        float a = (lid < nw) ? s1[lid] : 0.f;
        float c = (lid < nw) ? s2[lid] : 0.f;
        #pragma unroll
        for (int o = 16; o; o >>= 1) {
            a += __shfl_xor_sync(0xffffffffu, a, o);
            c += __shfl_xor_sync(0xffffffffu, c, o);
        }
        if (lid == 0) { s1[0] = a; s2[0] = c; }
    }
    __syncthreads();
    float inv_n = 1.0f / (float)ncols;
    mu = s1[0] * inv_n;
    float var = s2[0] * inv_n - mu * mu;
    rs = rsqrtf(var + 1e-5f);
}

__global__ void ln_h_kernel(const float* __restrict__ x, const float* __restrict__ w,
                            const float* __restrict__ b,
                            __half* __restrict__ o16, int ncols) {
    __shared__ float s1[32], s2[32];
    const size_t row = blockIdx.x;
    const float* xr = x + row * (size_t)ncols;
    float mu, rs;
    ln_stats(xr, ncols, mu, rs, s1, s2);
    __half* orow = o16 + row * (size_t)ncols;
    for (int i = threadIdx.x; i < ncols; i += blockDim.x) {
        float y = (xr[i] - mu) * rs * w[i] + b[i];
        orow[i] = __float2half_rn(y);
    }
}

__global__ void cvt_h_kernel(const float* __restrict__ x, __half* __restrict__ o, int n) {
    int i = blockIdx.x * blockDim.x + threadIdx.x;
    if (i < n) o[i] = __float2half_rn(x[i]);
}

__global__ void bias_kernel(const float* __restrict__ size_in, const float* __restrict__ mask,
                            float* __restrict__ bias, int n) {
    int i = blockIdx.x * blockDim.x + threadIdx.x;
    if (i < n) {
        float s = size_in[i];
        s = (s < 0.5f) ? 1.0f : s;
        bias[i] = logf(s) + mask[i];
    }
}

// ============================ launch ============================
extern "C" void kernel_launch(void* const* d_in, const int* in_sizes, int n_in,
                              void* d_out, int out_size) {
    const float* x     = (const float*)d_in[0];
    const float* sizei = (const float*)d_in[1];
    const float* amask = (const float*)d_in[2];
    const float* query = (const float*)d_in[3];
    const float* ln_q_w = (const float*)d_in[4];
    const float* ln_q_b = (const float*)d_in[5];
    const float* ln_k_w = (const float*)d_in[6];
    const float* ln_k_b = (const float*)d_in[7];
    const float* Wq = (const float*)d_in[8];
    const float* Wk = (const float*)d_in[9];
    const float* Wv = (const float*)d_in[10];
    const float* bq = (const float*)d_in[11];
    const float* bk = (const float*)d_in[12];
    const float* bv = (const float*)d_in[13];
    const float* Wo = (const float*)d_in[14];
    const float* bo = (const float*)d_in[15];
    float* out = (float*)d_out;

    __half *x16, *wk16, *wv16, *wq16, *wo16, *kh16, *vh16, *qln16, *qh16, *ao16;
    float *bias;
    cudaGetSymbolAddress((void**)&x16, g_x16);
    cudaGetSymbolAddress((void**)&wk16, g_wk16);
    cudaGetSymbolAddress((void**)&wv16, g_wv16);
    cudaGetSymbolAddress((void**)&wq16, g_wq16);
    cudaGetSymbolAddress((void**)&wo16, g_wo16);
    cudaGetSymbolAddress((void**)&kh16, g_kh16);
    cudaGetSymbolAddress((void**)&vh16, g_vh16);
    cudaGetSymbolAddress((void**)&qln16, g_qln16);
    cudaGetSymbolAddress((void**)&qh16, g_qh16);
    cudaGetSymbolAddress((void**)&ao16, g_ao16);
    cudaGetSymbolAddress((void**)&bias, g_bias);

    cudaFuncSetAttribute(kvfused_gemm, cudaFuncAttributeMaxDynamicSharedMemorySize, KVF_SMEM);
    cudaFuncSetAttribute(oproj_h,      cudaFuncAttributeMaxDynamicSharedMemorySize, OP_SMEM);
    cudaFuncSetAttribute(qproj_h,      cudaFuncAttributeMaxDynamicSharedMemorySize, OP_SMEM);
    cudaFuncSetAttribute(fa_kernel,    cudaFuncAttributeMaxDynamicSharedMemorySize, FA_SMEM);

    const float scale = 0.10206207261596575f;  // 1/sqrt(96)

    // launch order: index 3 (ncu-profiled) = kvfused_gemm
    ln_h_kernel<<<MROWS, 256>>>(x, ln_k_w, ln_k_b, x16, CTXD);                         // 0
    cvt_h_kernel<<<(DMODEL * CTXD + 255) / 256, 256>>>(Wk, wk16, DMODEL * CTXD);       // 1
    cvt_h_kernel<<<(DMODEL * CTXD + 255) / 256, 256>>>(Wv, wv16, DMODEL * CTXD);       // 2
    kvfused_gemm<<<dim3(DMODEL / 64, MROWS / 128), 256, KVF_SMEM>>>(                   // 3 (profiled)
        x16, wk16, wv16, bk, bv, kh16, vh16);
    ln_h_kernel<<<NQ, 256>>>(query, ln_q_w, ln_q_b, qln16, DMODEL);                    // 4
    cvt_h_kernel<<<(DMODEL * DMODEL + 255) / 256, 256>>>(Wq, wq16, DMODEL * DMODEL);   // 5
    cvt_h_kernel<<<(DMODEL * DMODEL + 255) / 256, 256>>>(Wo, wo16, DMODEL * DMODEL);   // 6
    bias_kernel<<<(MROWS + 255) / 256, 256>>>(sizei, amask, bias, MROWS);              // 7
    qproj_h<<<dim3(DMODEL / 128, NQ / 128), 256, OP_SMEM>>>(qln16, wq16, bq, qh16);    // 8

    fa_kernel<<<dim3(NQ / 128, NZ), 256, FA_SMEM>>>(                                   // 9
        qh16, kh16, vh16, bias, scale, ao16);

    oproj_h<<<dim3(DMODEL / 128, BATCH * NQ / 128), 256, OP_SMEM>>>(                   // 10
        ao16, wo16, bo, out);
}

// round 17
// speedup vs baseline: 2.4540x; 1.0068x over previous
#include <cuda_runtime.h>
#include <cuda_bf16.h>
#include <cuda_fp16.h>
#include <cstdint>

#define BATCH     32
#define SEQ       1024
#define CTXD      1024
#define DMODEL    768
#define NHEAD     8
#define HDIM      96
#define NQ        256
#define MROWS     (BATCH * SEQ)   // 32768
#define NZ        (BATCH * NHEAD) // 256

typedef __nv_bfloat16 bf16;

// ============================ device scratch ============================
__device__ __half g_x16[MROWS * CTXD];            // LN(x) fp16
__device__ __half g_wk16[DMODEL * CTXD];
__device__ __half g_wv16[DMODEL * CTXD];
__device__ __half g_wq16[DMODEL * DMODEL];
__device__ __half g_wo16[DMODEL * DMODEL];
__device__ __half g_kh16[MROWS * DMODEL];
__device__ __half g_vh16[MROWS * DMODEL];
__device__ __half g_qln16[NQ * DMODEL];           // LN(query) fp16
__device__ __half g_qh16[NQ * DMODEL];            // Q proj fp16
__device__ __half g_ao16[BATCH * NQ * DMODEL];    // attnout fp16
__device__ float g_bias[MROWS];

// ============================ asm helpers ============================
__device__ __forceinline__ uint32_t smem_u32(const void* p) {
    uint32_t a;
    asm("{ .reg .u64 t; cvta.to.shared.u64 t, %1; cvt.u32.u64 %0, t; }" : "=r"(a) : "l"(p));
    return a;
}
__device__ __forceinline__ void ldm_x4(uint32_t* r, uint32_t addr) {
    asm volatile("ldmatrix.sync.aligned.m8n8.x4.shared.b16 {%0,%1,%2,%3}, [%4];"
                 : "=r"(r[0]), "=r"(r[1]), "=r"(r[2]), "=r"(r[3]) : "r"(addr));
}
__device__ __forceinline__ void ldm_x4_t(uint32_t* r, uint32_t addr) {
    asm volatile("ldmatrix.sync.aligned.m8n8.x4.trans.shared.b16 {%0,%1,%2,%3}, [%4];"
                 : "=r"(r[0]), "=r"(r[1]), "=r"(r[2]), "=r"(r[3]) : "r"(addr));
}
__device__ __forceinline__ void mma16816h(float* c, const uint32_t* a, const uint32_t* b) {
    asm volatile("mma.sync.aligned.m16n8k16.row.col.f32.f16.f16.f32 "
                 "{%0,%1,%2,%3}, {%4,%5,%6,%7}, {%8,%9}, {%0,%1,%2,%3};"
                 : "+f"(c[0]), "+f"(c[1]), "+f"(c[2]), "+f"(c[3])
                 : "r"(a[0]), "r"(a[1]), "r"(a[2]), "r"(a[3]), "r"(b[0]), "r"(b[1]));
}
__device__ __forceinline__ void cp16(uint32_t dst, const void* src) {
    asm volatile("cp.async.cg.shared.global [%0], [%1], 16;" :: "r"(dst), "l"(src));
}
#define CP_COMMIT() asm volatile("cp.async.commit_group;")
#define CP_WAIT0()  asm volatile("cp.async.wait_group 0;")

__device__ __forceinline__ uint32_t packh2(float v0, float v1) {
    __half2 h = __floats2half2_rn(v0, v1);
    return *reinterpret_cast<uint32_t*>(&h);
}

#define LDS_K 72        // fp16 row stride (144B, odd 16B-granule count -> conflict-free)
#define ATILE 18432u    // 128 * 72 * 2
#define BTILE 9216u     // 64 * 72 * 2

// ============================ fused K+V fp16 GEMM (256 thr, 2 CTAs/SM) ============================
// Single barrier per chunk: the top sync (after CP_WAIT0, before the prefetch
// that would overwrite the buffer read last iteration) is sufficient.
#define KVF_SMEM 73728

__global__ void __launch_bounds__(256, 2)
kvfused_gemm(const __half* __restrict__ A16,
             const __half* __restrict__ Bk16, const __half* __restrict__ Bv16,
             const float* __restrict__ bias_k, const float* __restrict__ bias_v,
             __half* __restrict__ Ck, __half* __restrict__ Cv) {
    extern __shared__ char smem[];
    const int tid  = threadIdx.x;
    const int wid  = tid >> 5;
    const int lane = tid & 31;
    const int grp  = wid >> 2;          // 0 = K, 1 = V
    const int wg   = wid & 3;
    const int m0 = blockIdx.y * 128;
    const int n0 = blockIdx.x * 64;
    const int wm = wg * 32;

    const uint32_t smBase = smem_u32(smem);
    const uint32_t aRow = (uint32_t)(wm + (lane & 15)) * LDS_K + (uint32_t)(lane >> 4) * 8u;
    const uint32_t bRow = (uint32_t)((lane & 7) + ((lane >> 4) * 8)) * LDS_K
                        + (uint32_t)((lane >> 3) & 1) * 8u;
    const uint32_t bOff = ATILE + (uint32_t)grp * BTILE;

    float acc[2][8][4];
    #pragma unroll
    for (int i = 0; i < 2; i++)
        #pragma unroll
        for (int j = 0; j < 8; j++)
            #pragma unroll
            for (int k = 0; k < 4; k++) acc[i][j][k] = 0.f;

    auto load_chunk = [&](int k0, int buf) {
        uint32_t base = smBase + (uint32_t)buf * 36864u;
        #pragma unroll
        for (int i = 0; i < 4; i++) {
            int idx = tid + i * 256;
            int row = idx >> 3, col = idx & 7;
            uint32_t so = ((uint32_t)row * LDS_K + (uint32_t)col * 8u) * 2u;
            cp16(base + so, A16 + (size_t)(m0 + row) * CTXD + k0 + col * 8);
        }
        #pragma unroll
        for (int i = 0; i < 2; i++) {
            int idx = tid + i * 256;
            int row = idx >> 3, col = idx & 7;
            uint32_t so = ((uint32_t)row * LDS_K + (uint32_t)col * 8u) * 2u;
            size_t gb = (size_t)(n0 + row) * CTXD + k0 + col * 8;
            cp16(base + ATILE + so,         Bk16 + gb);
            cp16(base + ATILE + BTILE + so, Bv16 + gb);
        }
    };

    load_chunk(0, 0);
    CP_COMMIT();

    for (int c = 0; c < CTXD / 64; c++) {
        CP_WAIT0();
        __syncthreads();   // data ready + all warps done reading the buffer we overwrite next
        if (c + 1 < CTXD / 64) { load_chunk((c + 1) << 6, (c + 1) & 1); CP_COMMIT(); }

        uint32_t base = smBase + (uint32_t)(c & 1) * 36864u;
        uint32_t bB = base + bOff;
        #pragma unroll
        for (int ks = 0; ks < 4; ks++) {
            const uint32_t kcol = (uint32_t)ks * 16u;
            uint32_t a[2][4], b[4][4];
            #pragma unroll
            for (int g = 0; g < 4; g++) {
                uint32_t off = (bRow + (uint32_t)g * 16u * LDS_K + kcol) * 2u;
                ldm_x4(b[g], bB + off);
            }
            #pragma unroll
            for (int mi = 0; mi < 2; mi++) {
                uint32_t off = (aRow + (uint32_t)mi * 16u * LDS_K + kcol) * 2u;
                ldm_x4(a[mi], base + off);
            }
            #pragma unroll
            for (int mi = 0; mi < 2; mi++)
                #pragma unroll
                for (int nj = 0; nj < 8; nj++)
                    mma16816h(acc[mi][nj], a[mi], &b[nj >> 1][(nj & 1) * 2]);
        }
        // no bottom barrier: next overwrite of this buffer is gated by next top sync
    }

    const float* bias_n = grp ? bias_v : bias_k;
    __half* C16 = grp ? Cv : Ck;
    #pragma unroll
    for (int mi = 0; mi < 2; mi++) {
        int gm = m0 + wm + mi * 16 + (lane >> 2);
        #pragma unroll
        for (int nj = 0; nj < 8; nj++) {
            int gn = n0 + nj * 8 + (lane & 3) * 2;
            float b0 = bias_n[gn], b1 = bias_n[gn + 1];
            uint32_t p0 = packh2(acc[mi][nj][0] + b0, acc[mi][nj][1] + b1);
            uint32_t p1 = packh2(acc[mi][nj][2] + b0, acc[mi][nj][3] + b1);
            *reinterpret_cast<uint32_t*>(C16 + (size_t)gm * DMODEL + gn)       = p0;
            *reinterpret_cast<uint32_t*>(C16 + (size_t)(gm + 8) * DMODEL + gn) = p1;
        }
    }
}

// ============================ plain fp16 NT GEMM (O-proj fp32 out / Q-proj fp16 out) ============================
#define OP_SMEM 73728

template<int EPI>  // 0: fp32 out, 1: fp16 out
__device__ __forceinline__ void gemm_h_dev(
    char* smem, const __half* __restrict__ A16, const __half* __restrict__ B16,
    int K, int m0, int n0,
    const float* __restrict__ bias_n, float* __restrict__ Cf, __half* __restrict__ Ch) {
    const int tid  = threadIdx.x;
    const int wid  = tid >> 5;
    const int lane = tid & 31;
    const int wm = (wid & 3) * 32;
    const int wn = (wid >> 2) * 64;

    const uint32_t smBase = smem_u32(smem);
    const uint32_t aRow = (uint32_t)(wm + (lane & 15)) * LDS_K + (uint32_t)(lane >> 4) * 8u;
    const uint32_t bRow = (uint32_t)(wn + (lane & 7) + ((lane >> 4) * 8)) * LDS_K
                        + (uint32_t)((lane >> 3) & 1) * 8u;

    float acc[2][8][4];
    #pragma unroll
    for (int i = 0; i < 2; i++)
        #pragma unroll
        for (int j = 0; j < 8; j++)
            #pragma unroll
            for (int k = 0; k < 4; k++) acc[i][j][k] = 0.f;

    auto load_chunk = [&](int k0, int buf) {
        uint32_t base = smBase + (uint32_t)buf * 36864u;
        #pragma unroll
        for (int i = 0; i < 4; i++) {
            int idx = tid + i * 256;
            int row = idx >> 3, col = idx & 7;
            uint32_t so = ((uint32_t)row * LDS_K + (uint32_t)col * 8u) * 2u;
            cp16(base + so,         A16 + (size_t)(m0 + row) * K + k0 + col * 8);
            cp16(base + ATILE + so, B16 + (size_t)(n0 + row) * K + k0 + col * 8);
        }
    };

    load_chunk(0, 0);
    CP_COMMIT();

    for (int c = 0; c < K / 64; c++) {
        CP_WAIT0();
        __syncthreads();
        if (c + 1 < K / 64) { load_chunk((c + 1) << 6, (c + 1) & 1); CP_COMMIT(); }

        uint32_t base = smBase + (uint32_t)(c & 1) * 36864u;
        uint32_t bB = base + ATILE;
        #pragma unroll
        for (int ks = 0; ks < 4; ks++) {
            const uint32_t kcol = (uint32_t)ks * 16u;
            uint32_t a[2][4], b[4][4];
            #pragma unroll
            for (int g = 0; g < 4; g++) {
                uint32_t off = (bRow + (uint32_t)g * 16u * LDS_K + kcol) * 2u;
                ldm_x4(b[g], bB + off);
            }
            #pragma unroll
            for (int mi = 0; mi < 2; mi++) {
                uint32_t off = (aRow + (uint32_t)mi * 16u * LDS_K + kcol) * 2u;
                ldm_x4(a[mi], base + off);
            }
            #pragma unroll
            for (int mi = 0; mi < 2; mi++)
                #pragma unroll
                for (int nj = 0; nj < 8; nj++)
                    mma16816h(acc[mi][nj], a[mi], &b[nj >> 1][(nj & 1) * 2]);
        }
        // no bottom barrier (see kvfused_gemm)
    }

    #pragma unroll
    for (int mi = 0; mi < 2; mi++) {
        int gm = m0 + wm + mi * 16 + (lane >> 2);
        #pragma unroll
        for (int nj = 0; nj < 8; nj++) {
            int gn = n0 + wn + nj * 8 + (lane & 3) * 2;
            float b0 = bias_n[gn], b1 = bias_n[gn + 1];
            float v00 = acc[mi][nj][0] + b0, v01 = acc[mi][nj][1] + b1;
            float v10 = acc[mi][nj][2] + b0, v11 = acc[mi][nj][3] + b1;
            if (EPI == 0) {
                *reinterpret_cast<float2*>(Cf + (size_t)gm * DMODEL + gn) = make_float2(v00, v01);
                *reinterpret_cast<float2*>(Cf + (size_t)(gm + 8) * DMODEL + gn) = make_float2(v10, v11);
            } else {
                *reinterpret_cast<uint32_t*>(Ch + (size_t)gm * DMODEL + gn)       = packh2(v00, v01);
                *reinterpret_cast<uint32_t*>(Ch + (size_t)(gm + 8) * DMODEL + gn) = packh2(v10, v11);
            }
        }
    }
}

__global__ void __launch_bounds__(256, 2)
oproj_h(const __half* __restrict__ A16, const __half* __restrict__ B16,
        const float* __restrict__ bias_n, float* __restrict__ C) {
    extern __shared__ char smem[];
    gemm_h_dev<0>(smem, A16, B16, DMODEL, blockIdx.y * 128, blockIdx.x * 128,
                  bias_n, C, nullptr);
}

__global__ void __launch_bounds__(256, 2)
qproj_h(const __half* __restrict__ A16, const __half* __restrict__ B16,
        const float* __restrict__ bias_n, __half* __restrict__ C) {
    extern __shared__ char smem[];
    gemm_h_dev<1>(smem, A16, B16, DMODEL, blockIdx.y * 128, blockIdx.x * 128,
                  bias_n, nullptr, C);
}

// ============================ fused flash attention (all fp16, 2 CTAs/SM) ============================
#define FA_SMEM 80384
#define FA_LDS 104

__global__ void __launch_bounds__(256, 2)
fa_kernel(const __half* __restrict__ Q16,
          const __half* __restrict__ K16, const __half* __restrict__ V16,
          const float* __restrict__ biasBL, float scale,
          __half* __restrict__ O16) {
    extern __shared__ char smem[];
    const int tid = threadIdx.x;
    const int wid = tid >> 5, lane = tid & 31;
    const int z = blockIdx.y;
    const int b = z >> 3, h = z & 7;
    const int q0 = blockIdx.x * 128;
    const size_t bSeq = (size_t)b * SEQ;
    const int hOff = h * HDIM;

    const uint32_t smBase = smem_u32(smem);
    const uint32_t KBASE = 26624u, VBASE = 53248u, BBASE = 79872u;

    for (int i = tid; i < 1536; i += 256) {
        int row = i / 12, col = i % 12;
        uint32_t so = ((uint32_t)row * FA_LDS + (uint32_t)col * 8u) * 2u;
        size_t go = (size_t)(q0 + row) * DMODEL + hOff + col * 8;
        cp16(smBase + so, Q16 + go);
    }
    CP_COMMIT();

    auto load_kv = [&](int c, int buf) {
        int l0 = c * 64;
        uint32_t kB = smBase + KBASE + (uint32_t)buf * 13312u;
        uint32_t vB = smBase + VBASE + (uint32_t)buf * 13312u;
        for (int i = tid; i < 768; i += 256) {
            int row = i / 12, col = i % 12;
            uint32_t so = ((uint32_t)row * FA_LDS + (uint32_t)col * 8u) * 2u;
            size_t go = (bSeq + l0 + row) * DMODEL + hOff + col * 8;
            cp16(kB + so, K16 + go);
            cp16(vB + so, V16 + go);
        }
        if (tid < 16)
            cp16(smBase + BBASE + (uint32_t)buf * 256u + (uint32_t)tid * 16u,
                 biasBL + bSeq + l0 + tid * 4);
    };
    load_kv(0, 0);
    CP_COMMIT();

    const uint32_t aRow = (uint32_t)(wid * 16 + (lane & 15)) * FA_LDS + (uint32_t)(lane >> 4) * 8u;
    const uint32_t bRow = (uint32_t)((lane & 7) + ((lane >> 4) * 8)) * FA_LDS
                        + (uint32_t)((lane >> 3) & 1) * 8u;
    const uint32_t vLaneRow = (uint32_t)((lane & 7) + ((lane >> 3) & 1) * 8);
    const uint32_t vLaneCol = (uint32_t)(lane >> 4) * 8u;

    float oacc[12][4];
    #pragma unroll
    for (int j = 0; j < 12; j++)
        #pragma unroll
        for (int k = 0; k < 4; k++) oacc[j][k] = 0.f;
    float m0 = -1e30f, m1 = -1e30f, l0s = 0.f, l1s = 0.f;

    for (int c = 0; c < 16; c++) {
        CP_WAIT0();
        __syncthreads();
        if (c + 1 < 16) { load_kv(c + 1, (c + 1) & 1); CP_COMMIT(); }

        const uint32_t kB = smBase + KBASE + (uint32_t)(c & 1) * 13312u;
        const uint32_t vB = smBase + VBASE + (uint32_t)(c & 1) * 13312u;
        const float* sbias = reinterpret_cast<const float*>(smem + BBASE + (c & 1) * 256);

        float s[8][4];
        #pragma unroll
        for (int j = 0; j < 8; j++)
            #pragma unroll
            for (int k = 0; k < 4; k++) s[j][k] = 0.f;

        #pragma unroll
        for (int ks = 0; ks < 6; ks++) {
            const uint32_t kcol = (uint32_t)ks * 16u;
            uint32_t qF[4], kk[4];
            ldm_x4(qF, smBase + (aRow + kcol) * 2u);
            #pragma unroll
            for (int g = 0; g < 4; g++) {
                uint32_t off = (bRow + (uint32_t)g * 16u * FA_LDS + kcol) * 2u;
                ldm_x4(kk, kB + off);
                mma16816h(s[2 * g],     qF, &kk[0]);
                mma16816h(s[2 * g + 1], qF, &kk[2]);
            }
        }

        float mx0 = -1e30f, mx1 = -1e30f;
        #pragma unroll
        for (int nj = 0; nj < 8; nj++) {
            int cidx = nj * 8 + (lane & 3) * 2;
            float bj0 = sbias[cidx], bj1 = sbias[cidx + 1];
            s[nj][0] = s[nj][0] * scale + bj0;
            s[nj][1] = s[nj][1] * scale + bj1;
            s[nj][2] = s[nj][2] * scale + bj0;
            s[nj][3] = s[nj][3] * scale + bj1;
            mx0 = fmaxf(mx0, fmaxf(s[nj][0], s[nj][1]));
            mx1 = fmaxf(mx1, fmaxf(s[nj][2], s[nj][3]));
        }
        #pragma unroll
        for (int o = 1; o <= 2; o <<= 1) {
            mx0 = fmaxf(mx0, __shfl_xor_sync(0xffffffffu, mx0, o));
            mx1 = fmaxf(mx1, __shfl_xor_sync(0xffffffffu, mx1, o));
        }
        float mn0 = fmaxf(m0, mx0), mn1 = fmaxf(m1, mx1);
        float cor0 = __expf(m0 - mn0), cor1 = __expf(m1 - mn1);
        l0s *= cor0; l1s *= cor1;
        #pragma unroll
        for (int j = 0; j < 12; j++) {
            oacc[j][0] *= cor0; oacc[j][1] *= cor0;
            oacc[j][2] *= cor1; oacc[j][3] *= cor1;
        }
        m0 = mn0; m1 = mn1;

        float rs0 = 0.f, rs1 = 0.f;
        uint32_t pF[4][4];
        #pragma unroll
        for (int t = 0; t < 4; t++) {
            float p00 = __expf(s[2 * t][0] - mn0);
            float p01 = __expf(s[2 * t][1] - mn0);
            float p10 = __expf(s[2 * t][2] - mn1);
            float p11 = __expf(s[2 * t][3] - mn1);
            float p20 = __expf(s[2 * t + 1][0] - mn0);
            float p21 = __expf(s[2 * t + 1][1] - mn0);
            float p30 = __expf(s[2 * t + 1][2] - mn1);
            float p31 = __expf(s[2 * t + 1][3] - mn1);
            rs0 += p00 + p01 + p20 + p21;
            rs1 += p10 + p11 + p30 + p31;
            pF[t][0] = packh2(p00, p01);
            pF[t][1] = packh2(p10, p11);
            pF[t][2] = packh2(p20, p21);
            pF[t][3] = packh2(p30, p31);
        }
        #pragma unroll
        for (int o = 1; o <= 2; o <<= 1) {
            rs0 += __shfl_xor_sync(0xffffffffu, rs0, o);
            rs1 += __shfl_xor_sync(0xffffffffu, rs1, o);
        }
        l0s += rs0; l1s += rs1;

        #pragma unroll
        for (int t = 0; t < 4; t++) {
            uint32_t vv[4];
            #pragma unroll
            for (int g = 0; g < 6; g++) {
                uint32_t off = (((uint32_t)t * 16u + vLaneRow) * FA_LDS
                                + (uint32_t)g * 16u + vLaneCol) * 2u;
                ldm_x4_t(vv, vB + off);
                mma16816h(oacc[2 * g],     pF[t], &vv[0]);
                mma16816h(oacc[2 * g + 1], pF[t], &vv[2]);
            }
        }
    }

    float inv0 = 1.0f / l0s, inv1 = 1.0f / l1s;
    const int q = q0 + wid * 16 + (lane >> 2);
    #pragma unroll
    for (int j = 0; j < 12; j++) {
        int n = j * 8 + (lane & 3) * 2;
        size_t o0 = ((size_t)(b * NQ + q)) * DMODEL + hOff + n;
        size_t o1 = o0 + (size_t)8 * DMODEL;
        *reinterpret_cast<uint32_t*>(O16 + o0) = packh2(oacc[j][0] * inv0, oacc[j][1] * inv0);
        *reinterpret_cast<uint32_t*>(O16 + o1) = packh2(oacc[j][2] * inv1, oacc[j][3] * inv1);
    }
}

// ============================ LayerNorm / misc ============================
__device__ __forceinline__ void ln_stats(const float* __restrict__ xr, int ncols,
                                         float& mu, float& rs, float* s1, float* s2) {
    float sum = 0.f, sumsq = 0.f;
    for (int i = threadIdx.x; i < ncols; i += blockDim.x) {
        float v = xr[i];
        sum += v; sumsq += v * v;
    }
    #pragma unroll
    for (int o = 16; o; o >>= 1) {
        sum   += __shfl_xor_sync(0xffffffffu, sum, o);
        sumsq += __shfl_xor_sync(0xffffffffu, sumsq, o);
    }
    int wid = threadIdx.x >> 5, lid = threadIdx.x & 31;
    if (lid == 0) { s1[wid] = sum; s2[wid] = sumsq; }
    __syncthreads();
    if (threadIdx.x < 32) {
        int nw = blockDim.x >> 5;
        float a = (lid < nw) ? s1[lid] : 0.f;
        float c = (lid < nw) ? s2[lid] : 0.f;
        #pragma unroll
        for (int o = 16; o; o >>= 1) {
            a += __shfl_xor_sync(0xffffffffu, a, o);
            c += __shfl_xor_sync(0xffffffffu, c, o);
        }
        if (lid == 0) { s1[0] = a; s2[0] = c; }
    }
    __syncthreads();
    float inv_n = 1.0f / (float)ncols;
    mu = s1[0] * inv_n;
    float var = s2[0] * inv_n - mu * mu;
    rs = rsqrtf(var + 1e-5f);
}

__global__ void ln_h_kernel(const float* __restrict__ x, const float* __restrict__ w,
                            const float* __restrict__ b,
                            __half* __restrict__ o16, int ncols) {
    __shared__ float s1[32], s2[32];
    const size_t row = blockIdx.x;
    const float* xr = x + row * (size_t)ncols;
    float mu, rs;
    ln_stats(xr, ncols, mu, rs, s1, s2);
    __half* orow = o16 + row * (size_t)ncols;
    for (int i = threadIdx.x; i < ncols; i += blockDim.x) {
        float y = (xr[i] - mu) * rs * w[i] + b[i];
        orow[i] = __float2half_rn(y);
    }
}

__global__ void cvt_h_kernel(const float* __restrict__ x, __half* __restrict__ o, int n) {
    int i = blockIdx.x * blockDim.x + threadIdx.x;
    if (i < n) o[i] = __float2half_rn(x[i]);
}

__global__ void bias_kernel(const float* __restrict__ size_in, const float* __restrict__ mask,
                            float* __restrict__ bias, int n) {
    int i = blockIdx.x * blockDim.x + threadIdx.x;
    if (i < n) {
        float s = size_in[i];
        s = (s < 0.5f) ? 1.0f : s;
        bias[i] = logf(s) + mask[i];
    }
}

// ============================ launch ============================
extern "C" void kernel_launch(void* const* d_in, const int* in_sizes, int n_in,
                              void* d_out, int out_size) {
    const float* x     = (const float*)d_in[0];
    const float* sizei = (const float*)d_in[1];
    const float* amask = (const float*)d_in[2];
    const float* query = (const float*)d_in[3];
    const float* ln_q_w = (const float*)d_in[4];
    const float* ln_q_b = (const float*)d_in[5];
    const float* ln_k_w = (const float*)d_in[6];
    const float* ln_k_b = (const float*)d_in[7];
    const float* Wq = (const float*)d_in[8];
    const float* Wk = (const float*)d_in[9];
    const float* Wv = (const float*)d_in[10];
    const float* bq = (const float*)d_in[11];
    const float* bk = (const float*)d_in[12];
    const float* bv = (const float*)d_in[13];
    const float* Wo = (const float*)d_in[14];
    const float* bo = (const float*)d_in[15];
    float* out = (float*)d_out;

    __half *x16, *wk16, *wv16, *wq16, *wo16, *kh16, *vh16, *qln16, *qh16, *ao16;
    float *bias;
    cudaGetSymbolAddress((void**)&x16, g_x16);
    cudaGetSymbolAddress((void**)&wk16, g_wk16);
    cudaGetSymbolAddress((void**)&wv16, g_wv16);
    cudaGetSymbolAddress((void**)&wq16, g_wq16);
    cudaGetSymbolAddress((void**)&wo16, g_wo16);
    cudaGetSymbolAddress((void**)&kh16, g_kh16);
    cudaGetSymbolAddress((void**)&vh16, g_vh16);
    cudaGetSymbolAddress((void**)&qln16, g_qln16);
    cudaGetSymbolAddress((void**)&qh16, g_qh16);
    cudaGetSymbolAddress((void**)&ao16, g_ao16);
    cudaGetSymbolAddress((void**)&bias, g_bias);

    cudaFuncSetAttribute(kvfused_gemm, cudaFuncAttributeMaxDynamicSharedMemorySize, KVF_SMEM);
    cudaFuncSetAttribute(oproj_h,      cudaFuncAttributeMaxDynamicSharedMemorySize, OP_SMEM);
    cudaFuncSetAttribute(qproj_h,      cudaFuncAttributeMaxDynamicSharedMemorySize, OP_SMEM);
    cudaFuncSetAttribute(fa_kernel,    cudaFuncAttributeMaxDynamicSharedMemorySize, FA_SMEM);

    const float scale = 0.10206207261596575f;  // 1/sqrt(96)

    // launch order: index 3 (ncu-profiled) = kvfused_gemm
    ln_h_kernel<<<MROWS, 256>>>(x, ln_k_w, ln_k_b, x16, CTXD);                         // 0
    cvt_h_kernel<<<(DMODEL * CTXD + 255) / 256, 256>>>(Wk, wk16, DMODEL * CTXD);       // 1
    cvt_h_kernel<<<(DMODEL * CTXD + 255) / 256, 256>>>(Wv, wv16, DMODEL * CTXD);       // 2
    kvfused_gemm<<<dim3(DMODEL / 64, MROWS / 128), 256, KVF_SMEM>>>(                   // 3 (profiled)
        x16, wk16, wv16, bk, bv, kh16, vh16);
    ln_h_kernel<<<NQ, 256>>>(query, ln_q_w, ln_q_b, qln16, DMODEL);                    // 4
    cvt_h_kernel<<<(DMODEL * DMODEL + 255) / 256, 256>>>(Wq, wq16, DMODEL * DMODEL);   // 5
    cvt_h_kernel<<<(DMODEL * DMODEL + 255) / 256, 256>>>(Wo, wo16, DMODEL * DMODEL);   // 6
    bias_kernel<<<(MROWS + 255) / 256, 256>>>(sizei, amask, bias, MROWS);              // 7
    qproj_h<<<dim3(DMODEL / 128, NQ / 128), 256, OP_SMEM>>>(qln16, wq16, bq, qh16);    // 8

    fa_kernel<<<dim3(NQ / 128, NZ), 256, FA_SMEM>>>(                                   // 9
        qh16, kh16, vh16, bias, scale, ao16);

    oproj_h<<<dim3(DMODEL / 128, BATCH * NQ / 128), 256, OP_SMEM>>>(                   // 10
        ao16, wo16, bo, out);
}